// round 9
// baseline (speedup 1.0000x reference)
#include <cuda_runtime.h>
#include <cuda_bf16.h>
#include <math.h>

// Problem constants
#define S_LEN 2048
#define HID   2048
#define NH    16
#define DN    128
#define DR    64
#define DV    128
#define DQ    192      // DN + DR
#define QLR   1536
#define KVLR  512
#define QDIM  (NH * DQ)        // 3072
#define KVDIM (NH * (DN + DV)) // 4096
#define AODIM (NH * DV)        // 2048
#define SCALE 0.07216878364870323f  // 192^-0.5
#define EPSV  1e-6f

// ---------------- scratch (allocation-free: __device__ global) ----------------
#define OFF_QA    0UL
#define OFF_Q     (OFF_QA   + (size_t)S_LEN * QLR)
#define OFF_CKV   (OFF_Q    + (size_t)S_LEN * QDIM)
#define OFF_CKVN  (OFF_CKV  + (size_t)S_LEN * 576)
#define OFF_KPE   (OFF_CKVN + (size_t)S_LEN * KVLR)
#define OFF_KV    (OFF_KPE  + (size_t)S_LEN * DR)
#define OFF_ATTN  (OFF_KV   + (size_t)S_LEN * KVDIM)
// rounded (tf32-in-fp32) copies
#define OFF_HR    (OFF_ATTN + (size_t)S_LEN * AODIM)
#define OFF_W_QA  (OFF_HR   + (size_t)S_LEN * HID)
#define OFF_W_KVA (OFF_W_QA + (size_t)QLR * HID)          // padded to 640 rows
#define OFF_W_QB  (OFF_W_KVA + (size_t)640 * HID)
#define OFF_W_KVB (OFF_W_QB + (size_t)QDIM * QLR)
#define OFF_W_O   (OFF_W_KVB + (size_t)KVDIM * KVLR)
#define SCRATCH_TOTAL (OFF_W_O + (size_t)HID * AODIM)

__device__ float g_scratch[SCRATCH_TOTAL];

// ---------------- helpers ------------------------------------------------------
__device__ __forceinline__ unsigned f2tf(float x) {
    unsigned u;
    asm("cvt.rna.tf32.f32 %0, %1;" : "=r"(u) : "f"(x));
    return u;
}
__device__ __forceinline__ float rtf(float x) { return __uint_as_float(f2tf(x)); }

__device__ __forceinline__ void mma8(float* d, const unsigned* a, const unsigned* b) {
    asm volatile(
        "mma.sync.aligned.m16n8k8.row.col.f32.tf32.tf32.f32 "
        "{%0,%1,%2,%3},{%4,%5,%6,%7},{%8,%9},{%0,%1,%2,%3};\n"
        : "+f"(d[0]), "+f"(d[1]), "+f"(d[2]), "+f"(d[3])
        : "r"(a[0]), "r"(a[1]), "r"(a[2]), "r"(a[3]), "r"(b[0]), "r"(b[1]));
}

__device__ __forceinline__ void cpa16(unsigned saddr, const void* g) {
    asm volatile("cp.async.cg.shared.global [%0], [%1], 16;\n" :: "r"(saddr), "l"(g));
}
__device__ __forceinline__ void cp_commit() { asm volatile("cp.async.commit_group;\n"); }
template <int N> __device__ __forceinline__ void cp_wait() {
    asm volatile("cp.async.wait_group %0;\n" :: "n"(N));
}

// ---------------- round/copy pass: dst[i] = i<n_src ? tf32(src[i]) : 0 ---------
__global__ __launch_bounds__(256) void round_copy(
    const float4* __restrict__ src, float4* __restrict__ dst, int n4_src, int n4_dst)
{
    int i = blockIdx.x * blockDim.x + threadIdx.x;
    if (i >= n4_dst) return;
    float4 v = make_float4(0.f, 0.f, 0.f, 0.f);
    if (i < n4_src) v = src[i];
    v.x = rtf(v.x); v.y = rtf(v.y); v.z = rtf(v.z); v.w = rtf(v.w);
    dst[i] = v;
}

// ---------------- GEMM: C[M,N] = A[M,K] * W[N,K]^T, tf32, cp.async 2-stage -----
// BM=128, BN=128, BK=32, 256 threads (8 warps, 4x2), warp tile 32x64.  (R7 exact)
#define GS 36                      // smem k-stride: 36 % 8 == 4 -> conflict-free
#define STG_WORDS (2 * 128 * GS)   // A + B per stage
#define GEMM_SMEM_BYTES (2 * STG_WORDS * 4)

__device__ __forceinline__ void gemm_issue(
    const float* __restrict__ A, const float* __restrict__ W, int K,
    int m0, int n0, int k0, unsigned sa, unsigned sb, int t)
{
#pragma unroll
    for (int i = 0; i < 4; i++) {
        int id = t + 256 * i;
        int r = id >> 3, c4 = (id & 7) << 2;
        cpa16(sa + (unsigned)(r * GS + c4) * 4u, A + (size_t)(m0 + r) * K + k0 + c4);
        cpa16(sb + (unsigned)(r * GS + c4) * 4u, W + (size_t)(n0 + r) * K + k0 + c4);
    }
    cp_commit();
}

template <bool RND>
__global__ __launch_bounds__(256, 2) void gemm_tf32(
    const float* __restrict__ A, const float* __restrict__ W,
    float* __restrict__ C, int M, int N, int K)
{
    extern __shared__ unsigned sm[];

    const int t    = threadIdx.x;
    const int lane = t & 31;
    const int wid  = t >> 5;
    const int ln4  = lane >> 2;
    const int lnk  = lane & 3;
    const int warpM = wid & 3;
    const int warpN = wid >> 2;
    const int m0 = blockIdx.y * 128;
    const int n0 = blockIdx.x * 128;

    unsigned sbase = (unsigned)__cvta_generic_to_shared(sm);

    float acc[2][8][4];
#pragma unroll
    for (int mt = 0; mt < 2; mt++)
#pragma unroll
        for (int nt = 0; nt < 8; nt++)
#pragma unroll
            for (int j = 0; j < 4; j++) acc[mt][nt][j] = 0.f;

    const int nIter = K >> 5;

    // prologue: stage 0
    gemm_issue(A, W, K, m0, n0, 0, sbase, sbase + 128 * GS * 4, t);

    for (int it = 0; it < nIter; it++) {
        const int buf = it & 1;
        if (it + 1 < nIter) {
            const int nb = buf ^ 1;
            gemm_issue(A, W, K, m0, n0, (it + 1) << 5,
                       sbase + (unsigned)(nb * STG_WORDS) * 4u,
                       sbase + (unsigned)(nb * STG_WORDS + 128 * GS) * 4u, t);
            cp_wait<1>();
        } else {
            cp_wait<0>();
        }
        __syncthreads();

        const unsigned* As = sm + buf * STG_WORDS;
        const unsigned* Bs = As + 128 * GS;

#pragma unroll
        for (int ks = 0; ks < 4; ks++) {
            const int kk = ks * 8;
            unsigned a[2][4];
#pragma unroll
            for (int mt = 0; mt < 2; mt++) {
                const unsigned* p = As + (warpM * 32 + mt * 16 + ln4) * GS + kk + lnk;
                a[mt][0] = p[0];
                a[mt][1] = p[8 * GS];
                a[mt][2] = p[4];
                a[mt][3] = p[8 * GS + 4];
            }
#pragma unroll
            for (int nt = 0; nt < 8; nt++) {
                const unsigned* p = Bs + (warpN * 64 + nt * 8 + ln4) * GS + kk + lnk;
                unsigned b[2] = { p[0], p[4] };
#pragma unroll
                for (int mt = 0; mt < 2; mt++) mma8(acc[mt][nt], a[mt], b);
            }
        }
        __syncthreads();
    }

#pragma unroll
    for (int mt = 0; mt < 2; mt++) {
        int r0 = m0 + warpM * 32 + mt * 16 + ln4;
#pragma unroll
        for (int nt = 0; nt < 8; nt++) {
            int c = n0 + warpN * 64 + nt * 8 + 2 * lnk;
            if (c < N) {
                float v0 = acc[mt][nt][0], v1 = acc[mt][nt][1];
                float v2 = acc[mt][nt][2], v3 = acc[mt][nt][3];
                if (RND) { v0 = rtf(v0); v1 = rtf(v1); v2 = rtf(v2); v3 = rtf(v3); }
                *(float2*)(C + (size_t)r0 * N + c)       = make_float2(v0, v1);
                *(float2*)(C + (size_t)(r0 + 8) * N + c) = make_float2(v2, v3);
            }
        }
    }
}

// ---------------- RMSNorm (writes tf32-rounded) ---------------------------------
__global__ __launch_bounds__(256) void rmsnorm_kernel(
    const float* __restrict__ X, int ldx, const float* __restrict__ w,
    float* __restrict__ Y, int ldy, int n)
{
    const int row = blockIdx.x;
    const float* x = X + (size_t)row * ldx;
    float* y = Y + (size_t)row * ldy;

    float s = 0.f;
    for (int i = threadIdx.x; i < n; i += blockDim.x) { float v = x[i]; s += v * v; }

    __shared__ float red[8];
    int lane = threadIdx.x & 31, wid = threadIdx.x >> 5;
#pragma unroll
    for (int o = 16; o; o >>= 1) s += __shfl_down_sync(0xFFFFFFFFu, s, o);
    if (!lane) red[wid] = s;
    __syncthreads();
    if (wid == 0) {
        s = (lane < 8) ? red[lane] : 0.f;
#pragma unroll
        for (int o = 4; o; o >>= 1) s += __shfl_down_sync(0xFFFFFFFFu, s, o);
        if (!lane) red[0] = s;
    }
    __syncthreads();
    const float inv = rsqrtf(red[0] / (float)n + EPSV);
    for (int i = threadIdx.x; i < n; i += blockDim.x) y[i] = rtf(x[i] * inv * w[i]);
}

// ---------------- k_pe RoPE (writes rounded) ------------------------------------
__global__ __launch_bounds__(256) void kpe_rope_kernel(
    const float* __restrict__ ckv, const int* __restrict__ pos,
    const float* __restrict__ cosb, const float* __restrict__ sinb,
    float* __restrict__ kpe)
{
    int warp = (blockIdx.x * blockDim.x + threadIdx.x) >> 5;
    int lane = threadIdx.x & 31;
    if (warp >= S_LEN) return;
    int s = warp;
    int p = pos[s];
    const float* x = ckv + (size_t)s * 576 + 512;
    float x0 = x[2 * lane], x1 = x[2 * lane + 1];
    float c0 = cosb[(size_t)p * DR + lane],      s0 = sinb[(size_t)p * DR + lane];
    float c1 = cosb[(size_t)p * DR + 32 + lane], s1 = sinb[(size_t)p * DR + 32 + lane];
    kpe[(size_t)s * DR + lane]      = rtf(x0 * c0 - x1 * s0);
    kpe[(size_t)s * DR + 32 + lane] = rtf(x1 * c1 + x0 * s1);
}

// ---------------- q_pe RoPE (in place, writes rounded) --------------------------
__global__ __launch_bounds__(256) void q_rope_kernel(
    float* __restrict__ Q, const int* __restrict__ pos,
    const float* __restrict__ cosb, const float* __restrict__ sinb)
{
    int warp = (blockIdx.x * blockDim.x + threadIdx.x) >> 5;
    int lane = threadIdx.x & 31;
    if (warp >= S_LEN * NH) return;
    int s = warp >> 4, h = warp & 15;
    int p = pos[s];
    float* x = Q + (size_t)s * QDIM + h * DQ + DN;
    float x0 = x[2 * lane], x1 = x[2 * lane + 1];
    float c0 = cosb[(size_t)p * DR + lane],      s0 = sinb[(size_t)p * DR + lane];
    float c1 = cosb[(size_t)p * DR + 32 + lane], s1 = sinb[(size_t)p * DR + 32 + lane];
    float o0 = rtf(x0 * c0 - x1 * s0);
    float o1 = rtf(x1 * c1 + x0 * s1);
    __syncwarp();
    x[lane]      = o0;
    x[32 + lane] = o1;
}

// ---------------- Flash attention (causal, tf32 mma.sync) -----------------------
// Q fragments preloaded to registers (staged through K buffer 0).
// K/V tiles double-buffered via cp.async.  (R8 attention, retained)
#define QKS 196
#define VS_ 136
#define PS_ 68
#define ATT_SMEM_WORDS (2 * 64 * QKS + 2 * 64 * VS_ + 64 * PS_ + 3 * 64)

__global__ __launch_bounds__(256) void attn_kernel(
    const float* __restrict__ Q, const float* __restrict__ KV,
    const float* __restrict__ KPE, float* __restrict__ O)
{
    extern __shared__ unsigned smu[];
    unsigned* Ks0 = smu;                    // [2][64][QKS]
    unsigned* Vs0 = Ks0 + 2 * 64 * QKS;     // [2][64][VS_]
    unsigned* Ps  = Vs0 + 2 * 64 * VS_;     // [64][PS_]
    float* mrow = (float*)(Ps + 64 * PS_);
    float* lrow = mrow + 64;
    float* arow = lrow + 64;

    const unsigned sb = (unsigned)__cvta_generic_to_shared(smu);
    const unsigned ks_b = sb;
    const unsigned vs_b = sb + 2u * 64 * QKS * 4;

    const int h  = blockIdx.y;
    const int qb = 31 - blockIdx.x;
    const int q0 = qb * 64;
    const int t    = threadIdx.x;
    const int lane = t & 31;
    const int wid  = t >> 5;
    const int ln4  = lane >> 2;
    const int lnk  = lane & 3;
    const int warpM = wid & 3;
    const int warpN = wid >> 2;

    const float* KVh = KV + h * 256;

    // ---- stage Q tile [64 x 192] through K buffer 0, preload fragments ----
    for (int idx = t; idx < 64 * 48; idx += 256) {
        int r = idx / 48, c4 = (idx % 48) * 4;
        *(float4*)(Ks0 + r * QKS + c4) =
            *(const float4*)(Q + (size_t)(q0 + r) * QDIM + h * DQ + c4);
    }
    if (t < 64) { mrow[t] = -1e30f; lrow[t] = 0.f; }
    __syncthreads();

    unsigned qf[96];
    {
        const unsigned* qbase = Ks0 + (warpM * 16 + ln4) * QKS + lnk;
#pragma unroll
        for (int ks = 0; ks < 24; ks++) {
            const int kk = ks * 8;
            qf[ks * 4 + 0] = qbase[kk];
            qf[ks * 4 + 1] = qbase[8 * QKS + kk];
            qf[ks * 4 + 2] = qbase[kk + 4];
            qf[ks * 4 + 3] = qbase[8 * QKS + kk + 4];
        }
    }

    float o[8][4];
#pragma unroll
    for (int nt = 0; nt < 8; nt++)
#pragma unroll
        for (int j = 0; j < 4; j++) o[nt][j] = 0.f;
    __syncthreads();   // all warps done reading Q from Ks0[0]

    // ---- cp.async issue of one K/V tile into buffer `bf` ----
    auto issue_kv = [&](int kt, int bf) {
        const unsigned ksb = ks_b + (unsigned)bf * 64 * QKS * 4;
        const unsigned vsb = vs_b + (unsigned)bf * 64 * VS_ * 4;
        const float* rowbase = KVh + (size_t)(kt * 64) * KVDIM;
#pragma unroll
        for (int i = 0; i < 16; i++) {
            int idx = t + 256 * i;             // 0..4095
            int r = idx >> 6, c4 = (idx & 63) << 2;
            const float* src = rowbase + (size_t)r * KVDIM + c4;
            if (c4 < 128) cpa16(ksb + (unsigned)(r * QKS + c4) * 4u, src);
            else          cpa16(vsb + (unsigned)(r * VS_ + c4 - 128) * 4u, src);
        }
#pragma unroll
        for (int i = 0; i < 4; i++) {
            int idx = t + 256 * i;             // 0..1023
            int r = idx >> 4, c4 = (idx & 15) << 2;
            cpa16(ksb + (unsigned)(r * QKS + 128 + c4) * 4u,
                  KPE + (size_t)(kt * 64 + r) * DR + c4);
        }
        cp_commit();
    };

    issue_kv(0, 0);   // prologue

    for (int kt = 0; kt <= qb; kt++) {
        const int buf = kt & 1;
        if (kt < qb) { issue_kv(kt + 1, buf ^ 1); cp_wait<1>(); }
        else         { cp_wait<0>(); }
        __syncthreads();

        const unsigned* Ks = Ks0 + buf * 64 * QKS;
        const unsigned* Vs = Vs0 + buf * 64 * VS_;
        const int k0 = kt * 64;

        // ---- S = Q K^T ----
        float sacc[4][4];
#pragma unroll
        for (int nt = 0; nt < 4; nt++)
#pragma unroll
            for (int j = 0; j < 4; j++) sacc[nt][j] = 0.f;

#pragma unroll 4
        for (int ks = 0; ks < 24; ks++) {
            const int kk = ks * 8;
#pragma unroll
            for (int nt = 0; nt < 4; nt++) {
                const unsigned* p = Ks + (warpN * 32 + nt * 8 + ln4) * QKS + kk + lnk;
                unsigned b[2] = { p[0], p[4] };
                mma8(sacc[nt], &qf[ks * 4], b);
            }
        }

        const bool diag = (kt == qb);
        const int rl0 = warpM * 16 + ln4;
#pragma unroll
        for (int nt = 0; nt < 4; nt++) {
            int cl = warpN * 32 + nt * 8 + 2 * lnk;
            float v0 = sacc[nt][0] * SCALE;
            float v1 = sacc[nt][1] * SCALE;
            float v2 = sacc[nt][2] * SCALE;
            float v3 = sacc[nt][3] * SCALE;
            if (diag) {
                if (cl     > rl0)     v0 = -1e30f;
                if (cl + 1 > rl0)     v1 = -1e30f;
                if (cl     > rl0 + 8) v2 = -1e30f;
                if (cl + 1 > rl0 + 8) v3 = -1e30f;
            }
            Ps[rl0 * PS_ + cl]           = __float_as_uint(v0);
            Ps[rl0 * PS_ + cl + 1]       = __float_as_uint(v1);
            Ps[(rl0 + 8) * PS_ + cl]     = __float_as_uint(v2);
            Ps[(rl0 + 8) * PS_ + cl + 1] = __float_as_uint(v3);
        }
        __syncthreads();

        // ---- online softmax: 4 threads per row ----
        {
            const int r = t >> 2, seg = t & 3;
            const float* pf = (const float*)Ps + r * PS_ + seg * 16;
            unsigned* pu = Ps + r * PS_ + seg * 16;
            float mprev = mrow[r];
            float mx = mprev;
#pragma unroll
            for (int j = 0; j < 16; j++) mx = fmaxf(mx, pf[j]);
            mx = fmaxf(mx, __shfl_xor_sync(0xFFFFFFFFu, mx, 1));
            mx = fmaxf(mx, __shfl_xor_sync(0xFFFFFFFFu, mx, 2));
            float alpha = __expf(mprev - mx);
            float s = 0.f;
#pragma unroll
            for (int j = 0; j < 16; j++) {
                float e = __expf(pf[j] - mx);
                s += e;
                pu[j] = f2tf(e);
            }
            s += __shfl_xor_sync(0xFFFFFFFFu, s, 1);
            s += __shfl_xor_sync(0xFFFFFFFFu, s, 2);
            if (seg == 0) {
                mrow[r] = mx;
                lrow[r] = lrow[r] * alpha + s;
                arow[r] = alpha;
            }
        }
        __syncthreads();

        // ---- O = O*alpha + P @ V ----
        {
            float ar0 = arow[warpM * 16 + ln4];
            float ar1 = arow[warpM * 16 + ln4 + 8];
#pragma unroll
            for (int nt = 0; nt < 8; nt++) {
                o[nt][0] *= ar0; o[nt][1] *= ar0;
                o[nt][2] *= ar1; o[nt][3] *= ar1;
            }
            const unsigned* pbase = Ps + (warpM * 16 + ln4) * PS_ + lnk;
#pragma unroll
            for (int ks = 0; ks < 8; ks++) {
                const int kk = ks * 8;
                unsigned a[4];
                a[0] = pbase[kk];
                a[1] = pbase[8 * PS_ + kk];
                a[2] = pbase[kk + 4];
                a[3] = pbase[8 * PS_ + kk + 4];
#pragma unroll
                for (int nt = 0; nt < 8; nt++) {
                    const unsigned* p = Vs + (kk + lnk) * VS_ + warpN * 64 + nt * 8 + ln4;
                    unsigned b[2] = { p[0], p[4 * VS_] };
                    mma8(o[nt], a, b);
                }
            }
        }
        __syncthreads();
    }

    {
        float inv0 = 1.f / lrow[warpM * 16 + ln4];
        float inv1 = 1.f / lrow[warpM * 16 + ln4 + 8];
        int r0 = q0 + warpM * 16 + ln4;
#pragma unroll
        for (int nt = 0; nt < 8; nt++) {
            int c = warpN * 64 + nt * 8 + 2 * lnk;
            float* dst0 = O + (size_t)r0 * AODIM + h * DV + c;
            float* dst1 = O + (size_t)(r0 + 8) * AODIM + h * DV + c;
            *(float2*)dst0 = make_float2(rtf(o[nt][0] * inv0), rtf(o[nt][1] * inv0));
            *(float2*)dst1 = make_float2(rtf(o[nt][2] * inv1), rtf(o[nt][3] * inv1));
        }
    }
}

// ---------------- host launcher ---------------------------------------------------
template <bool RND>
static inline void launch_gemm(const float* A, const float* W, float* C,
                               int M, int N, int K) {
    dim3 grid((N + 127) / 128, M / 128);
    gemm_tf32<RND><<<grid, 256, GEMM_SMEM_BYTES>>>(A, W, C, M, N, K);
}

static inline void launch_round(const float* src, float* dst, size_t n_src, size_t n_dst) {
    int n4s = (int)(n_src / 4), n4d = (int)(n_dst / 4);
    round_copy<<<(n4d + 255) / 256, 256>>>((const float4*)src, (float4*)dst, n4s, n4d);
}

extern "C" void kernel_launch(void* const* d_in, const int* in_sizes, int n_in,
                              void* d_out, int out_size)
{
    const float* hidden  = (const float*)d_in[0];
    const float* q_a_w   = (const float*)d_in[1];
    const float* q_a_ln  = (const float*)d_in[2];
    const float* q_b_w   = (const float*)d_in[3];
    const float* kv_a_w  = (const float*)d_in[4];
    const float* kv_a_ln = (const float*)d_in[5];
    const float* kv_b_w  = (const float*)d_in[6];
    const float* o_w     = (const float*)d_in[7];
    const float* cosb    = (const float*)d_in[8];
    const float* sinb    = (const float*)d_in[9];
    // d_in[10] = attention_mask (causal triu; semantics reproduced directly)
    const int*   pos     = (const int*)d_in[11];
    float* out = (float*)d_out;

    float* base;
    cudaGetSymbolAddress((void**)&base, g_scratch);
    float* qa    = base + OFF_QA;
    float* q     = base + OFF_Q;
    float* ckv   = base + OFF_CKV;
    float* ckvn  = base + OFF_CKVN;
    float* kpe   = base + OFF_KPE;
    float* kv    = base + OFF_KV;
    float* attn  = base + OFF_ATTN;
    float* hr    = base + OFF_HR;
    float* w_qa  = base + OFF_W_QA;
    float* w_kva = base + OFF_W_KVA;
    float* w_qb  = base + OFF_W_QB;
    float* w_kvb = base + OFF_W_KVB;
    float* w_o   = base + OFF_W_O;

    cudaFuncSetAttribute(attn_kernel, cudaFuncAttributeMaxDynamicSharedMemorySize,
                         ATT_SMEM_WORDS * 4);
    cudaFuncSetAttribute(gemm_tf32<true>, cudaFuncAttributeMaxDynamicSharedMemorySize,
                         GEMM_SMEM_BYTES);
    cudaFuncSetAttribute(gemm_tf32<false>, cudaFuncAttributeMaxDynamicSharedMemorySize,
                         GEMM_SMEM_BYTES);

    // 0) round inputs/weights to tf32 bit patterns (kv_a_w padded 576 -> 640 rows)
    launch_round(hidden, hr,    (size_t)S_LEN * HID, (size_t)S_LEN * HID);
    launch_round(q_a_w,  w_qa,  (size_t)QLR * HID,   (size_t)QLR * HID);
    launch_round(kv_a_w, w_kva, (size_t)576 * HID,   (size_t)640 * HID);
    launch_round(q_b_w,  w_qb,  (size_t)QDIM * QLR,  (size_t)QDIM * QLR);
    launch_round(kv_b_w, w_kvb, (size_t)KVDIM * KVLR,(size_t)KVDIM * KVLR);

    // 1) q_a = hidden @ q_a_w^T           [2048,1536]
    launch_gemm<true>(hr, w_qa, qa, S_LEN, QLR, HID);
    // 2) ckv = hidden @ kv_a_w^T          [2048,576]
    launch_gemm<true>(hr, w_kva, ckv, S_LEN, 576, HID);
    // 3) rmsnorm(q_a) in place
    rmsnorm_kernel<<<S_LEN, 256>>>(qa, QLR, q_a_ln, qa, QLR, QLR);
    // 4) rmsnorm(ckv[:, :512]) -> ckvn
    rmsnorm_kernel<<<S_LEN, 256>>>(ckv, 576, kv_a_ln, ckvn, KVLR, KVLR);
    // 5) rope(k_pe) -> kpe
    kpe_rope_kernel<<<(S_LEN * 32 + 255) / 256, 256>>>(ckv, pos, cosb, sinb, kpe);
    // 6) q = qa_n @ q_b_w^T               [2048,3072]
    launch_gemm<true>(qa, w_qb, q, S_LEN, QDIM, QLR);
    // 7) kv = ckvn @ kv_b_w^T             [2048,4096]
    launch_gemm<true>(ckvn, w_kvb, kv, S_LEN, KVDIM, KVLR);
    // 8) rope(q_pe) in place
    q_rope_kernel<<<(S_LEN * NH * 32 + 255) / 256, 256>>>(q, pos, cosb, sinb);
    // 9) attention -> attn                [2048,2048]
    attn_kernel<<<dim3(32, NH), 256, ATT_SMEM_WORDS * 4>>>(q, kv, kpe, attn);
    // 10) round o_w
    launch_round(o_w, w_o, (size_t)HID * AODIM, (size_t)HID * AODIM);
    // 11) out = attn @ o_w^T              [2048,2048]
    launch_gemm<false>(attn, w_o, out, S_LEN, HID, AODIM);
}

// round 10
// speedup vs baseline: 1.2052x; 1.2052x over previous
#include <cuda_runtime.h>
#include <cuda_bf16.h>
#include <math.h>

// Problem constants
#define S_LEN 2048
#define HID   2048
#define NH    16
#define DN    128
#define DR    64
#define DV    128
#define DQ    192      // DN + DR
#define QLR   1536
#define KVLR  512
#define QDIM  (NH * DQ)        // 3072
#define KVDIM (NH * (DN + DV)) // 4096
#define AODIM (NH * DV)        // 2048
#define SCALE 0.07216878364870323f  // 192^-0.5
#define EPSV  1e-6f

// ---------------- scratch (allocation-free: __device__ global) ----------------
#define OFF_QA    0UL
#define OFF_Q     (OFF_QA   + (size_t)S_LEN * QLR)
#define OFF_CKV   (OFF_Q    + (size_t)S_LEN * QDIM)
#define OFF_CKVN  (OFF_CKV  + (size_t)S_LEN * 576)
#define OFF_KPE   (OFF_CKVN + (size_t)S_LEN * KVLR)
#define OFF_KV    (OFF_KPE  + (size_t)S_LEN * DR)
#define OFF_ATTN  (OFF_KV   + (size_t)S_LEN * KVDIM)
// rounded (tf32-in-fp32) copies
#define OFF_HR    (OFF_ATTN + (size_t)S_LEN * AODIM)
#define OFF_W_QA  (OFF_HR   + (size_t)S_LEN * HID)
#define OFF_W_KVA (OFF_W_QA + (size_t)QLR * HID)          // padded to 640 rows
#define OFF_W_QB  (OFF_W_KVA + (size_t)640 * HID)
#define OFF_W_KVB (OFF_W_QB + (size_t)QDIM * QLR)
#define OFF_W_O   (OFF_W_KVB + (size_t)KVDIM * KVLR)
#define SCRATCH_TOTAL (OFF_W_O + (size_t)HID * AODIM)

__device__ float g_scratch[SCRATCH_TOTAL];

// ---------------- helpers ------------------------------------------------------
__device__ __forceinline__ unsigned f2tf(float x) {
    unsigned u;
    asm("cvt.rna.tf32.f32 %0, %1;" : "=r"(u) : "f"(x));
    return u;
}
__device__ __forceinline__ float rtf(float x) { return __uint_as_float(f2tf(x)); }

__device__ __forceinline__ void mma8(float* d, const unsigned* a, const unsigned* b) {
    asm volatile(
        "mma.sync.aligned.m16n8k8.row.col.f32.tf32.tf32.f32 "
        "{%0,%1,%2,%3},{%4,%5,%6,%7},{%8,%9},{%0,%1,%2,%3};\n"
        : "+f"(d[0]), "+f"(d[1]), "+f"(d[2]), "+f"(d[3])
        : "r"(a[0]), "r"(a[1]), "r"(a[2]), "r"(a[3]), "r"(b[0]), "r"(b[1]));
}

__device__ __forceinline__ void cpa16(unsigned saddr, const void* g) {
    asm volatile("cp.async.cg.shared.global [%0], [%1], 16;\n" :: "r"(saddr), "l"(g));
}
__device__ __forceinline__ void cp_commit() { asm volatile("cp.async.commit_group;\n"); }
template <int N> __device__ __forceinline__ void cp_wait() {
    asm volatile("cp.async.wait_group %0;\n" :: "n"(N));
}

// ---------------- round/copy pass: dst[i] = i<n_src ? tf32(src[i]) : 0 ---------
__global__ __launch_bounds__(256) void round_copy(
    const float4* __restrict__ src, float4* __restrict__ dst, int n4_src, int n4_dst)
{
    int i = blockIdx.x * blockDim.x + threadIdx.x;
    if (i >= n4_dst) return;
    float4 v = make_float4(0.f, 0.f, 0.f, 0.f);
    if (i < n4_src) v = src[i];
    v.x = rtf(v.x); v.y = rtf(v.y); v.z = rtf(v.z); v.w = rtf(v.w);
    dst[i] = v;
}

// ---------------- GEMM: C[M,N] = A[M,K] * W[N,K]^T, tf32, cp.async 2-stage -----
// BM=128, BN=128, BK=32, 128 threads (4 warps, 2x2), warp tile 64x64.  (R8 GEMM)
#define GS 36                      // smem k-stride: 36 % 8 == 4 -> conflict-free
#define STG_WORDS (2 * 128 * GS)   // A + B per stage
#define GEMM_SMEM_BYTES (2 * STG_WORDS * 4)

__device__ __forceinline__ void gemm_issue(
    const float* __restrict__ A, const float* __restrict__ W, int K,
    int m0, int n0, int k0, unsigned sa, unsigned sb, int t)
{
#pragma unroll
    for (int i = 0; i < 8; i++) {
        int id = t + 128 * i;
        int r = id >> 3, c4 = (id & 7) << 2;
        cpa16(sa + (unsigned)(r * GS + c4) * 4u, A + (size_t)(m0 + r) * K + k0 + c4);
    }
#pragma unroll
    for (int i = 0; i < 8; i++) {
        int id = t + 128 * i;
        int r = id >> 3, c4 = (id & 7) << 2;
        cpa16(sb + (unsigned)(r * GS + c4) * 4u, W + (size_t)(n0 + r) * K + k0 + c4);
    }
    cp_commit();
}

template <bool RND>
__global__ __launch_bounds__(128, 2) void gemm_tf32(
    const float* __restrict__ A, const float* __restrict__ W,
    float* __restrict__ C, int M, int N, int K)
{
    extern __shared__ unsigned sm[];

    const int t    = threadIdx.x;
    const int lane = t & 31;
    const int wid  = t >> 5;
    const int ln4  = lane >> 2;
    const int lnk  = lane & 3;
    const int warpM = wid & 1;   // 2 -> 64 rows each
    const int warpN = wid >> 1;  // 2 -> 64 cols each
    const int m0 = blockIdx.y * 128;
    const int n0 = blockIdx.x * 128;

    unsigned sbase = (unsigned)__cvta_generic_to_shared(sm);

    float acc[4][8][4];
#pragma unroll
    for (int mt = 0; mt < 4; mt++)
#pragma unroll
        for (int nt = 0; nt < 8; nt++)
#pragma unroll
            for (int j = 0; j < 4; j++) acc[mt][nt][j] = 0.f;

    const int nIter = K >> 5;

    // prologue: stage 0
    gemm_issue(A, W, K, m0, n0, 0, sbase, sbase + 128 * GS * 4, t);

    for (int it = 0; it < nIter; it++) {
        const int buf = it & 1;
        if (it + 1 < nIter) {
            const int nb = buf ^ 1;
            gemm_issue(A, W, K, m0, n0, (it + 1) << 5,
                       sbase + (unsigned)(nb * STG_WORDS) * 4u,
                       sbase + (unsigned)(nb * STG_WORDS + 128 * GS) * 4u, t);
            cp_wait<1>();
        } else {
            cp_wait<0>();
        }
        __syncthreads();

        const unsigned* As = sm + buf * STG_WORDS;
        const unsigned* Bs = As + 128 * GS;

#pragma unroll
        for (int ks = 0; ks < 4; ks++) {
            const int kk = ks * 8;
            unsigned a[4][4];
#pragma unroll
            for (int mt = 0; mt < 4; mt++) {
                const unsigned* p = As + (warpM * 64 + mt * 16 + ln4) * GS + kk + lnk;
                a[mt][0] = p[0];
                a[mt][1] = p[8 * GS];
                a[mt][2] = p[4];
                a[mt][3] = p[8 * GS + 4];
            }
#pragma unroll
            for (int nt = 0; nt < 8; nt++) {
                const unsigned* p = Bs + (warpN * 64 + nt * 8 + ln4) * GS + kk + lnk;
                unsigned b[2] = { p[0], p[4] };
#pragma unroll
                for (int mt = 0; mt < 4; mt++) mma8(acc[mt][nt], a[mt], b);
            }
        }
        __syncthreads();
    }

#pragma unroll
    for (int mt = 0; mt < 4; mt++) {
        int r0 = m0 + warpM * 64 + mt * 16 + ln4;
#pragma unroll
        for (int nt = 0; nt < 8; nt++) {
            int c = n0 + warpN * 64 + nt * 8 + 2 * lnk;
            if (c < N) {
                float v0 = acc[mt][nt][0], v1 = acc[mt][nt][1];
                float v2 = acc[mt][nt][2], v3 = acc[mt][nt][3];
                if (RND) { v0 = rtf(v0); v1 = rtf(v1); v2 = rtf(v2); v3 = rtf(v3); }
                *(float2*)(C + (size_t)r0 * N + c)       = make_float2(v0, v1);
                *(float2*)(C + (size_t)(r0 + 8) * N + c) = make_float2(v2, v3);
            }
        }
    }
}

// ---------------- RMSNorm (writes tf32-rounded) ---------------------------------
__global__ __launch_bounds__(256) void rmsnorm_kernel(
    const float* __restrict__ X, int ldx, const float* __restrict__ w,
    float* __restrict__ Y, int ldy, int n)
{
    const int row = blockIdx.x;
    const float* x = X + (size_t)row * ldx;
    float* y = Y + (size_t)row * ldy;

    float s = 0.f;
    for (int i = threadIdx.x; i < n; i += blockDim.x) { float v = x[i]; s += v * v; }

    __shared__ float red[8];
    int lane = threadIdx.x & 31, wid = threadIdx.x >> 5;
#pragma unroll
    for (int o = 16; o; o >>= 1) s += __shfl_down_sync(0xFFFFFFFFu, s, o);
    if (!lane) red[wid] = s;
    __syncthreads();
    if (wid == 0) {
        s = (lane < 8) ? red[lane] : 0.f;
#pragma unroll
        for (int o = 4; o; o >>= 1) s += __shfl_down_sync(0xFFFFFFFFu, s, o);
        if (!lane) red[0] = s;
    }
    __syncthreads();
    const float inv = rsqrtf(red[0] / (float)n + EPSV);
    for (int i = threadIdx.x; i < n; i += blockDim.x) y[i] = rtf(x[i] * inv * w[i]);
}

// ---------------- k_pe RoPE (writes rounded) ------------------------------------
__global__ __launch_bounds__(256) void kpe_rope_kernel(
    const float* __restrict__ ckv, const int* __restrict__ pos,
    const float* __restrict__ cosb, const float* __restrict__ sinb,
    float* __restrict__ kpe)
{
    int warp = (blockIdx.x * blockDim.x + threadIdx.x) >> 5;
    int lane = threadIdx.x & 31;
    if (warp >= S_LEN) return;
    int s = warp;
    int p = pos[s];
    const float* x = ckv + (size_t)s * 576 + 512;
    float x0 = x[2 * lane], x1 = x[2 * lane + 1];
    float c0 = cosb[(size_t)p * DR + lane],      s0 = sinb[(size_t)p * DR + lane];
    float c1 = cosb[(size_t)p * DR + 32 + lane], s1 = sinb[(size_t)p * DR + 32 + lane];
    kpe[(size_t)s * DR + lane]      = rtf(x0 * c0 - x1 * s0);
    kpe[(size_t)s * DR + 32 + lane] = rtf(x1 * c1 + x0 * s1);
}

// ---------------- q_pe RoPE (in place, writes rounded) --------------------------
__global__ __launch_bounds__(256) void q_rope_kernel(
    float* __restrict__ Q, const int* __restrict__ pos,
    const float* __restrict__ cosb, const float* __restrict__ sinb)
{
    int warp = (blockIdx.x * blockDim.x + threadIdx.x) >> 5;
    int lane = threadIdx.x & 31;
    if (warp >= S_LEN * NH) return;
    int s = warp >> 4, h = warp & 15;
    int p = pos[s];
    float* x = Q + (size_t)s * QDIM + h * DQ + DN;
    float x0 = x[2 * lane], x1 = x[2 * lane + 1];
    float c0 = cosb[(size_t)p * DR + lane],      s0 = sinb[(size_t)p * DR + lane];
    float c1 = cosb[(size_t)p * DR + 32 + lane], s1 = sinb[(size_t)p * DR + 32 + lane];
    float o0 = rtf(x0 * c0 - x1 * s0);
    float o1 = rtf(x1 * c1 + x0 * s1);
    __syncwarp();
    x[lane]      = o0;
    x[32 + lane] = o1;
}

// ---------------- Flash attention (causal, tf32 mma.sync) -----------------------
// R7-exact attention: Q in smem, fused coalesced K/V loads, no double buffer.
#define QKS 196
#define VS_ 136
#define PS_ 68
#define ATT_SMEM_WORDS (2 * 64 * QKS + 64 * VS_ + 64 * PS_ + 3 * 64)

__global__ __launch_bounds__(256) void attn_kernel(
    const float* __restrict__ Q, const float* __restrict__ KV,
    const float* __restrict__ KPE, float* __restrict__ O)
{
    extern __shared__ unsigned smu[];
    unsigned* Qs = smu;
    unsigned* Ks = Qs + 64 * QKS;
    unsigned* Vs = Ks + 64 * QKS;
    unsigned* Ps = Vs + 64 * VS_;
    float* mrow = (float*)(Ps + 64 * PS_);
    float* lrow = mrow + 64;
    float* arow = lrow + 64;

    const int h  = blockIdx.y;
    const int qb = 31 - blockIdx.x;
    const int q0 = qb * 64;
    const int t    = threadIdx.x;
    const int lane = t & 31;
    const int wid  = t >> 5;
    const int ln4  = lane >> 2;
    const int lnk  = lane & 3;
    const int warpM = wid & 3;
    const int warpN = wid >> 2;

    const float* KVh = KV + h * 256;

    for (int idx = t; idx < 64 * 48; idx += 256) {
        int r = idx / 48, c4 = (idx % 48) * 4;
        *(float4*)(Qs + r * QKS + c4) =
            *(const float4*)(Q + (size_t)(q0 + r) * QDIM + h * DQ + c4);
    }
    if (t < 64) { mrow[t] = -1e30f; lrow[t] = 0.f; }

    float o[8][4];
#pragma unroll
    for (int nt = 0; nt < 8; nt++)
#pragma unroll
        for (int j = 0; j < 4; j++) o[nt][j] = 0.f;
    __syncthreads();

    for (int kt = 0; kt <= qb; kt++) {
        const int k0 = kt * 64;
        // fused K-nope + V load: one coalesced sweep of 64 float4 per kv row
#pragma unroll
        for (int i = 0; i < 16; i++) {
            int idx = t + 256 * i;            // 0 .. 4095
            int r = idx >> 6, c4 = (idx & 63) << 2;
            float4 v = *(const float4*)(KVh + (size_t)(k0 + r) * KVDIM + c4);
            if (c4 < 128) *(float4*)(Ks + r * QKS + c4)         = v;
            else          *(float4*)(Vs + r * VS_ + (c4 - 128)) = v;
        }
        // kpe -> Ks cols 128..191
#pragma unroll
        for (int i = 0; i < 4; i++) {
            int idx = t + 256 * i;            // 0 .. 1023
            int r = idx >> 4, c4 = (idx & 15) << 2;
            *(float4*)(Ks + r * QKS + 128 + c4) =
                *(const float4*)(KPE + (size_t)(k0 + r) * DR + c4);
        }
        __syncthreads();

        // ---- S = Q K^T ----
        float sacc[4][4];
#pragma unroll
        for (int nt = 0; nt < 4; nt++)
#pragma unroll
            for (int j = 0; j < 4; j++) sacc[nt][j] = 0.f;

        const unsigned* qbase = Qs + (warpM * 16 + ln4) * QKS + lnk;
#pragma unroll 4
        for (int ks = 0; ks < 24; ks++) {
            const int kk = ks * 8;
            unsigned a[4];
            a[0] = qbase[kk];
            a[1] = qbase[8 * QKS + kk];
            a[2] = qbase[kk + 4];
            a[3] = qbase[8 * QKS + kk + 4];
#pragma unroll
            for (int nt = 0; nt < 4; nt++) {
                const unsigned* p = Ks + (warpN * 32 + nt * 8 + ln4) * QKS + kk + lnk;
                unsigned b[2] = { p[0], p[4] };
                mma8(sacc[nt], a, b);
            }
        }

        const bool diag = (kt == qb);
        const int rl0 = warpM * 16 + ln4;
#pragma unroll
        for (int nt = 0; nt < 4; nt++) {
            int cl = warpN * 32 + nt * 8 + 2 * lnk;
            float v0 = sacc[nt][0] * SCALE;
            float v1 = sacc[nt][1] * SCALE;
            float v2 = sacc[nt][2] * SCALE;
            float v3 = sacc[nt][3] * SCALE;
            if (diag) {
                if (cl     > rl0)     v0 = -1e30f;
                if (cl + 1 > rl0)     v1 = -1e30f;
                if (cl     > rl0 + 8) v2 = -1e30f;
                if (cl + 1 > rl0 + 8) v3 = -1e30f;
            }
            Ps[rl0 * PS_ + cl]           = __float_as_uint(v0);
            Ps[rl0 * PS_ + cl + 1]       = __float_as_uint(v1);
            Ps[(rl0 + 8) * PS_ + cl]     = __float_as_uint(v2);
            Ps[(rl0 + 8) * PS_ + cl + 1] = __float_as_uint(v3);
        }
        __syncthreads();

        // ---- online softmax: 4 threads per row ----
        {
            const int r = t >> 2, seg = t & 3;
            const float* pf = (const float*)Ps + r * PS_ + seg * 16;
            unsigned* pu = Ps + r * PS_ + seg * 16;
            float mprev = mrow[r];
            float mx = mprev;
#pragma unroll
            for (int j = 0; j < 16; j++) mx = fmaxf(mx, pf[j]);
            mx = fmaxf(mx, __shfl_xor_sync(0xFFFFFFFFu, mx, 1));
            mx = fmaxf(mx, __shfl_xor_sync(0xFFFFFFFFu, mx, 2));
            float alpha = __expf(mprev - mx);
            float s = 0.f;
#pragma unroll
            for (int j = 0; j < 16; j++) {
                float e = __expf(pf[j] - mx);
                s += e;
                pu[j] = f2tf(e);
            }
            s += __shfl_xor_sync(0xFFFFFFFFu, s, 1);
            s += __shfl_xor_sync(0xFFFFFFFFu, s, 2);
            if (seg == 0) {
                mrow[r] = mx;
                lrow[r] = lrow[r] * alpha + s;
                arow[r] = alpha;
            }
        }
        __syncthreads();

        // ---- O = O*alpha + P @ V ----
        {
            float ar0 = arow[warpM * 16 + ln4];
            float ar1 = arow[warpM * 16 + ln4 + 8];
#pragma unroll
            for (int nt = 0; nt < 8; nt++) {
                o[nt][0] *= ar0; o[nt][1] *= ar0;
                o[nt][2] *= ar1; o[nt][3] *= ar1;
            }
            const unsigned* pbase = Ps + (warpM * 16 + ln4) * PS_ + lnk;
#pragma unroll
            for (int ks = 0; ks < 8; ks++) {
                const int kk = ks * 8;
                unsigned a[4];
                a[0] = pbase[kk];
                a[1] = pbase[8 * PS_ + kk];
                a[2] = pbase[kk + 4];
                a[3] = pbase[8 * PS_ + kk + 4];
#pragma unroll
                for (int nt = 0; nt < 8; nt++) {
                    const unsigned* p = Vs + (kk + lnk) * VS_ + warpN * 64 + nt * 8 + ln4;
                    unsigned b[2] = { p[0], p[4 * VS_] };
                    mma8(o[nt], a, b);
                }
            }
        }
        __syncthreads();
    }

    {
        float inv0 = 1.f / lrow[warpM * 16 + ln4];
        float inv1 = 1.f / lrow[warpM * 16 + ln4 + 8];
        int r0 = q0 + warpM * 16 + ln4;
#pragma unroll
        for (int nt = 0; nt < 8; nt++) {
            int c = warpN * 64 + nt * 8 + 2 * lnk;
            float* dst0 = O + (size_t)r0 * AODIM + h * DV + c;
            float* dst1 = O + (size_t)(r0 + 8) * AODIM + h * DV + c;
            *(float2*)dst0 = make_float2(rtf(o[nt][0] * inv0), rtf(o[nt][1] * inv0));
            *(float2*)dst1 = make_float2(rtf(o[nt][2] * inv1), rtf(o[nt][3] * inv1));
        }
    }
}

// ---------------- host launcher ---------------------------------------------------
template <bool RND>
static inline void launch_gemm(const float* A, const float* W, float* C,
                               int M, int N, int K) {
    dim3 grid((N + 127) / 128, M / 128);
    gemm_tf32<RND><<<grid, 128, GEMM_SMEM_BYTES>>>(A, W, C, M, N, K);
}

static inline void launch_round(const float* src, float* dst, size_t n_src, size_t n_dst) {
    int n4s = (int)(n_src / 4), n4d = (int)(n_dst / 4);
    round_copy<<<(n4d + 255) / 256, 256>>>((const float4*)src, (float4*)dst, n4s, n4d);
}

extern "C" void kernel_launch(void* const* d_in, const int* in_sizes, int n_in,
                              void* d_out, int out_size)
{
    const float* hidden  = (const float*)d_in[0];
    const float* q_a_w   = (const float*)d_in[1];
    const float* q_a_ln  = (const float*)d_in[2];
    const float* q_b_w   = (const float*)d_in[3];
    const float* kv_a_w  = (const float*)d_in[4];
    const float* kv_a_ln = (const float*)d_in[5];
    const float* kv_b_w  = (const float*)d_in[6];
    const float* o_w     = (const float*)d_in[7];
    const float* cosb    = (const float*)d_in[8];
    const float* sinb    = (const float*)d_in[9];
    // d_in[10] = attention_mask (causal triu; semantics reproduced directly)
    const int*   pos     = (const int*)d_in[11];
    float* out = (float*)d_out;

    float* base;
    cudaGetSymbolAddress((void**)&base, g_scratch);
    float* qa    = base + OFF_QA;
    float* q     = base + OFF_Q;
    float* ckv   = base + OFF_CKV;
    float* ckvn  = base + OFF_CKVN;
    float* kpe   = base + OFF_KPE;
    float* kv    = base + OFF_KV;
    float* attn  = base + OFF_ATTN;
    float* hr    = base + OFF_HR;
    float* w_qa  = base + OFF_W_QA;
    float* w_kva = base + OFF_W_KVA;
    float* w_qb  = base + OFF_W_QB;
    float* w_kvb = base + OFF_W_KVB;
    float* w_o   = base + OFF_W_O;

    cudaFuncSetAttribute(attn_kernel, cudaFuncAttributeMaxDynamicSharedMemorySize,
                         ATT_SMEM_WORDS * 4);
    cudaFuncSetAttribute(gemm_tf32<true>, cudaFuncAttributeMaxDynamicSharedMemorySize,
                         GEMM_SMEM_BYTES);
    cudaFuncSetAttribute(gemm_tf32<false>, cudaFuncAttributeMaxDynamicSharedMemorySize,
                         GEMM_SMEM_BYTES);

    // 0) round inputs/weights to tf32 bit patterns (kv_a_w padded 576 -> 640 rows)
    launch_round(hidden, hr,    (size_t)S_LEN * HID, (size_t)S_LEN * HID);
    launch_round(q_a_w,  w_qa,  (size_t)QLR * HID,   (size_t)QLR * HID);
    launch_round(kv_a_w, w_kva, (size_t)576 * HID,   (size_t)640 * HID);
    launch_round(q_b_w,  w_qb,  (size_t)QDIM * QLR,  (size_t)QDIM * QLR);
    launch_round(kv_b_w, w_kvb, (size_t)KVDIM * KVLR,(size_t)KVDIM * KVLR);

    // 1) q_a = hidden @ q_a_w^T           [2048,1536]
    launch_gemm<true>(hr, w_qa, qa, S_LEN, QLR, HID);
    // 2) ckv = hidden @ kv_a_w^T          [2048,576]
    launch_gemm<true>(hr, w_kva, ckv, S_LEN, 576, HID);
    // 3) rmsnorm(q_a) in place
    rmsnorm_kernel<<<S_LEN, 256>>>(qa, QLR, q_a_ln, qa, QLR, QLR);
    // 4) rmsnorm(ckv[:, :512]) -> ckvn
    rmsnorm_kernel<<<S_LEN, 256>>>(ckv, 576, kv_a_ln, ckvn, KVLR, KVLR);
    // 5) rope(k_pe) -> kpe
    kpe_rope_kernel<<<(S_LEN * 32 + 255) / 256, 256>>>(ckv, pos, cosb, sinb, kpe);
    // 6) q = qa_n @ q_b_w^T               [2048,3072]
    launch_gemm<true>(qa, w_qb, q, S_LEN, QDIM, QLR);
    // 7) kv = ckvn @ kv_b_w^T             [2048,4096]
    launch_gemm<true>(ckvn, w_kvb, kv, S_LEN, KVDIM, KVLR);
    // 8) rope(q_pe) in place
    q_rope_kernel<<<(S_LEN * NH * 32 + 255) / 256, 256>>>(q, pos, cosb, sinb);
    // 9) attention -> attn                [2048,2048]
    attn_kernel<<<dim3(32, NH), 256, ATT_SMEM_WORDS * 4>>>(q, kv, kpe, attn);
    // 10) round o_w
    launch_round(o_w, w_o, (size_t)HID * AODIM, (size_t)HID * AODIM);
    // 11) out = attn @ o_w^T              [2048,2048]
    launch_gemm<false>(attn, w_o, out, S_LEN, HID, AODIM);
}

// round 11
// speedup vs baseline: 1.3229x; 1.0977x over previous
#include <cuda_runtime.h>
#include <cuda_bf16.h>
#include <math.h>

// Problem constants
#define S_LEN 2048
#define HID   2048
#define NH    16
#define DN    128
#define DR    64
#define DV    128
#define DQ    192      // DN + DR
#define QLR   1536
#define KVLR  512
#define QDIM  (NH * DQ)        // 3072
#define KVDIM (NH * (DN + DV)) // 4096
#define AODIM (NH * DV)        // 2048
#define SCALE 0.07216878364870323f  // 192^-0.5
#define EPSV  1e-6f

// ---------------- scratch (allocation-free: __device__ global) ----------------
#define OFF_QA    0UL
#define OFF_Q     (OFF_QA   + (size_t)S_LEN * QLR)
#define OFF_CKV   (OFF_Q    + (size_t)S_LEN * QDIM)
#define OFF_CKVN  (OFF_CKV  + (size_t)S_LEN * 576)
#define OFF_KPE   (OFF_CKVN + (size_t)S_LEN * KVLR)
#define OFF_KV    (OFF_KPE  + (size_t)S_LEN * DR)
#define OFF_ATTN  (OFF_KV   + (size_t)S_LEN * KVDIM)
// rounded (tf32-in-fp32) copies. w_qa and w_kva MUST stay adjacent (fused GEMM
// treats them as one 2176-row weight).
#define OFF_HR    (OFF_ATTN + (size_t)S_LEN * AODIM)
#define OFF_W_QA  (OFF_HR   + (size_t)S_LEN * HID)
#define OFF_W_KVA (OFF_W_QA + (size_t)QLR * HID)          // padded to 640 rows
#define OFF_W_QB  (OFF_W_KVA + (size_t)640 * HID)
#define OFF_W_KVB (OFF_W_QB + (size_t)QDIM * QLR)
#define OFF_W_O   (OFF_W_KVB + (size_t)KVDIM * KVLR)
#define SCRATCH_TOTAL (OFF_W_O + (size_t)HID * AODIM)

__device__ float g_scratch[SCRATCH_TOTAL];

// ---------------- helpers ------------------------------------------------------
__device__ __forceinline__ unsigned f2tf(float x) {
    unsigned u;
    asm("cvt.rna.tf32.f32 %0, %1;" : "=r"(u) : "f"(x));
    return u;
}
__device__ __forceinline__ float rtf(float x) { return __uint_as_float(f2tf(x)); }

__device__ __forceinline__ void mma8(float* d, const unsigned* a, const unsigned* b) {
    asm volatile(
        "mma.sync.aligned.m16n8k8.row.col.f32.tf32.tf32.f32 "
        "{%0,%1,%2,%3},{%4,%5,%6,%7},{%8,%9},{%0,%1,%2,%3};\n"
        : "+f"(d[0]), "+f"(d[1]), "+f"(d[2]), "+f"(d[3])
        : "r"(a[0]), "r"(a[1]), "r"(a[2]), "r"(a[3]), "r"(b[0]), "r"(b[1]));
}

__device__ __forceinline__ void cpa16(unsigned saddr, const void* g) {
    asm volatile("cp.async.cg.shared.global [%0], [%1], 16;\n" :: "r"(saddr), "l"(g));
}
__device__ __forceinline__ void cp_commit() { asm volatile("cp.async.commit_group;\n"); }
template <int N> __device__ __forceinline__ void cp_wait() {
    asm volatile("cp.async.wait_group %0;\n" :: "n"(N));
}

// ---------------- fused rounding pass (all 6 tensors in one launch) -------------
// segment boundaries in float4 units (compile-time)
#define RN_H    ((S_LEN * HID) / 4)            // 1,048,576
#define RN_QA   ((QLR * HID) / 4)              //   786,432
#define RN_KVAD ((640 * HID) / 4)              //   327,680 (dst, padded)
#define RN_KVAS ((576 * HID) / 4)              //   294,912 (src)
#define RN_QB   ((QDIM * QLR) / 4)             // 1,179,648
#define RN_KVB  ((KVDIM * KVLR) / 4)           //   524,288
#define RN_O    ((HID * AODIM) / 4)            // 1,048,576
#define RB0 RN_H
#define RB1 (RB0 + RN_QA)
#define RB2 (RB1 + RN_KVAD)
#define RB3 (RB2 + RN_QB)
#define RB4 (RB3 + RN_KVB)
#define RB5 (RB4 + RN_O)

__global__ __launch_bounds__(256) void round_all(
    const float4* __restrict__ h,    const float4* __restrict__ wqa,
    const float4* __restrict__ wkva, const float4* __restrict__ wqb,
    const float4* __restrict__ wkvb, const float4* __restrict__ wo,
    float4* __restrict__ dh,   float4* __restrict__ dqa,  float4* __restrict__ dkva,
    float4* __restrict__ dqb,  float4* __restrict__ dkvb, float4* __restrict__ dwo)
{
    int i = blockIdx.x * blockDim.x + threadIdx.x;
    if (i >= RB5) return;
    const float4* src; float4* dst; int loc; bool ok = true;
    if (i < RB0)      { src = h;    dst = dh;   loc = i; }
    else if (i < RB1) { src = wqa;  dst = dqa;  loc = i - RB0; }
    else if (i < RB2) { src = wkva; dst = dkva; loc = i - RB1; ok = (loc < RN_KVAS); }
    else if (i < RB3) { src = wqb;  dst = dqb;  loc = i - RB2; }
    else if (i < RB4) { src = wkvb; dst = dkvb; loc = i - RB3; }
    else              { src = wo;   dst = dwo;  loc = i - RB4; }
    float4 v = make_float4(0.f, 0.f, 0.f, 0.f);
    if (ok) v = src[loc];
    v.x = rtf(v.x); v.y = rtf(v.y); v.z = rtf(v.z); v.w = rtf(v.w);
    dst[loc] = v;
}

// ---------------- GEMM: C[M,N] = A[M,K] * W[N,K]^T, tf32, cp.async 2-stage -----
// BM=128, BN=128, BK=32, 128 threads (4 warps, 2x2), warp tile 64x64.
#define GS 36                      // smem k-stride: 36 % 8 == 4 -> conflict-free
#define STG_WORDS (2 * 128 * GS)   // A + B per stage
#define GEMM_SMEM_BYTES (2 * STG_WORDS * 4)

__device__ __forceinline__ void gemm_issue(
    const float* __restrict__ A, const float* __restrict__ W, int K,
    int m0, int n0, int k0, unsigned sa, unsigned sb, int t)
{
#pragma unroll
    for (int i = 0; i < 8; i++) {
        int id = t + 128 * i;
        int r = id >> 3, c4 = (id & 7) << 2;
        cpa16(sa + (unsigned)(r * GS + c4) * 4u, A + (size_t)(m0 + r) * K + k0 + c4);
    }
#pragma unroll
    for (int i = 0; i < 8; i++) {
        int id = t + 128 * i;
        int r = id >> 3, c4 = (id & 7) << 2;
        cpa16(sb + (unsigned)(r * GS + c4) * 4u, W + (size_t)(n0 + r) * K + k0 + c4);
    }
    cp_commit();
}

// shared mainloop: accumulates the 128x128 tile into acc
__device__ __forceinline__ void gemm_mainloop(
    const float* __restrict__ A, const float* __restrict__ W, int K,
    int m0, int n0, unsigned* sm, float acc[4][8][4],
    int t, int warpM, int warpN, int ln4, int lnk)
{
    unsigned sbase = (unsigned)__cvta_generic_to_shared(sm);
    const int nIter = K >> 5;
    gemm_issue(A, W, K, m0, n0, 0, sbase, sbase + 128 * GS * 4, t);
    for (int it = 0; it < nIter; it++) {
        const int buf = it & 1;
        if (it + 1 < nIter) {
            const int nb = buf ^ 1;
            gemm_issue(A, W, K, m0, n0, (it + 1) << 5,
                       sbase + (unsigned)(nb * STG_WORDS) * 4u,
                       sbase + (unsigned)(nb * STG_WORDS + 128 * GS) * 4u, t);
            cp_wait<1>();
        } else {
            cp_wait<0>();
        }
        __syncthreads();
        const unsigned* As = sm + buf * STG_WORDS;
        const unsigned* Bs = As + 128 * GS;
#pragma unroll
        for (int ks = 0; ks < 4; ks++) {
            const int kk = ks * 8;
            unsigned a[4][4];
#pragma unroll
            for (int mt = 0; mt < 4; mt++) {
                const unsigned* p = As + (warpM * 64 + mt * 16 + ln4) * GS + kk + lnk;
                a[mt][0] = p[0];
                a[mt][1] = p[8 * GS];
                a[mt][2] = p[4];
                a[mt][3] = p[8 * GS + 4];
            }
#pragma unroll
            for (int nt = 0; nt < 8; nt++) {
                const unsigned* p = Bs + (warpN * 64 + nt * 8 + ln4) * GS + kk + lnk;
                unsigned b[2] = { p[0], p[4] };
#pragma unroll
                for (int mt = 0; mt < 4; mt++) mma8(acc[mt][nt], a[mt], b);
            }
        }
        __syncthreads();
    }
}

template <bool RND>
__global__ __launch_bounds__(128, 2) void gemm_tf32(
    const float* __restrict__ A, const float* __restrict__ W,
    float* __restrict__ C, int M, int N, int K)
{
    extern __shared__ unsigned sm[];
    const int t = threadIdx.x;
    const int lane = t & 31, wid = t >> 5;
    const int ln4 = lane >> 2, lnk = lane & 3;
    const int warpM = wid & 1, warpN = wid >> 1;
    const int m0 = blockIdx.y * 128, n0 = blockIdx.x * 128;

    float acc[4][8][4];
#pragma unroll
    for (int mt = 0; mt < 4; mt++)
#pragma unroll
        for (int nt = 0; nt < 8; nt++)
#pragma unroll
            for (int j = 0; j < 4; j++) acc[mt][nt][j] = 0.f;

    gemm_mainloop(A, W, K, m0, n0, sm, acc, t, warpM, warpN, ln4, lnk);

#pragma unroll
    for (int mt = 0; mt < 4; mt++) {
        int r0 = m0 + warpM * 64 + mt * 16 + ln4;
#pragma unroll
        for (int nt = 0; nt < 8; nt++) {
            int c = n0 + warpN * 64 + nt * 8 + 2 * lnk;
            if (c < N) {
                float v0 = acc[mt][nt][0], v1 = acc[mt][nt][1];
                float v2 = acc[mt][nt][2], v3 = acc[mt][nt][3];
                if (RND) { v0 = rtf(v0); v1 = rtf(v1); v2 = rtf(v2); v3 = rtf(v3); }
                *(float2*)(C + (size_t)r0 * N + c)       = make_float2(v0, v1);
                *(float2*)(C + (size_t)(r0 + 8) * N + c) = make_float2(v2, v3);
            }
        }
    }
}

// Fused down-projection GEMM: A[2048,2048] x Wcat[2176,2048]^T.
// Wcat = [q_a_w (1536 rows); kv_a_w padded (640 rows)] contiguous in scratch.
// cols [0,1536) -> qa (ld 1536); cols [1536,2112) -> ckv (ld 576); rest dropped.
__global__ __launch_bounds__(128, 2) void gemm_a_fused(
    const float* __restrict__ A, const float* __restrict__ W,
    float* __restrict__ qa, float* __restrict__ ckv)
{
    extern __shared__ unsigned sm[];
    const int t = threadIdx.x;
    const int lane = t & 31, wid = t >> 5;
    const int ln4 = lane >> 2, lnk = lane & 3;
    const int warpM = wid & 1, warpN = wid >> 1;
    const int m0 = blockIdx.y * 128, n0 = blockIdx.x * 128;

    float acc[4][8][4];
#pragma unroll
    for (int mt = 0; mt < 4; mt++)
#pragma unroll
        for (int nt = 0; nt < 8; nt++)
#pragma unroll
            for (int j = 0; j < 4; j++) acc[mt][nt][j] = 0.f;

    gemm_mainloop(A, W, HID, m0, n0, sm, acc, t, warpM, warpN, ln4, lnk);

#pragma unroll
    for (int mt = 0; mt < 4; mt++) {
        int r0 = m0 + warpM * 64 + mt * 16 + ln4;
#pragma unroll
        for (int nt = 0; nt < 8; nt++) {
            int c = n0 + warpN * 64 + nt * 8 + 2 * lnk;
            float v0 = rtf(acc[mt][nt][0]), v1 = rtf(acc[mt][nt][1]);
            float v2 = rtf(acc[mt][nt][2]), v3 = rtf(acc[mt][nt][3]);
            if (c < QLR) {
                *(float2*)(qa + (size_t)r0 * QLR + c)       = make_float2(v0, v1);
                *(float2*)(qa + (size_t)(r0 + 8) * QLR + c) = make_float2(v2, v3);
            } else {
                int cc = c - QLR;
                if (cc < 576) {
                    *(float2*)(ckv + (size_t)r0 * 576 + cc)       = make_float2(v0, v1);
                    *(float2*)(ckv + (size_t)(r0 + 8) * 576 + cc) = make_float2(v2, v3);
                }
            }
        }
    }
}

// ---------------- RMSNorm (writes tf32-rounded) ---------------------------------
__global__ __launch_bounds__(256) void rmsnorm_kernel(
    const float* __restrict__ X, int ldx, const float* __restrict__ w,
    float* __restrict__ Y, int ldy, int n)
{
    const int row = blockIdx.x;
    const float* x = X + (size_t)row * ldx;
    float* y = Y + (size_t)row * ldy;

    float s = 0.f;
    for (int i = threadIdx.x; i < n; i += blockDim.x) { float v = x[i]; s += v * v; }

    __shared__ float red[8];
    int lane = threadIdx.x & 31, wid = threadIdx.x >> 5;
#pragma unroll
    for (int o = 16; o; o >>= 1) s += __shfl_down_sync(0xFFFFFFFFu, s, o);
    if (!lane) red[wid] = s;
    __syncthreads();
    if (wid == 0) {
        s = (lane < 8) ? red[lane] : 0.f;
#pragma unroll
        for (int o = 4; o; o >>= 1) s += __shfl_down_sync(0xFFFFFFFFu, s, o);
        if (!lane) red[0] = s;
    }
    __syncthreads();
    const float inv = rsqrtf(red[0] / (float)n + EPSV);
    for (int i = threadIdx.x; i < n; i += blockDim.x) y[i] = rtf(x[i] * inv * w[i]);
}

// ---------------- k_pe RoPE (writes rounded) ------------------------------------
__global__ __launch_bounds__(256) void kpe_rope_kernel(
    const float* __restrict__ ckv, const int* __restrict__ pos,
    const float* __restrict__ cosb, const float* __restrict__ sinb,
    float* __restrict__ kpe)
{
    int warp = (blockIdx.x * blockDim.x + threadIdx.x) >> 5;
    int lane = threadIdx.x & 31;
    if (warp >= S_LEN) return;
    int s = warp;
    int p = pos[s];
    const float* x = ckv + (size_t)s * 576 + 512;
    float x0 = x[2 * lane], x1 = x[2 * lane + 1];
    float c0 = cosb[(size_t)p * DR + lane],      s0 = sinb[(size_t)p * DR + lane];
    float c1 = cosb[(size_t)p * DR + 32 + lane], s1 = sinb[(size_t)p * DR + 32 + lane];
    kpe[(size_t)s * DR + lane]      = rtf(x0 * c0 - x1 * s0);
    kpe[(size_t)s * DR + 32 + lane] = rtf(x1 * c1 + x0 * s1);
}

// ---------------- q_pe RoPE (in place, writes rounded) --------------------------
__global__ __launch_bounds__(256) void q_rope_kernel(
    float* __restrict__ Q, const int* __restrict__ pos,
    const float* __restrict__ cosb, const float* __restrict__ sinb)
{
    int warp = (blockIdx.x * blockDim.x + threadIdx.x) >> 5;
    int lane = threadIdx.x & 31;
    if (warp >= S_LEN * NH) return;
    int s = warp >> 4, h = warp & 15;
    int p = pos[s];
    float* x = Q + (size_t)s * QDIM + h * DQ + DN;
    float x0 = x[2 * lane], x1 = x[2 * lane + 1];
    float c0 = cosb[(size_t)p * DR + lane],      s0 = sinb[(size_t)p * DR + lane];
    float c1 = cosb[(size_t)p * DR + 32 + lane], s1 = sinb[(size_t)p * DR + 32 + lane];
    float o0 = rtf(x0 * c0 - x1 * s0);
    float o1 = rtf(x1 * c1 + x0 * s1);
    __syncwarp();
    x[lane]      = o0;
    x[32 + lane] = o1;
}

// ---------------- Flash attention (causal, tf32 mma.sync) -----------------------
// R7-exact attention: Q in smem, fused coalesced K/V loads, no double buffer.
#define QKS 196
#define VS_ 136
#define PS_ 68
#define ATT_SMEM_WORDS (2 * 64 * QKS + 64 * VS_ + 64 * PS_ + 3 * 64)

__global__ __launch_bounds__(256) void attn_kernel(
    const float* __restrict__ Q, const float* __restrict__ KV,
    const float* __restrict__ KPE, float* __restrict__ O)
{
    extern __shared__ unsigned smu[];
    unsigned* Qs = smu;
    unsigned* Ks = Qs + 64 * QKS;
    unsigned* Vs = Ks + 64 * QKS;
    unsigned* Ps = Vs + 64 * VS_;
    float* mrow = (float*)(Ps + 64 * PS_);
    float* lrow = mrow + 64;
    float* arow = lrow + 64;

    const int h  = blockIdx.y;
    const int qb = 31 - blockIdx.x;
    const int q0 = qb * 64;
    const int t    = threadIdx.x;
    const int lane = t & 31;
    const int wid  = t >> 5;
    const int ln4  = lane >> 2;
    const int lnk  = lane & 3;
    const int warpM = wid & 3;
    const int warpN = wid >> 2;

    const float* KVh = KV + h * 256;

    for (int idx = t; idx < 64 * 48; idx += 256) {
        int r = idx / 48, c4 = (idx % 48) * 4;
        *(float4*)(Qs + r * QKS + c4) =
            *(const float4*)(Q + (size_t)(q0 + r) * QDIM + h * DQ + c4);
    }
    if (t < 64) { mrow[t] = -1e30f; lrow[t] = 0.f; }

    float o[8][4];
#pragma unroll
    for (int nt = 0; nt < 8; nt++)
#pragma unroll
        for (int j = 0; j < 4; j++) o[nt][j] = 0.f;
    __syncthreads();

    for (int kt = 0; kt <= qb; kt++) {
        const int k0 = kt * 64;
        // fused K-nope + V load: one coalesced sweep of 64 float4 per kv row
#pragma unroll
        for (int i = 0; i < 16; i++) {
            int idx = t + 256 * i;            // 0 .. 4095
            int r = idx >> 6, c4 = (idx & 63) << 2;
            float4 v = *(const float4*)(KVh + (size_t)(k0 + r) * KVDIM + c4);
            if (c4 < 128) *(float4*)(Ks + r * QKS + c4)         = v;
            else          *(float4*)(Vs + r * VS_ + (c4 - 128)) = v;
        }
        // kpe -> Ks cols 128..191
#pragma unroll
        for (int i = 0; i < 4; i++) {
            int idx = t + 256 * i;            // 0 .. 1023
            int r = idx >> 4, c4 = (idx & 15) << 2;
            *(float4*)(Ks + r * QKS + 128 + c4) =
                *(const float4*)(KPE + (size_t)(k0 + r) * DR + c4);
        }
        __syncthreads();

        // ---- S = Q K^T ----
        float sacc[4][4];
#pragma unroll
        for (int nt = 0; nt < 4; nt++)
#pragma unroll
            for (int j = 0; j < 4; j++) sacc[nt][j] = 0.f;

        const unsigned* qbase = Qs + (warpM * 16 + ln4) * QKS + lnk;
#pragma unroll 4
        for (int ks = 0; ks < 24; ks++) {
            const int kk = ks * 8;
            unsigned a[4];
            a[0] = qbase[kk];
            a[1] = qbase[8 * QKS + kk];
            a[2] = qbase[kk + 4];
            a[3] = qbase[8 * QKS + kk + 4];
#pragma unroll
            for (int nt = 0; nt < 4; nt++) {
                const unsigned* p = Ks + (warpN * 32 + nt * 8 + ln4) * QKS + kk + lnk;
                unsigned b[2] = { p[0], p[4] };
                mma8(sacc[nt], a, b);
            }
        }

        const bool diag = (kt == qb);
        const int rl0 = warpM * 16 + ln4;
#pragma unroll
        for (int nt = 0; nt < 4; nt++) {
            int cl = warpN * 32 + nt * 8 + 2 * lnk;
            float v0 = sacc[nt][0] * SCALE;
            float v1 = sacc[nt][1] * SCALE;
            float v2 = sacc[nt][2] * SCALE;
            float v3 = sacc[nt][3] * SCALE;
            if (diag) {
                if (cl     > rl0)     v0 = -1e30f;
                if (cl + 1 > rl0)     v1 = -1e30f;
                if (cl     > rl0 + 8) v2 = -1e30f;
                if (cl + 1 > rl0 + 8) v3 = -1e30f;
            }
            Ps[rl0 * PS_ + cl]           = __float_as_uint(v0);
            Ps[rl0 * PS_ + cl + 1]       = __float_as_uint(v1);
            Ps[(rl0 + 8) * PS_ + cl]     = __float_as_uint(v2);
            Ps[(rl0 + 8) * PS_ + cl + 1] = __float_as_uint(v3);
        }
        __syncthreads();

        // ---- online softmax: 4 threads per row ----
        {
            const int r = t >> 2, seg = t & 3;
            const float* pf = (const float*)Ps + r * PS_ + seg * 16;
            unsigned* pu = Ps + r * PS_ + seg * 16;
            float mprev = mrow[r];
            float mx = mprev;
#pragma unroll
            for (int j = 0; j < 16; j++) mx = fmaxf(mx, pf[j]);
            mx = fmaxf(mx, __shfl_xor_sync(0xFFFFFFFFu, mx, 1));
            mx = fmaxf(mx, __shfl_xor_sync(0xFFFFFFFFu, mx, 2));
            float alpha = __expf(mprev - mx);
            float s = 0.f;
#pragma unroll
            for (int j = 0; j < 16; j++) {
                float e = __expf(pf[j] - mx);
                s += e;
                pu[j] = f2tf(e);
            }
            s += __shfl_xor_sync(0xFFFFFFFFu, s, 1);
            s += __shfl_xor_sync(0xFFFFFFFFu, s, 2);
            if (seg == 0) {
                mrow[r] = mx;
                lrow[r] = lrow[r] * alpha + s;
                arow[r] = alpha;
            }
        }
        __syncthreads();

        // ---- O = O*alpha + P @ V ----
        {
            float ar0 = arow[warpM * 16 + ln4];
            float ar1 = arow[warpM * 16 + ln4 + 8];
#pragma unroll
            for (int nt = 0; nt < 8; nt++) {
                o[nt][0] *= ar0; o[nt][1] *= ar0;
                o[nt][2] *= ar1; o[nt][3] *= ar1;
            }
            const unsigned* pbase = Ps + (warpM * 16 + ln4) * PS_ + lnk;
#pragma unroll
            for (int ks = 0; ks < 8; ks++) {
                const int kk = ks * 8;
                unsigned a[4];
                a[0] = pbase[kk];
                a[1] = pbase[8 * PS_ + kk];
                a[2] = pbase[kk + 4];
                a[3] = pbase[8 * PS_ + kk + 4];
#pragma unroll
                for (int nt = 0; nt < 8; nt++) {
                    const unsigned* p = Vs + (kk + lnk) * VS_ + warpN * 64 + nt * 8 + ln4;
                    unsigned b[2] = { p[0], p[4 * VS_] };
                    mma8(o[nt], a, b);
                }
            }
        }
        __syncthreads();
    }

    {
        float inv0 = 1.f / lrow[warpM * 16 + ln4];
        float inv1 = 1.f / lrow[warpM * 16 + ln4 + 8];
        int r0 = q0 + warpM * 16 + ln4;
#pragma unroll
        for (int nt = 0; nt < 8; nt++) {
            int c = warpN * 64 + nt * 8 + 2 * lnk;
            float* dst0 = O + (size_t)r0 * AODIM + h * DV + c;
            float* dst1 = O + (size_t)(r0 + 8) * AODIM + h * DV + c;
            *(float2*)dst0 = make_float2(rtf(o[nt][0] * inv0), rtf(o[nt][1] * inv0));
            *(float2*)dst1 = make_float2(rtf(o[nt][2] * inv1), rtf(o[nt][3] * inv1));
        }
    }
}

// ---------------- host launcher ---------------------------------------------------
template <bool RND>
static inline void launch_gemm(const float* A, const float* W, float* C,
                               int M, int N, int K) {
    dim3 grid((N + 127) / 128, M / 128);
    gemm_tf32<RND><<<grid, 128, GEMM_SMEM_BYTES>>>(A, W, C, M, N, K);
}

extern "C" void kernel_launch(void* const* d_in, const int* in_sizes, int n_in,
                              void* d_out, int out_size)
{
    const float* hidden  = (const float*)d_in[0];
    const float* q_a_w   = (const float*)d_in[1];
    const float* q_a_ln  = (const float*)d_in[2];
    const float* q_b_w   = (const float*)d_in[3];
    const float* kv_a_w  = (const float*)d_in[4];
    const float* kv_a_ln = (const float*)d_in[5];
    const float* kv_b_w  = (const float*)d_in[6];
    const float* o_w     = (const float*)d_in[7];
    const float* cosb    = (const float*)d_in[8];
    const float* sinb    = (const float*)d_in[9];
    // d_in[10] = attention_mask (causal triu; semantics reproduced directly)
    const int*   pos     = (const int*)d_in[11];
    float* out = (float*)d_out;

    float* base;
    cudaGetSymbolAddress((void**)&base, g_scratch);
    float* qa    = base + OFF_QA;
    float* q     = base + OFF_Q;
    float* ckv   = base + OFF_CKV;
    float* ckvn  = base + OFF_CKVN;
    float* kpe   = base + OFF_KPE;
    float* kv    = base + OFF_KV;
    float* attn  = base + OFF_ATTN;
    float* hr    = base + OFF_HR;
    float* w_qa  = base + OFF_W_QA;
    float* w_kva = base + OFF_W_KVA;
    float* w_qb  = base + OFF_W_QB;
    float* w_kvb = base + OFF_W_KVB;
    float* w_o   = base + OFF_W_O;

    cudaFuncSetAttribute(attn_kernel, cudaFuncAttributeMaxDynamicSharedMemorySize,
                         ATT_SMEM_WORDS * 4);
    cudaFuncSetAttribute(gemm_tf32<true>, cudaFuncAttributeMaxDynamicSharedMemorySize,
                         GEMM_SMEM_BYTES);
    cudaFuncSetAttribute(gemm_tf32<false>, cudaFuncAttributeMaxDynamicSharedMemorySize,
                         GEMM_SMEM_BYTES);
    cudaFuncSetAttribute(gemm_a_fused, cudaFuncAttributeMaxDynamicSharedMemorySize,
                         GEMM_SMEM_BYTES);

    // 0) all 6 rounding passes in one launch
    round_all<<<(RB5 + 255) / 256, 256>>>(
        (const float4*)hidden, (const float4*)q_a_w, (const float4*)kv_a_w,
        (const float4*)q_b_w, (const float4*)kv_b_w, (const float4*)o_w,
        (float4*)hr, (float4*)w_qa, (float4*)w_kva,
        (float4*)w_qb, (float4*)w_kvb, (float4*)w_o);

    // 1+2) fused down-projection: qa[2048,1536] and ckv[2048,576] in one GEMM
    {
        dim3 grid(17, 16);   // N' = 2176 = 17 * 128
        gemm_a_fused<<<grid, 128, GEMM_SMEM_BYTES>>>(hr, w_qa, qa, ckv);
    }
    // 3) rmsnorm(q_a) in place
    rmsnorm_kernel<<<S_LEN, 256>>>(qa, QLR, q_a_ln, qa, QLR, QLR);
    // 4) rmsnorm(ckv[:, :512]) -> ckvn
    rmsnorm_kernel<<<S_LEN, 256>>>(ckv, 576, kv_a_ln, ckvn, KVLR, KVLR);
    // 5) rope(k_pe) -> kpe
    kpe_rope_kernel<<<(S_LEN * 32 + 255) / 256, 256>>>(ckv, pos, cosb, sinb, kpe);
    // 6) q = qa_n @ q_b_w^T               [2048,3072]
    launch_gemm<true>(qa, w_qb, q, S_LEN, QDIM, QLR);
    // 7) kv = ckvn @ kv_b_w^T             [2048,4096]
    launch_gemm<true>(ckvn, w_kvb, kv, S_LEN, KVDIM, KVLR);
    // 8) rope(q_pe) in place
    q_rope_kernel<<<(S_LEN * NH * 32 + 255) / 256, 256>>>(q, pos, cosb, sinb);
    // 9) attention -> attn                [2048,2048]
    attn_kernel<<<dim3(32, NH), 256, ATT_SMEM_WORDS * 4>>>(q, kv, kpe, attn);
    // 10) out = attn @ o_w^T              [2048,2048]
    launch_gemm<false>(attn, w_o, out, S_LEN, HID, AODIM);
}

// round 12
// speedup vs baseline: 1.5052x; 1.1377x over previous
#include <cuda_runtime.h>
#include <cuda_bf16.h>
#include <math.h>

// Problem constants
#define S_LEN 2048
#define HID   2048
#define NH    16
#define DN    128
#define DR    64
#define DV    128
#define DQ    192      // DN + DR
#define QLR   1536
#define KVLR  512
#define QDIM  (NH * DQ)        // 3072
#define KVDIM (NH * (DN + DV)) // 4096
#define AODIM (NH * DV)        // 2048
#define SCALE 0.07216878364870323f  // 192^-0.5
#define EPSV  1e-6f

// ---------------- scratch (allocation-free: __device__ global) ----------------
#define OFF_QA    0UL
#define OFF_Q     (OFF_QA   + (size_t)S_LEN * QLR)
#define OFF_CKV   (OFF_Q    + (size_t)S_LEN * QDIM)
#define OFF_CKVN  (OFF_CKV  + (size_t)S_LEN * 576)
#define OFF_KPE   (OFF_CKVN + (size_t)S_LEN * KVLR)
#define OFF_KV    (OFF_KPE  + (size_t)S_LEN * DR)
#define OFF_ATTN  (OFF_KV   + (size_t)S_LEN * KVDIM)
// rounded (tf32-in-fp32) copies. w_qa and w_kva MUST stay adjacent (fused GEMM).
#define OFF_HR    (OFF_ATTN + (size_t)S_LEN * AODIM)
#define OFF_W_QA  (OFF_HR   + (size_t)S_LEN * HID)
#define OFF_W_KVA (OFF_W_QA + (size_t)QLR * HID)          // padded to 640 rows
#define OFF_W_QB  (OFF_W_KVA + (size_t)640 * HID)
#define OFF_W_KVB (OFF_W_QB + (size_t)QDIM * QLR)
#define OFF_W_O   (OFF_W_KVB + (size_t)KVDIM * KVLR)
#define SCRATCH_TOTAL (OFF_W_O + (size_t)HID * AODIM)

__device__ float g_scratch[SCRATCH_TOTAL];

// ---------------- helpers ------------------------------------------------------
__device__ __forceinline__ unsigned f2tf(float x) {
    unsigned u;
    asm("cvt.rna.tf32.f32 %0, %1;" : "=r"(u) : "f"(x));
    return u;
}
__device__ __forceinline__ float rtf(float x) { return __uint_as_float(f2tf(x)); }

__device__ __forceinline__ void mma8(float* d, const unsigned* a, const unsigned* b) {
    asm volatile(
        "mma.sync.aligned.m16n8k8.row.col.f32.tf32.tf32.f32 "
        "{%0,%1,%2,%3},{%4,%5,%6,%7},{%8,%9},{%0,%1,%2,%3};\n"
        : "+f"(d[0]), "+f"(d[1]), "+f"(d[2]), "+f"(d[3])
        : "r"(a[0]), "r"(a[1]), "r"(a[2]), "r"(a[3]), "r"(b[0]), "r"(b[1]));
}

__device__ __forceinline__ void cpa16(unsigned saddr, const void* g) {
    asm volatile("cp.async.cg.shared.global [%0], [%1], 16;\n" :: "r"(saddr), "l"(g));
}
__device__ __forceinline__ void cp_commit() { asm volatile("cp.async.commit_group;\n"); }
template <int N> __device__ __forceinline__ void cp_wait() {
    asm volatile("cp.async.wait_group %0;\n" :: "n"(N));
}

// ---------------- fused rounding pass (all 6 tensors in one launch) -------------
#define RN_H    ((S_LEN * HID) / 4)
#define RN_QA   ((QLR * HID) / 4)
#define RN_KVAD ((640 * HID) / 4)
#define RN_KVAS ((576 * HID) / 4)
#define RN_QB   ((QDIM * QLR) / 4)
#define RN_KVB  ((KVDIM * KVLR) / 4)
#define RN_O    ((HID * AODIM) / 4)
#define RB0 RN_H
#define RB1 (RB0 + RN_QA)
#define RB2 (RB1 + RN_KVAD)
#define RB3 (RB2 + RN_QB)
#define RB4 (RB3 + RN_KVB)
#define RB5 (RB4 + RN_O)

__global__ __launch_bounds__(256) void round_all(
    const float4* __restrict__ h,    const float4* __restrict__ wqa,
    const float4* __restrict__ wkva, const float4* __restrict__ wqb,
    const float4* __restrict__ wkvb, const float4* __restrict__ wo,
    float4* __restrict__ dh,   float4* __restrict__ dqa,  float4* __restrict__ dkva,
    float4* __restrict__ dqb,  float4* __restrict__ dkvb, float4* __restrict__ dwo)
{
    int i = blockIdx.x * blockDim.x + threadIdx.x;
    if (i >= RB5) return;
    const float4* src; float4* dst; int loc; bool ok = true;
    if (i < RB0)      { src = h;    dst = dh;   loc = i; }
    else if (i < RB1) { src = wqa;  dst = dqa;  loc = i - RB0; }
    else if (i < RB2) { src = wkva; dst = dkva; loc = i - RB1; ok = (loc < RN_KVAS); }
    else if (i < RB3) { src = wqb;  dst = dqb;  loc = i - RB2; }
    else if (i < RB4) { src = wkvb; dst = dkvb; loc = i - RB3; }
    else              { src = wo;   dst = dwo;  loc = i - RB4; }
    float4 v = make_float4(0.f, 0.f, 0.f, 0.f);
    if (ok) v = src[loc];
    v.x = rtf(v.x); v.y = rtf(v.y); v.z = rtf(v.z); v.w = rtf(v.w);
    dst[loc] = v;
}

// ---------------- GEMM: C[M,N] = A[M,K] * W[N,K]^T, tf32, cp.async 2-stage -----
// BM=128, BN=128, BK=32, 128 threads (4 warps, 2x2), warp tile 64x64.
#define GS 36
#define STG_WORDS (2 * 128 * GS)
#define GEMM_SMEM_BYTES (2 * STG_WORDS * 4)

__device__ __forceinline__ void gemm_issue(
    const float* __restrict__ A, const float* __restrict__ W, int K,
    int m0, int n0, int k0, unsigned sa, unsigned sb, int t)
{
#pragma unroll
    for (int i = 0; i < 8; i++) {
        int id = t + 128 * i;
        int r = id >> 3, c4 = (id & 7) << 2;
        cpa16(sa + (unsigned)(r * GS + c4) * 4u, A + (size_t)(m0 + r) * K + k0 + c4);
    }
#pragma unroll
    for (int i = 0; i < 8; i++) {
        int id = t + 128 * i;
        int r = id >> 3, c4 = (id & 7) << 2;
        cpa16(sb + (unsigned)(r * GS + c4) * 4u, W + (size_t)(n0 + r) * K + k0 + c4);
    }
    cp_commit();
}

__device__ __forceinline__ void gemm_mainloop(
    const float* __restrict__ A, const float* __restrict__ W, int K,
    int m0, int n0, unsigned* sm, float acc[4][8][4],
    int t, int warpM, int warpN, int ln4, int lnk)
{
    unsigned sbase = (unsigned)__cvta_generic_to_shared(sm);
    const int nIter = K >> 5;
    gemm_issue(A, W, K, m0, n0, 0, sbase, sbase + 128 * GS * 4, t);
    for (int it = 0; it < nIter; it++) {
        const int buf = it & 1;
        if (it + 1 < nIter) {
            const int nb = buf ^ 1;
            gemm_issue(A, W, K, m0, n0, (it + 1) << 5,
                       sbase + (unsigned)(nb * STG_WORDS) * 4u,
                       sbase + (unsigned)(nb * STG_WORDS + 128 * GS) * 4u, t);
            cp_wait<1>();
        } else {
            cp_wait<0>();
        }
        __syncthreads();
        const unsigned* As = sm + buf * STG_WORDS;
        const unsigned* Bs = As + 128 * GS;
#pragma unroll
        for (int ks = 0; ks < 4; ks++) {
            const int kk = ks * 8;
            unsigned a[4][4];
#pragma unroll
            for (int mt = 0; mt < 4; mt++) {
                const unsigned* p = As + (warpM * 64 + mt * 16 + ln4) * GS + kk + lnk;
                a[mt][0] = p[0];
                a[mt][1] = p[8 * GS];
                a[mt][2] = p[4];
                a[mt][3] = p[8 * GS + 4];
            }
#pragma unroll
            for (int nt = 0; nt < 8; nt++) {
                const unsigned* p = Bs + (warpN * 64 + nt * 8 + ln4) * GS + kk + lnk;
                unsigned b[2] = { p[0], p[4] };
#pragma unroll
                for (int mt = 0; mt < 4; mt++) mma8(acc[mt][nt], a[mt], b);
            }
        }
        __syncthreads();
    }
}

template <bool RND>
__global__ __launch_bounds__(128, 2) void gemm_tf32(
    const float* __restrict__ A, const float* __restrict__ W,
    float* __restrict__ C, int M, int N, int K)
{
    extern __shared__ unsigned sm[];
    const int t = threadIdx.x;
    const int lane = t & 31, wid = t >> 5;
    const int ln4 = lane >> 2, lnk = lane & 3;
    const int warpM = wid & 1, warpN = wid >> 1;
    const int m0 = blockIdx.y * 128, n0 = blockIdx.x * 128;

    float acc[4][8][4];
#pragma unroll
    for (int mt = 0; mt < 4; mt++)
#pragma unroll
        for (int nt = 0; nt < 8; nt++)
#pragma unroll
            for (int j = 0; j < 4; j++) acc[mt][nt][j] = 0.f;

    gemm_mainloop(A, W, K, m0, n0, sm, acc, t, warpM, warpN, ln4, lnk);

#pragma unroll
    for (int mt = 0; mt < 4; mt++) {
        int r0 = m0 + warpM * 64 + mt * 16 + ln4;
#pragma unroll
        for (int nt = 0; nt < 8; nt++) {
            int c = n0 + warpN * 64 + nt * 8 + 2 * lnk;
            if (c < N) {
                float v0 = acc[mt][nt][0], v1 = acc[mt][nt][1];
                float v2 = acc[mt][nt][2], v3 = acc[mt][nt][3];
                if (RND) { v0 = rtf(v0); v1 = rtf(v1); v2 = rtf(v2); v3 = rtf(v3); }
                *(float2*)(C + (size_t)r0 * N + c)       = make_float2(v0, v1);
                *(float2*)(C + (size_t)(r0 + 8) * N + c) = make_float2(v2, v3);
            }
        }
    }
}

// Fused down-projection GEMM: A[2048,2048] x Wcat[2176,2048]^T.
__global__ __launch_bounds__(128, 2) void gemm_a_fused(
    const float* __restrict__ A, const float* __restrict__ W,
    float* __restrict__ qa, float* __restrict__ ckv)
{
    extern __shared__ unsigned sm[];
    const int t = threadIdx.x;
    const int lane = t & 31, wid = t >> 5;
    const int ln4 = lane >> 2, lnk = lane & 3;
    const int warpM = wid & 1, warpN = wid >> 1;
    const int m0 = blockIdx.y * 128, n0 = blockIdx.x * 128;

    float acc[4][8][4];
#pragma unroll
    for (int mt = 0; mt < 4; mt++)
#pragma unroll
        for (int nt = 0; nt < 8; nt++)
#pragma unroll
            for (int j = 0; j < 4; j++) acc[mt][nt][j] = 0.f;

    gemm_mainloop(A, W, HID, m0, n0, sm, acc, t, warpM, warpN, ln4, lnk);

#pragma unroll
    for (int mt = 0; mt < 4; mt++) {
        int r0 = m0 + warpM * 64 + mt * 16 + ln4;
#pragma unroll
        for (int nt = 0; nt < 8; nt++) {
            int c = n0 + warpN * 64 + nt * 8 + 2 * lnk;
            float v0 = rtf(acc[mt][nt][0]), v1 = rtf(acc[mt][nt][1]);
            float v2 = rtf(acc[mt][nt][2]), v3 = rtf(acc[mt][nt][3]);
            if (c < QLR) {
                *(float2*)(qa + (size_t)r0 * QLR + c)       = make_float2(v0, v1);
                *(float2*)(qa + (size_t)(r0 + 8) * QLR + c) = make_float2(v2, v3);
            } else {
                int cc = c - QLR;
                if (cc < 576) {
                    *(float2*)(ckv + (size_t)r0 * 576 + cc)       = make_float2(v0, v1);
                    *(float2*)(ckv + (size_t)(r0 + 8) * 576 + cc) = make_float2(v2, v3);
                }
            }
        }
    }
}

// ---------------- RMSNorm (writes tf32-rounded) ---------------------------------
__global__ __launch_bounds__(256) void rmsnorm_kernel(
    const float* __restrict__ X, int ldx, const float* __restrict__ w,
    float* __restrict__ Y, int ldy, int n)
{
    const int row = blockIdx.x;
    const float* x = X + (size_t)row * ldx;
    float* y = Y + (size_t)row * ldy;

    float s = 0.f;
    for (int i = threadIdx.x; i < n; i += blockDim.x) { float v = x[i]; s += v * v; }

    __shared__ float red[8];
    int lane = threadIdx.x & 31, wid = threadIdx.x >> 5;
#pragma unroll
    for (int o = 16; o; o >>= 1) s += __shfl_down_sync(0xFFFFFFFFu, s, o);
    if (!lane) red[wid] = s;
    __syncthreads();
    if (wid == 0) {
        s = (lane < 8) ? red[lane] : 0.f;
#pragma unroll
        for (int o = 4; o; o >>= 1) s += __shfl_down_sync(0xFFFFFFFFu, s, o);
        if (!lane) red[0] = s;
    }
    __syncthreads();
    const float inv = rsqrtf(red[0] / (float)n + EPSV);
    for (int i = threadIdx.x; i < n; i += blockDim.x) y[i] = rtf(x[i] * inv * w[i]);
}

// ---------------- k_pe RoPE (writes rounded) ------------------------------------
__global__ __launch_bounds__(256) void kpe_rope_kernel(
    const float* __restrict__ ckv, const int* __restrict__ pos,
    const float* __restrict__ cosb, const float* __restrict__ sinb,
    float* __restrict__ kpe)
{
    int warp = (blockIdx.x * blockDim.x + threadIdx.x) >> 5;
    int lane = threadIdx.x & 31;
    if (warp >= S_LEN) return;
    int s = warp;
    int p = pos[s];
    const float* x = ckv + (size_t)s * 576 + 512;
    float x0 = x[2 * lane], x1 = x[2 * lane + 1];
    float c0 = cosb[(size_t)p * DR + lane],      s0 = sinb[(size_t)p * DR + lane];
    float c1 = cosb[(size_t)p * DR + 32 + lane], s1 = sinb[(size_t)p * DR + 32 + lane];
    kpe[(size_t)s * DR + lane]      = rtf(x0 * c0 - x1 * s0);
    kpe[(size_t)s * DR + 32 + lane] = rtf(x1 * c1 + x0 * s1);
}

// ---------------- q_pe RoPE (in place, writes rounded) --------------------------
__global__ __launch_bounds__(256) void q_rope_kernel(
    float* __restrict__ Q, const int* __restrict__ pos,
    const float* __restrict__ cosb, const float* __restrict__ sinb)
{
    int warp = (blockIdx.x * blockDim.x + threadIdx.x) >> 5;
    int lane = threadIdx.x & 31;
    if (warp >= S_LEN * NH) return;
    int s = warp >> 4, h = warp & 15;
    int p = pos[s];
    float* x = Q + (size_t)s * QDIM + h * DQ + DN;
    float x0 = x[2 * lane], x1 = x[2 * lane + 1];
    float c0 = cosb[(size_t)p * DR + lane],      s0 = sinb[(size_t)p * DR + lane];
    float c1 = cosb[(size_t)p * DR + 32 + lane], s1 = sinb[(size_t)p * DR + 32 + lane];
    float o0 = rtf(x0 * c0 - x1 * s0);
    float o1 = rtf(x1 * c1 + x0 * s1);
    __syncwarp();
    x[lane]      = o0;
    x[32 + lane] = o1;
}

// ---------------- Flash attention (causal, tf32 mma.sync) -----------------------
// Q fragments in registers (FULL unroll -> no LMEM), K/V double-buffered cp.async.
#define QKS 196
#define VS_ 136
#define PS_ 68
#define ATT_SMEM_WORDS (2 * 64 * QKS + 2 * 64 * VS_ + 64 * PS_ + 3 * 64)

__global__ __launch_bounds__(256) void attn_kernel(
    const float* __restrict__ Q, const float* __restrict__ KV,
    const float* __restrict__ KPE, float* __restrict__ O)
{
    extern __shared__ unsigned smu[];
    unsigned* Ks0 = smu;                    // [2][64][QKS]
    unsigned* Vs0 = Ks0 + 2 * 64 * QKS;     // [2][64][VS_]
    unsigned* Ps  = Vs0 + 2 * 64 * VS_;     // [64][PS_]
    float* mrow = (float*)(Ps + 64 * PS_);
    float* lrow = mrow + 64;
    float* arow = lrow + 64;

    const unsigned sb = (unsigned)__cvta_generic_to_shared(smu);
    const unsigned ks_b = sb;
    const unsigned vs_b = sb + 2u * 64 * QKS * 4;

    const int h  = blockIdx.y;
    const int qb = 31 - blockIdx.x;
    const int q0 = qb * 64;
    const int t    = threadIdx.x;
    const int lane = t & 31;
    const int wid  = t >> 5;
    const int ln4  = lane >> 2;
    const int lnk  = lane & 3;
    const int warpM = wid & 3;
    const int warpN = wid >> 2;

    const float* KVh = KV + h * 256;

    // ---- stage Q tile [64 x 192] through K buffer 0, preload fragments ----
    for (int idx = t; idx < 64 * 48; idx += 256) {
        int r = idx / 48, c4 = (idx % 48) * 4;
        *(float4*)(Ks0 + r * QKS + c4) =
            *(const float4*)(Q + (size_t)(q0 + r) * QDIM + h * DQ + c4);
    }
    if (t < 64) { mrow[t] = -1e30f; lrow[t] = 0.f; }
    __syncthreads();

    unsigned qf[96];
    {
        const unsigned* qbase = Ks0 + (warpM * 16 + ln4) * QKS + lnk;
#pragma unroll
        for (int ks = 0; ks < 24; ks++) {
            const int kk = ks * 8;
            qf[ks * 4 + 0] = qbase[kk];
            qf[ks * 4 + 1] = qbase[8 * QKS + kk];
            qf[ks * 4 + 2] = qbase[kk + 4];
            qf[ks * 4 + 3] = qbase[8 * QKS + kk + 4];
        }
    }

    float o[8][4];
#pragma unroll
    for (int nt = 0; nt < 8; nt++)
#pragma unroll
        for (int j = 0; j < 4; j++) o[nt][j] = 0.f;
    __syncthreads();   // all warps done reading Q from Ks0[0]

    // ---- cp.async issue of one K/V tile into buffer `bf` ----
    auto issue_kv = [&](int kt, int bf) {
        const unsigned ksb = ks_b + (unsigned)bf * 64 * QKS * 4;
        const unsigned vsb = vs_b + (unsigned)bf * 64 * VS_ * 4;
        const float* rowbase = KVh + (size_t)(kt * 64) * KVDIM;
#pragma unroll
        for (int i = 0; i < 16; i++) {
            int idx = t + 256 * i;             // 0..4095
            int r = idx >> 6, c4 = (idx & 63) << 2;
            const float* src = rowbase + (size_t)r * KVDIM + c4;
            if (c4 < 128) cpa16(ksb + (unsigned)(r * QKS + c4) * 4u, src);
            else          cpa16(vsb + (unsigned)(r * VS_ + c4 - 128) * 4u, src);
        }
#pragma unroll
        for (int i = 0; i < 4; i++) {
            int idx = t + 256 * i;             // 0..1023
            int r = idx >> 4, c4 = (idx & 15) << 2;
            cpa16(ksb + (unsigned)(r * QKS + 128 + c4) * 4u,
                  KPE + (size_t)(kt * 64 + r) * DR + c4);
        }
        cp_commit();
    };

    issue_kv(0, 0);   // prologue

    for (int kt = 0; kt <= qb; kt++) {
        const int buf = kt & 1;
        if (kt < qb) { issue_kv(kt + 1, buf ^ 1); cp_wait<1>(); }
        else         { cp_wait<0>(); }
        __syncthreads();

        const unsigned* Ks = Ks0 + buf * 64 * QKS;
        const unsigned* Vs = Vs0 + buf * 64 * VS_;

        // ---- S = Q K^T (FULL unroll: qf indices compile-time constant) ----
        float sacc[4][4];
#pragma unroll
        for (int nt = 0; nt < 4; nt++)
#pragma unroll
            for (int j = 0; j < 4; j++) sacc[nt][j] = 0.f;

#pragma unroll
        for (int ks = 0; ks < 24; ks++) {
            const int kk = ks * 8;
#pragma unroll
            for (int nt = 0; nt < 4; nt++) {
                const unsigned* p = Ks + (warpN * 32 + nt * 8 + ln4) * QKS + kk + lnk;
                unsigned b[2] = { p[0], p[4] };
                mma8(sacc[nt], &qf[ks * 4], b);
            }
        }

        const bool diag = (kt == qb);
        const int rl0 = warpM * 16 + ln4;
#pragma unroll
        for (int nt = 0; nt < 4; nt++) {
            int cl = warpN * 32 + nt * 8 + 2 * lnk;
            float v0 = sacc[nt][0] * SCALE;
            float v1 = sacc[nt][1] * SCALE;
            float v2 = sacc[nt][2] * SCALE;
            float v3 = sacc[nt][3] * SCALE;
            if (diag) {
                if (cl     > rl0)     v0 = -1e30f;
                if (cl + 1 > rl0)     v1 = -1e30f;
                if (cl     > rl0 + 8) v2 = -1e30f;
                if (cl + 1 > rl0 + 8) v3 = -1e30f;
            }
            Ps[rl0 * PS_ + cl]           = __float_as_uint(v0);
            Ps[rl0 * PS_ + cl + 1]       = __float_as_uint(v1);
            Ps[(rl0 + 8) * PS_ + cl]     = __float_as_uint(v2);
            Ps[(rl0 + 8) * PS_ + cl + 1] = __float_as_uint(v3);
        }
        __syncthreads();

        // ---- online softmax: 4 threads per row ----
        {
            const int r = t >> 2, seg = t & 3;
            const float* pf = (const float*)Ps + r * PS_ + seg * 16;
            unsigned* pu = Ps + r * PS_ + seg * 16;
            float mprev = mrow[r];
            float mx = mprev;
#pragma unroll
            for (int j = 0; j < 16; j++) mx = fmaxf(mx, pf[j]);
            mx = fmaxf(mx, __shfl_xor_sync(0xFFFFFFFFu, mx, 1));
            mx = fmaxf(mx, __shfl_xor_sync(0xFFFFFFFFu, mx, 2));
            float alpha = __expf(mprev - mx);
            float s = 0.f;
#pragma unroll
            for (int j = 0; j < 16; j++) {
                float e = __expf(pf[j] - mx);
                s += e;
                pu[j] = f2tf(e);
            }
            s += __shfl_xor_sync(0xFFFFFFFFu, s, 1);
            s += __shfl_xor_sync(0xFFFFFFFFu, s, 2);
            if (seg == 0) {
                mrow[r] = mx;
                lrow[r] = lrow[r] * alpha + s;
                arow[r] = alpha;
            }
        }
        __syncthreads();

        // ---- O = O*alpha + P @ V ----
        {
            float ar0 = arow[warpM * 16 + ln4];
            float ar1 = arow[warpM * 16 + ln4 + 8];
#pragma unroll
            for (int nt = 0; nt < 8; nt++) {
                o[nt][0] *= ar0; o[nt][1] *= ar0;
                o[nt][2] *= ar1; o[nt][3] *= ar1;
            }
            const unsigned* pbase = Ps + (warpM * 16 + ln4) * PS_ + lnk;
#pragma unroll
            for (int ks = 0; ks < 8; ks++) {
                const int kk = ks * 8;
                unsigned a[4];
                a[0] = pbase[kk];
                a[1] = pbase[8 * PS_ + kk];
                a[2] = pbase[kk + 4];
                a[3] = pbase[8 * PS_ + kk + 4];
#pragma unroll
                for (int nt = 0; nt < 8; nt++) {
                    const unsigned* p = Vs + (kk + lnk) * VS_ + warpN * 64 + nt * 8 + ln4;
                    unsigned b[2] = { p[0], p[4 * VS_] };
                    mma8(o[nt], a, b);
                }
            }
        }
        __syncthreads();
    }

    {
        float inv0 = 1.f / lrow[warpM * 16 + ln4];
        float inv1 = 1.f / lrow[warpM * 16 + ln4 + 8];
        int r0 = q0 + warpM * 16 + ln4;
#pragma unroll
        for (int nt = 0; nt < 8; nt++) {
            int c = warpN * 64 + nt * 8 + 2 * lnk;
            float* dst0 = O + (size_t)r0 * AODIM + h * DV + c;
            float* dst1 = O + (size_t)(r0 + 8) * AODIM + h * DV + c;
            *(float2*)dst0 = make_float2(rtf(o[nt][0] * inv0), rtf(o[nt][1] * inv0));
            *(float2*)dst1 = make_float2(rtf(o[nt][2] * inv1), rtf(o[nt][3] * inv1));
        }
    }
}

// ---------------- host launcher ---------------------------------------------------
template <bool RND>
static inline void launch_gemm(const float* A, const float* W, float* C,
                               int M, int N, int K) {
    dim3 grid((N + 127) / 128, M / 128);
    gemm_tf32<RND><<<grid, 128, GEMM_SMEM_BYTES>>>(A, W, C, M, N, K);
}

extern "C" void kernel_launch(void* const* d_in, const int* in_sizes, int n_in,
                              void* d_out, int out_size)
{
    const float* hidden  = (const float*)d_in[0];
    const float* q_a_w   = (const float*)d_in[1];
    const float* q_a_ln  = (const float*)d_in[2];
    const float* q_b_w   = (const float*)d_in[3];
    const float* kv_a_w  = (const float*)d_in[4];
    const float* kv_a_ln = (const float*)d_in[5];
    const float* kv_b_w  = (const float*)d_in[6];
    const float* o_w     = (const float*)d_in[7];
    const float* cosb    = (const float*)d_in[8];
    const float* sinb    = (const float*)d_in[9];
    // d_in[10] = attention_mask (causal triu; semantics reproduced directly)
    const int*   pos     = (const int*)d_in[11];
    float* out = (float*)d_out;

    float* base;
    cudaGetSymbolAddress((void**)&base, g_scratch);
    float* qa    = base + OFF_QA;
    float* q     = base + OFF_Q;
    float* ckv   = base + OFF_CKV;
    float* ckvn  = base + OFF_CKVN;
    float* kpe   = base + OFF_KPE;
    float* kv    = base + OFF_KV;
    float* attn  = base + OFF_ATTN;
    float* hr    = base + OFF_HR;
    float* w_qa  = base + OFF_W_QA;
    float* w_kva = base + OFF_W_KVA;
    float* w_qb  = base + OFF_W_QB;
    float* w_kvb = base + OFF_W_KVB;
    float* w_o   = base + OFF_W_O;

    cudaFuncSetAttribute(attn_kernel, cudaFuncAttributeMaxDynamicSharedMemorySize,
                         ATT_SMEM_WORDS * 4);
    cudaFuncSetAttribute(gemm_tf32<true>, cudaFuncAttributeMaxDynamicSharedMemorySize,
                         GEMM_SMEM_BYTES);
    cudaFuncSetAttribute(gemm_tf32<false>, cudaFuncAttributeMaxDynamicSharedMemorySize,
                         GEMM_SMEM_BYTES);
    cudaFuncSetAttribute(gemm_a_fused, cudaFuncAttributeMaxDynamicSharedMemorySize,
                         GEMM_SMEM_BYTES);

    // 0) all 6 rounding passes in one launch
    round_all<<<(RB5 + 255) / 256, 256>>>(
        (const float4*)hidden, (const float4*)q_a_w, (const float4*)kv_a_w,
        (const float4*)q_b_w, (const float4*)kv_b_w, (const float4*)o_w,
        (float4*)hr, (float4*)w_qa, (float4*)w_kva,
        (float4*)w_qb, (float4*)w_kvb, (float4*)w_o);

    // 1+2) fused down-projection: qa[2048,1536] and ckv[2048,576] in one GEMM
    {
        dim3 grid(17, 16);
        gemm_a_fused<<<grid, 128, GEMM_SMEM_BYTES>>>(hr, w_qa, qa, ckv);
    }
    // 3) rmsnorm(q_a) in place
    rmsnorm_kernel<<<S_LEN, 256>>>(qa, QLR, q_a_ln, qa, QLR, QLR);
    // 4) rmsnorm(ckv[:, :512]) -> ckvn
    rmsnorm_kernel<<<S_LEN, 256>>>(ckv, 576, kv_a_ln, ckvn, KVLR, KVLR);
    // 5) rope(k_pe) -> kpe
    kpe_rope_kernel<<<(S_LEN * 32 + 255) / 256, 256>>>(ckv, pos, cosb, sinb, kpe);
    // 6) q = qa_n @ q_b_w^T               [2048,3072]
    launch_gemm<true>(qa, w_qb, q, S_LEN, QDIM, QLR);
    // 7) kv = ckvn @ kv_b_w^T             [2048,4096]
    launch_gemm<true>(ckvn, w_kvb, kv, S_LEN, KVDIM, KVLR);
    // 8) rope(q_pe) in place
    q_rope_kernel<<<(S_LEN * NH * 32 + 255) / 256, 256>>>(q, pos, cosb, sinb);
    // 9) attention -> attn                [2048,2048]
    attn_kernel<<<dim3(32, NH), 256, ATT_SMEM_WORDS * 4>>>(q, kv, kpe, attn);
    // 10) out = attn @ o_w^T              [2048,2048]
    launch_gemm<false>(attn, w_o, out, S_LEN, HID, AODIM);
}

// round 13
// speedup vs baseline: 1.5107x; 1.0037x over previous
#include <cuda_runtime.h>
#include <cuda_bf16.h>
#include <math.h>

// Problem constants
#define S_LEN 2048
#define HID   2048
#define NH    16
#define DN    128
#define DR    64
#define DV    128
#define DQ    192      // DN + DR
#define QLR   1536
#define KVLR  512
#define QDIM  (NH * DQ)        // 3072
#define KVDIM (NH * (DN + DV)) // 4096
#define AODIM (NH * DV)        // 2048
#define SCALE 0.07216878364870323f  // 192^-0.5
#define EPSV  1e-6f

// ---------------- scratch (allocation-free: __device__ global) ----------------
#define OFF_QA    0UL
#define OFF_Q     (OFF_QA   + (size_t)S_LEN * QLR)
#define OFF_CKV   (OFF_Q    + (size_t)S_LEN * QDIM)
#define OFF_CKVN  (OFF_CKV  + (size_t)S_LEN * 576)
#define OFF_KPE   (OFF_CKVN + (size_t)S_LEN * KVLR)
#define OFF_KV    (OFF_KPE  + (size_t)S_LEN * DR)
#define OFF_ATTN  (OFF_KV   + (size_t)S_LEN * KVDIM)
// rounded (tf32-in-fp32) copies. w_qa and w_kva MUST stay adjacent (fused GEMM).
#define OFF_HR    (OFF_ATTN + (size_t)S_LEN * AODIM)
#define OFF_W_QA  (OFF_HR   + (size_t)S_LEN * HID)
#define OFF_W_KVA (OFF_W_QA + (size_t)QLR * HID)          // padded to 640 rows
#define OFF_W_QB  (OFF_W_KVA + (size_t)640 * HID)
#define OFF_W_KVB (OFF_W_QB + (size_t)QDIM * QLR)
#define OFF_W_O   (OFF_W_KVB + (size_t)KVDIM * KVLR)
#define SCRATCH_TOTAL (OFF_W_O + (size_t)HID * AODIM)

__device__ float g_scratch[SCRATCH_TOTAL];

// ---------------- helpers ------------------------------------------------------
__device__ __forceinline__ unsigned f2tf(float x) {
    unsigned u;
    asm("cvt.rna.tf32.f32 %0, %1;" : "=r"(u) : "f"(x));
    return u;
}
__device__ __forceinline__ float rtf(float x) { return __uint_as_float(f2tf(x)); }

__device__ __forceinline__ void mma8(float* d, const unsigned* a, const unsigned* b) {
    asm volatile(
        "mma.sync.aligned.m16n8k8.row.col.f32.tf32.tf32.f32 "
        "{%0,%1,%2,%3},{%4,%5,%6,%7},{%8,%9},{%0,%1,%2,%3};\n"
        : "+f"(d[0]), "+f"(d[1]), "+f"(d[2]), "+f"(d[3])
        : "r"(a[0]), "r"(a[1]), "r"(a[2]), "r"(a[3]), "r"(b[0]), "r"(b[1]));
}

__device__ __forceinline__ void cpa16(unsigned saddr, const void* g) {
    asm volatile("cp.async.cg.shared.global [%0], [%1], 16;\n" :: "r"(saddr), "l"(g));
}
__device__ __forceinline__ void cp_commit() { asm volatile("cp.async.commit_group;\n"); }
template <int N> __device__ __forceinline__ void cp_wait() {
    asm volatile("cp.async.wait_group %0;\n" :: "n"(N));
}

// ---------------- fused rounding pass (all 6 tensors in one launch) -------------
#define RN_H    ((S_LEN * HID) / 4)
#define RN_QA   ((QLR * HID) / 4)
#define RN_KVAD ((640 * HID) / 4)
#define RN_KVAS ((576 * HID) / 4)
#define RN_QB   ((QDIM * QLR) / 4)
#define RN_KVB  ((KVDIM * KVLR) / 4)
#define RN_O    ((HID * AODIM) / 4)
#define RB0 RN_H
#define RB1 (RB0 + RN_QA)
#define RB2 (RB1 + RN_KVAD)
#define RB3 (RB2 + RN_QB)
#define RB4 (RB3 + RN_KVB)
#define RB5 (RB4 + RN_O)

__global__ __launch_bounds__(256) void round_all(
    const float4* __restrict__ h,    const float4* __restrict__ wqa,
    const float4* __restrict__ wkva, const float4* __restrict__ wqb,
    const float4* __restrict__ wkvb, const float4* __restrict__ wo,
    float4* __restrict__ dh,   float4* __restrict__ dqa,  float4* __restrict__ dkva,
    float4* __restrict__ dqb,  float4* __restrict__ dkvb, float4* __restrict__ dwo)
{
    int i = blockIdx.x * blockDim.x + threadIdx.x;
    if (i >= RB5) return;
    const float4* src; float4* dst; int loc; bool ok = true;
    if (i < RB0)      { src = h;    dst = dh;   loc = i; }
    else if (i < RB1) { src = wqa;  dst = dqa;  loc = i - RB0; }
    else if (i < RB2) { src = wkva; dst = dkva; loc = i - RB1; ok = (loc < RN_KVAS); }
    else if (i < RB3) { src = wqb;  dst = dqb;  loc = i - RB2; }
    else if (i < RB4) { src = wkvb; dst = dkvb; loc = i - RB3; }
    else              { src = wo;   dst = dwo;  loc = i - RB4; }
    float4 v = make_float4(0.f, 0.f, 0.f, 0.f);
    if (ok) v = src[loc];
    v.x = rtf(v.x); v.y = rtf(v.y); v.z = rtf(v.z); v.w = rtf(v.w);
    dst[loc] = v;
}

// ---------------- GEMM: C[M,N] = A[M,K] * W[N,K]^T, tf32, cp.async 3-stage -----
// BM=128, BN=128, BK=32, 128 threads (4 warps, 2x2), warp tile 64x64.
#define GS 36
#define STG_WORDS (2 * 128 * GS)          // A + B per stage (9216 words = 36 KB)
#define GEMM_STAGES 3
#define GEMM_SMEM_BYTES (GEMM_STAGES * STG_WORDS * 4)   // 110,592 B (2 CTAs fit)

__device__ __forceinline__ void gemm_issue(
    const float* __restrict__ A, const float* __restrict__ W, int K,
    int m0, int n0, int k0, unsigned sa, unsigned sb, int t)
{
#pragma unroll
    for (int i = 0; i < 8; i++) {
        int id = t + 128 * i;
        int r = id >> 3, c4 = (id & 7) << 2;
        cpa16(sa + (unsigned)(r * GS + c4) * 4u, A + (size_t)(m0 + r) * K + k0 + c4);
    }
#pragma unroll
    for (int i = 0; i < 8; i++) {
        int id = t + 128 * i;
        int r = id >> 3, c4 = (id & 7) << 2;
        cpa16(sb + (unsigned)(r * GS + c4) * 4u, W + (size_t)(n0 + r) * K + k0 + c4);
    }
    cp_commit();
}

__device__ __forceinline__ void gemm_mainloop(
    const float* __restrict__ A, const float* __restrict__ W, int K,
    int m0, int n0, unsigned* sm, float acc[4][8][4],
    int t, int warpM, int warpN, int ln4, int lnk)
{
    unsigned sbase = (unsigned)__cvta_generic_to_shared(sm);
    const int nIter = K >> 5;

    // prologue: stages 0 and 1 in flight
    gemm_issue(A, W, K, m0, n0, 0,
               sbase, sbase + 128 * GS * 4, t);
    if (nIter > 1)
        gemm_issue(A, W, K, m0, n0, 32,
                   sbase + (unsigned)STG_WORDS * 4u,
                   sbase + (unsigned)(STG_WORDS + 128 * GS) * 4u, t);

    int buf = 0;
    for (int it = 0; it < nIter; it++) {
        if (it + 2 < nIter) {
            int nb = buf + 2; if (nb >= GEMM_STAGES) nb -= GEMM_STAGES;
            gemm_issue(A, W, K, m0, n0, (it + 2) << 5,
                       sbase + (unsigned)(nb * STG_WORDS) * 4u,
                       sbase + (unsigned)(nb * STG_WORDS + 128 * GS) * 4u, t);
            cp_wait<2>();
        } else if (it + 1 < nIter) {
            cp_wait<1>();
        } else {
            cp_wait<0>();
        }
        __syncthreads();

        const unsigned* As = sm + buf * STG_WORDS;
        const unsigned* Bs = As + 128 * GS;
#pragma unroll
        for (int ks = 0; ks < 4; ks++) {
            const int kk = ks * 8;
            unsigned a[4][4];
#pragma unroll
            for (int mt = 0; mt < 4; mt++) {
                const unsigned* p = As + (warpM * 64 + mt * 16 + ln4) * GS + kk + lnk;
                a[mt][0] = p[0];
                a[mt][1] = p[8 * GS];
                a[mt][2] = p[4];
                a[mt][3] = p[8 * GS + 4];
            }
#pragma unroll
            for (int nt = 0; nt < 8; nt++) {
                const unsigned* p = Bs + (warpN * 64 + nt * 8 + ln4) * GS + kk + lnk;
                unsigned b[2] = { p[0], p[4] };
#pragma unroll
                for (int mt = 0; mt < 4; mt++) mma8(acc[mt][nt], a[mt], b);
            }
        }
        __syncthreads();
        if (++buf == GEMM_STAGES) buf = 0;
    }
}

template <bool RND>
__global__ __launch_bounds__(128, 2) void gemm_tf32(
    const float* __restrict__ A, const float* __restrict__ W,
    float* __restrict__ C, int M, int N, int K)
{
    extern __shared__ unsigned sm[];
    const int t = threadIdx.x;
    const int lane = t & 31, wid = t >> 5;
    const int ln4 = lane >> 2, lnk = lane & 3;
    const int warpM = wid & 1, warpN = wid >> 1;
    const int m0 = blockIdx.y * 128, n0 = blockIdx.x * 128;

    float acc[4][8][4];
#pragma unroll
    for (int mt = 0; mt < 4; mt++)
#pragma unroll
        for (int nt = 0; nt < 8; nt++)
#pragma unroll
            for (int j = 0; j < 4; j++) acc[mt][nt][j] = 0.f;

    gemm_mainloop(A, W, K, m0, n0, sm, acc, t, warpM, warpN, ln4, lnk);

#pragma unroll
    for (int mt = 0; mt < 4; mt++) {
        int r0 = m0 + warpM * 64 + mt * 16 + ln4;
#pragma unroll
        for (int nt = 0; nt < 8; nt++) {
            int c = n0 + warpN * 64 + nt * 8 + 2 * lnk;
            if (c < N) {
                float v0 = acc[mt][nt][0], v1 = acc[mt][nt][1];
                float v2 = acc[mt][nt][2], v3 = acc[mt][nt][3];
                if (RND) { v0 = rtf(v0); v1 = rtf(v1); v2 = rtf(v2); v3 = rtf(v3); }
                *(float2*)(C + (size_t)r0 * N + c)       = make_float2(v0, v1);
                *(float2*)(C + (size_t)(r0 + 8) * N + c) = make_float2(v2, v3);
            }
        }
    }
}

// Fused down-projection GEMM: A[2048,2048] x Wcat[2176,2048]^T.
__global__ __launch_bounds__(128, 2) void gemm_a_fused(
    const float* __restrict__ A, const float* __restrict__ W,
    float* __restrict__ qa, float* __restrict__ ckv)
{
    extern __shared__ unsigned sm[];
    const int t = threadIdx.x;
    const int lane = t & 31, wid = t >> 5;
    const int ln4 = lane >> 2, lnk = lane & 3;
    const int warpM = wid & 1, warpN = wid >> 1;
    const int m0 = blockIdx.y * 128, n0 = blockIdx.x * 128;

    float acc[4][8][4];
#pragma unroll
    for (int mt = 0; mt < 4; mt++)
#pragma unroll
        for (int nt = 0; nt < 8; nt++)
#pragma unroll
            for (int j = 0; j < 4; j++) acc[mt][nt][j] = 0.f;

    gemm_mainloop(A, W, HID, m0, n0, sm, acc, t, warpM, warpN, ln4, lnk);

#pragma unroll
    for (int mt = 0; mt < 4; mt++) {
        int r0 = m0 + warpM * 64 + mt * 16 + ln4;
#pragma unroll
        for (int nt = 0; nt < 8; nt++) {
            int c = n0 + warpN * 64 + nt * 8 + 2 * lnk;
            float v0 = rtf(acc[mt][nt][0]), v1 = rtf(acc[mt][nt][1]);
            float v2 = rtf(acc[mt][nt][2]), v3 = rtf(acc[mt][nt][3]);
            if (c < QLR) {
                *(float2*)(qa + (size_t)r0 * QLR + c)       = make_float2(v0, v1);
                *(float2*)(qa + (size_t)(r0 + 8) * QLR + c) = make_float2(v2, v3);
            } else {
                int cc = c - QLR;
                if (cc < 576) {
                    *(float2*)(ckv + (size_t)r0 * 576 + cc)       = make_float2(v0, v1);
                    *(float2*)(ckv + (size_t)(r0 + 8) * 576 + cc) = make_float2(v2, v3);
                }
            }
        }
    }
}

// ---------------- RMSNorm (writes tf32-rounded) ---------------------------------
__global__ __launch_bounds__(256) void rmsnorm_kernel(
    const float* __restrict__ X, int ldx, const float* __restrict__ w,
    float* __restrict__ Y, int ldy, int n)
{
    const int row = blockIdx.x;
    const float* x = X + (size_t)row * ldx;
    float* y = Y + (size_t)row * ldy;

    float s = 0.f;
    for (int i = threadIdx.x; i < n; i += blockDim.x) { float v = x[i]; s += v * v; }

    __shared__ float red[8];
    int lane = threadIdx.x & 31, wid = threadIdx.x >> 5;
#pragma unroll
    for (int o = 16; o; o >>= 1) s += __shfl_down_sync(0xFFFFFFFFu, s, o);
    if (!lane) red[wid] = s;
    __syncthreads();
    if (wid == 0) {
        s = (lane < 8) ? red[lane] : 0.f;
#pragma unroll
        for (int o = 4; o; o >>= 1) s += __shfl_down_sync(0xFFFFFFFFu, s, o);
        if (!lane) red[0] = s;
    }
    __syncthreads();
    const float inv = rsqrtf(red[0] / (float)n + EPSV);
    for (int i = threadIdx.x; i < n; i += blockDim.x) y[i] = rtf(x[i] * inv * w[i]);
}

// ---------------- k_pe RoPE (writes rounded) ------------------------------------
__global__ __launch_bounds__(256) void kpe_rope_kernel(
    const float* __restrict__ ckv, const int* __restrict__ pos,
    const float* __restrict__ cosb, const float* __restrict__ sinb,
    float* __restrict__ kpe)
{
    int warp = (blockIdx.x * blockDim.x + threadIdx.x) >> 5;
    int lane = threadIdx.x & 31;
    if (warp >= S_LEN) return;
    int s = warp;
    int p = pos[s];
    const float* x = ckv + (size_t)s * 576 + 512;
    float x0 = x[2 * lane], x1 = x[2 * lane + 1];
    float c0 = cosb[(size_t)p * DR + lane],      s0 = sinb[(size_t)p * DR + lane];
    float c1 = cosb[(size_t)p * DR + 32 + lane], s1 = sinb[(size_t)p * DR + 32 + lane];
    kpe[(size_t)s * DR + lane]      = rtf(x0 * c0 - x1 * s0);
    kpe[(size_t)s * DR + 32 + lane] = rtf(x1 * c1 + x0 * s1);
}

// ---------------- q_pe RoPE (in place, writes rounded) --------------------------
__global__ __launch_bounds__(256) void q_rope_kernel(
    float* __restrict__ Q, const int* __restrict__ pos,
    const float* __restrict__ cosb, const float* __restrict__ sinb)
{
    int warp = (blockIdx.x * blockDim.x + threadIdx.x) >> 5;
    int lane = threadIdx.x & 31;
    if (warp >= S_LEN * NH) return;
    int s = warp >> 4, h = warp & 15;
    int p = pos[s];
    float* x = Q + (size_t)s * QDIM + h * DQ + DN;
    float x0 = x[2 * lane], x1 = x[2 * lane + 1];
    float c0 = cosb[(size_t)p * DR + lane],      s0 = sinb[(size_t)p * DR + lane];
    float c1 = cosb[(size_t)p * DR + 32 + lane], s1 = sinb[(size_t)p * DR + 32 + lane];
    float o0 = rtf(x0 * c0 - x1 * s0);
    float o1 = rtf(x1 * c1 + x0 * s1);
    __syncwarp();
    x[lane]      = o0;
    x[32 + lane] = o1;
}

// ---------------- Flash attention (causal, tf32 mma.sync) -----------------------
// Q fragments in registers (FULL unroll -> no LMEM), K/V double-buffered cp.async.
#define QKS 196
#define VS_ 136
#define PS_ 68
#define ATT_SMEM_WORDS (2 * 64 * QKS + 2 * 64 * VS_ + 64 * PS_ + 3 * 64)

__global__ __launch_bounds__(256) void attn_kernel(
    const float* __restrict__ Q, const float* __restrict__ KV,
    const float* __restrict__ KPE, float* __restrict__ O)
{
    extern __shared__ unsigned smu[];
    unsigned* Ks0 = smu;                    // [2][64][QKS]
    unsigned* Vs0 = Ks0 + 2 * 64 * QKS;     // [2][64][VS_]
    unsigned* Ps  = Vs0 + 2 * 64 * VS_;     // [64][PS_]
    float* mrow = (float*)(Ps + 64 * PS_);
    float* lrow = mrow + 64;
    float* arow = lrow + 64;

    const unsigned sb = (unsigned)__cvta_generic_to_shared(smu);
    const unsigned ks_b = sb;
    const unsigned vs_b = sb + 2u * 64 * QKS * 4;

    const int h  = blockIdx.y;
    const int qb = 31 - blockIdx.x;
    const int q0 = qb * 64;
    const int t    = threadIdx.x;
    const int lane = t & 31;
    const int wid  = t >> 5;
    const int ln4  = lane >> 2;
    const int lnk  = lane & 3;
    const int warpM = wid & 3;
    const int warpN = wid >> 2;

    const float* KVh = KV + h * 256;

    // ---- stage Q tile [64 x 192] through K buffer 0, preload fragments ----
    for (int idx = t; idx < 64 * 48; idx += 256) {
        int r = idx / 48, c4 = (idx % 48) * 4;
        *(float4*)(Ks0 + r * QKS + c4) =
            *(const float4*)(Q + (size_t)(q0 + r) * QDIM + h * DQ + c4);
    }
    if (t < 64) { mrow[t] = -1e30f; lrow[t] = 0.f; }
    __syncthreads();

    unsigned qf[96];
    {
        const unsigned* qbase = Ks0 + (warpM * 16 + ln4) * QKS + lnk;
#pragma unroll
        for (int ks = 0; ks < 24; ks++) {
            const int kk = ks * 8;
            qf[ks * 4 + 0] = qbase[kk];
            qf[ks * 4 + 1] = qbase[8 * QKS + kk];
            qf[ks * 4 + 2] = qbase[kk + 4];
            qf[ks * 4 + 3] = qbase[8 * QKS + kk + 4];
        }
    }

    float o[8][4];
#pragma unroll
    for (int nt = 0; nt < 8; nt++)
#pragma unroll
        for (int j = 0; j < 4; j++) o[nt][j] = 0.f;
    __syncthreads();   // all warps done reading Q from Ks0[0]

    // ---- cp.async issue of one K/V tile into buffer `bf` ----
    auto issue_kv = [&](int kt, int bf) {
        const unsigned ksb = ks_b + (unsigned)bf * 64 * QKS * 4;
        const unsigned vsb = vs_b + (unsigned)bf * 64 * VS_ * 4;
        const float* rowbase = KVh + (size_t)(kt * 64) * KVDIM;
#pragma unroll
        for (int i = 0; i < 16; i++) {
            int idx = t + 256 * i;             // 0..4095
            int r = idx >> 6, c4 = (idx & 63) << 2;
            const float* src = rowbase + (size_t)r * KVDIM + c4;
            if (c4 < 128) cpa16(ksb + (unsigned)(r * QKS + c4) * 4u, src);
            else          cpa16(vsb + (unsigned)(r * VS_ + c4 - 128) * 4u, src);
        }
#pragma unroll
        for (int i = 0; i < 4; i++) {
            int idx = t + 256 * i;             // 0..1023
            int r = idx >> 4, c4 = (idx & 15) << 2;
            cpa16(ksb + (unsigned)(r * QKS + 128 + c4) * 4u,
                  KPE + (size_t)(kt * 64 + r) * DR + c4);
        }
        cp_commit();
    };

    issue_kv(0, 0);   // prologue

    for (int kt = 0; kt <= qb; kt++) {
        const int buf = kt & 1;
        if (kt < qb) { issue_kv(kt + 1, buf ^ 1); cp_wait<1>(); }
        else         { cp_wait<0>(); }
        __syncthreads();

        const unsigned* Ks = Ks0 + buf * 64 * QKS;
        const unsigned* Vs = Vs0 + buf * 64 * VS_;

        // ---- S = Q K^T (FULL unroll: qf indices compile-time constant) ----
        float sacc[4][4];
#pragma unroll
        for (int nt = 0; nt < 4; nt++)
#pragma unroll
            for (int j = 0; j < 4; j++) sacc[nt][j] = 0.f;

#pragma unroll
        for (int ks = 0; ks < 24; ks++) {
            const int kk = ks * 8;
#pragma unroll
            for (int nt = 0; nt < 4; nt++) {
                const unsigned* p = Ks + (warpN * 32 + nt * 8 + ln4) * QKS + kk + lnk;
                unsigned b[2] = { p[0], p[4] };
                mma8(sacc[nt], &qf[ks * 4], b);
            }
        }

        const bool diag = (kt == qb);
        const int rl0 = warpM * 16 + ln4;
#pragma unroll
        for (int nt = 0; nt < 4; nt++) {
            int cl = warpN * 32 + nt * 8 + 2 * lnk;
            float v0 = sacc[nt][0] * SCALE;
            float v1 = sacc[nt][1] * SCALE;
            float v2 = sacc[nt][2] * SCALE;
            float v3 = sacc[nt][3] * SCALE;
            if (diag) {
                if (cl     > rl0)     v0 = -1e30f;
                if (cl + 1 > rl0)     v1 = -1e30f;
                if (cl     > rl0 + 8) v2 = -1e30f;
                if (cl + 1 > rl0 + 8) v3 = -1e30f;
            }
            Ps[rl0 * PS_ + cl]           = __float_as_uint(v0);
            Ps[rl0 * PS_ + cl + 1]       = __float_as_uint(v1);
            Ps[(rl0 + 8) * PS_ + cl]     = __float_as_uint(v2);
            Ps[(rl0 + 8) * PS_ + cl + 1] = __float_as_uint(v3);
        }
        __syncthreads();

        // ---- online softmax: 4 threads per row ----
        {
            const int r = t >> 2, seg = t & 3;
            const float* pf = (const float*)Ps + r * PS_ + seg * 16;
            unsigned* pu = Ps + r * PS_ + seg * 16;
            float mprev = mrow[r];
            float mx = mprev;
#pragma unroll
            for (int j = 0; j < 16; j++) mx = fmaxf(mx, pf[j]);
            mx = fmaxf(mx, __shfl_xor_sync(0xFFFFFFFFu, mx, 1));
            mx = fmaxf(mx, __shfl_xor_sync(0xFFFFFFFFu, mx, 2));
            float alpha = __expf(mprev - mx);
            float s = 0.f;
#pragma unroll
            for (int j = 0; j < 16; j++) {
                float e = __expf(pf[j] - mx);
                s += e;
                pu[j] = f2tf(e);
            }
            s += __shfl_xor_sync(0xFFFFFFFFu, s, 1);
            s += __shfl_xor_sync(0xFFFFFFFFu, s, 2);
            if (seg == 0) {
                mrow[r] = mx;
                lrow[r] = lrow[r] * alpha + s;
                arow[r] = alpha;
            }
        }
        __syncthreads();

        // ---- O = O*alpha + P @ V ----
        {
            float ar0 = arow[warpM * 16 + ln4];
            float ar1 = arow[warpM * 16 + ln4 + 8];
#pragma unroll
            for (int nt = 0; nt < 8; nt++) {
                o[nt][0] *= ar0; o[nt][1] *= ar0;
                o[nt][2] *= ar1; o[nt][3] *= ar1;
            }
            const unsigned* pbase = Ps + (warpM * 16 + ln4) * PS_ + lnk;
#pragma unroll
            for (int ks = 0; ks < 8; ks++) {
                const int kk = ks * 8;
                unsigned a[4];
                a[0] = pbase[kk];
                a[1] = pbase[8 * PS_ + kk];
                a[2] = pbase[kk + 4];
                a[3] = pbase[8 * PS_ + kk + 4];
#pragma unroll
                for (int nt = 0; nt < 8; nt++) {
                    const unsigned* p = Vs + (kk + lnk) * VS_ + warpN * 64 + nt * 8 + ln4;
                    unsigned b[2] = { p[0], p[4 * VS_] };
                    mma8(o[nt], a, b);
                }
            }
        }
        __syncthreads();
    }

    {
        float inv0 = 1.f / lrow[warpM * 16 + ln4];
        float inv1 = 1.f / lrow[warpM * 16 + ln4 + 8];
        int r0 = q0 + warpM * 16 + ln4;
#pragma unroll
        for (int nt = 0; nt < 8; nt++) {
            int c = warpN * 64 + nt * 8 + 2 * lnk;
            float* dst0 = O + (size_t)r0 * AODIM + h * DV + c;
            float* dst1 = O + (size_t)(r0 + 8) * AODIM + h * DV + c;
            *(float2*)dst0 = make_float2(rtf(o[nt][0] * inv0), rtf(o[nt][1] * inv0));
            *(float2*)dst1 = make_float2(rtf(o[nt][2] * inv1), rtf(o[nt][3] * inv1));
        }
    }
}

// ---------------- host launcher ---------------------------------------------------
template <bool RND>
static inline void launch_gemm(const float* A, const float* W, float* C,
                               int M, int N, int K) {
    dim3 grid((N + 127) / 128, M / 128);
    gemm_tf32<RND><<<grid, 128, GEMM_SMEM_BYTES>>>(A, W, C, M, N, K);
}

extern "C" void kernel_launch(void* const* d_in, const int* in_sizes, int n_in,
                              void* d_out, int out_size)
{
    const float* hidden  = (const float*)d_in[0];
    const float* q_a_w   = (const float*)d_in[1];
    const float* q_a_ln  = (const float*)d_in[2];
    const float* q_b_w   = (const float*)d_in[3];
    const float* kv_a_w  = (const float*)d_in[4];
    const float* kv_a_ln = (const float*)d_in[5];
    const float* kv_b_w  = (const float*)d_in[6];
    const float* o_w     = (const float*)d_in[7];
    const float* cosb    = (const float*)d_in[8];
    const float* sinb    = (const float*)d_in[9];
    // d_in[10] = attention_mask (causal triu; semantics reproduced directly)
    const int*   pos     = (const int*)d_in[11];
    float* out = (float*)d_out;

    float* base;
    cudaGetSymbolAddress((void**)&base, g_scratch);
    float* qa    = base + OFF_QA;
    float* q     = base + OFF_Q;
    float* ckv   = base + OFF_CKV;
    float* ckvn  = base + OFF_CKVN;
    float* kpe   = base + OFF_KPE;
    float* kv    = base + OFF_KV;
    float* attn  = base + OFF_ATTN;
    float* hr    = base + OFF_HR;
    float* w_qa  = base + OFF_W_QA;
    float* w_kva = base + OFF_W_KVA;
    float* w_qb  = base + OFF_W_QB;
    float* w_kvb = base + OFF_W_KVB;
    float* w_o   = base + OFF_W_O;

    cudaFuncSetAttribute(attn_kernel, cudaFuncAttributeMaxDynamicSharedMemorySize,
                         ATT_SMEM_WORDS * 4);
    cudaFuncSetAttribute(gemm_tf32<true>, cudaFuncAttributeMaxDynamicSharedMemorySize,
                         GEMM_SMEM_BYTES);
    cudaFuncSetAttribute(gemm_tf32<false>, cudaFuncAttributeMaxDynamicSharedMemorySize,
                         GEMM_SMEM_BYTES);
    cudaFuncSetAttribute(gemm_a_fused, cudaFuncAttributeMaxDynamicSharedMemorySize,
                         GEMM_SMEM_BYTES);

    // 0) all 6 rounding passes in one launch
    round_all<<<(RB5 + 255) / 256, 256>>>(
        (const float4*)hidden, (const float4*)q_a_w, (const float4*)kv_a_w,
        (const float4*)q_b_w, (const float4*)kv_b_w, (const float4*)o_w,
        (float4*)hr, (float4*)w_qa, (float4*)w_kva,
        (float4*)w_qb, (float4*)w_kvb, (float4*)w_o);

    // 1+2) fused down-projection: qa[2048,1536] and ckv[2048,576] in one GEMM
    {
        dim3 grid(17, 16);
        gemm_a_fused<<<grid, 128, GEMM_SMEM_BYTES>>>(hr, w_qa, qa, ckv);
    }
    // 3) rmsnorm(q_a) in place
    rmsnorm_kernel<<<S_LEN, 256>>>(qa, QLR, q_a_ln, qa, QLR, QLR);
    // 4) rmsnorm(ckv[:, :512]) -> ckvn
    rmsnorm_kernel<<<S_LEN, 256>>>(ckv, 576, kv_a_ln, ckvn, KVLR, KVLR);
    // 5) rope(k_pe) -> kpe
    kpe_rope_kernel<<<(S_LEN * 32 + 255) / 256, 256>>>(ckv, pos, cosb, sinb, kpe);
    // 6) q = qa_n @ q_b_w^T               [2048,3072]
    launch_gemm<true>(qa, w_qb, q, S_LEN, QDIM, QLR);
    // 7) kv = ckvn @ kv_b_w^T             [2048,4096]
    launch_gemm<true>(ckvn, w_kvb, kv, S_LEN, KVDIM, KVLR);
    // 8) rope(q_pe) in place
    q_rope_kernel<<<(S_LEN * NH * 32 + 255) / 256, 256>>>(q, pos, cosb, sinb);
    // 9) attention -> attn                [2048,2048]
    attn_kernel<<<dim3(32, NH), 256, ATT_SMEM_WORDS * 4>>>(q, kv, kpe, attn);
    // 10) out = attn @ o_w^T              [2048,2048]
    launch_gemm<false>(attn, w_o, out, S_LEN, HID, AODIM);
}

// round 14
// speedup vs baseline: 2.5450x; 1.6847x over previous
#include <cuda_runtime.h>
#include <cuda_fp16.h>
#include <math.h>

// Problem constants
#define S_LEN 2048
#define HID   2048
#define NH    16
#define DN    128
#define DR    64
#define DV    128
#define DQ    192
#define QLR   1536
#define KVLR  512
#define QDIM  (NH * DQ)        // 3072
#define AODIM (NH * DV)        // 2048
#define SCALE 0.07216878364870323f
#define EPSV  1e-6f

// ---------------- scratch (half elements) ---------------------------------------
#define OFF_QA    0UL
#define OFF_Q     (OFF_QA    + (size_t)S_LEN * QLR)
#define OFF_CKV   (OFF_Q     + (size_t)S_LEN * QDIM)
#define OFF_CKVN  (OFF_CKV   + (size_t)S_LEN * 576)
#define OFF_KPE   (OFF_CKVN  + (size_t)S_LEN * KVLR)
#define OFF_KNOPE (OFF_KPE   + (size_t)S_LEN * DR)
#define OFF_VT    (OFF_KNOPE + (size_t)S_LEN * 2048)        // [16][128][2048]
#define OFF_ATTN  (OFF_VT    + (size_t)NH * DV * S_LEN)
#define OFF_HR    (OFF_ATTN  + (size_t)S_LEN * AODIM)
#define OFF_W_QA  (OFF_HR    + (size_t)S_LEN * HID)
#define OFF_W_KVA (OFF_W_QA  + (size_t)QLR * HID)           // padded to 640 rows
#define OFF_W_QB  (OFF_W_KVA + (size_t)640 * HID)
#define OFF_W_KVB (OFF_W_QB  + (size_t)QDIM * QLR)
#define OFF_W_O   (OFF_W_KVB + (size_t)4096 * KVLR)
#define SCRATCH_TOTAL (OFF_W_O + (size_t)HID * AODIM)

__device__ __half g_scratch[SCRATCH_TOTAL];

// ---------------- helpers --------------------------------------------------------
__device__ __forceinline__ void mma16(float* d, const unsigned* a, const unsigned* b) {
    asm volatile(
        "mma.sync.aligned.m16n8k16.row.col.f32.f16.f16.f32 "
        "{%0,%1,%2,%3},{%4,%5,%6,%7},{%8,%9},{%0,%1,%2,%3};\n"
        : "+f"(d[0]), "+f"(d[1]), "+f"(d[2]), "+f"(d[3])
        : "r"(a[0]), "r"(a[1]), "r"(a[2]), "r"(a[3]), "r"(b[0]), "r"(b[1]));
}
__device__ __forceinline__ void cpa16(unsigned saddr, const void* g) {
    asm volatile("cp.async.cg.shared.global [%0], [%1], 16;\n" :: "r"(saddr), "l"(g));
}
__device__ __forceinline__ void cp_commit() { asm volatile("cp.async.commit_group;\n"); }
template <int N> __device__ __forceinline__ void cp_wait() {
    asm volatile("cp.async.wait_group %0;\n" :: "n"(N));
}
__device__ __forceinline__ unsigned pack_h2(float lo, float hi) {
    __half2 h = __floats2half2_rn(lo, hi);
    return *(unsigned*)&h;
}

// ---------------- fused rounding: fp32 -> fp16 (all 6 tensors, one launch) -------
#define RN_H    ((S_LEN * HID) / 4)
#define RN_QA   ((QLR * HID) / 4)
#define RN_KVAD ((640 * HID) / 4)
#define RN_KVAS ((576 * HID) / 4)
#define RN_QB   ((QDIM * QLR) / 4)
#define RN_KVB  ((4096 * KVLR) / 4)
#define RN_O    ((HID * AODIM) / 4)
#define RB0 RN_H
#define RB1 (RB0 + RN_QA)
#define RB2 (RB1 + RN_KVAD)
#define RB3 (RB2 + RN_QB)
#define RB4 (RB3 + RN_KVB)
#define RB5 (RB4 + RN_O)

__global__ __launch_bounds__(256) void round_all(
    const float4* __restrict__ h,    const float4* __restrict__ wqa,
    const float4* __restrict__ wkva, const float4* __restrict__ wqb,
    const float4* __restrict__ wkvb, const float4* __restrict__ wo,
    __half* __restrict__ dh,   __half* __restrict__ dqa,  __half* __restrict__ dkva,
    __half* __restrict__ dqb,  __half* __restrict__ dkvb, __half* __restrict__ dwo)
{
    int i = blockIdx.x * blockDim.x + threadIdx.x;
    if (i >= RB5) return;
    const float4* src; __half* dst; int loc; bool ok = true;
    if (i < RB0)      { src = h;    dst = dh;   loc = i; }
    else if (i < RB1) { src = wqa;  dst = dqa;  loc = i - RB0; }
    else if (i < RB2) { src = wkva; dst = dkva; loc = i - RB1; ok = (loc < RN_KVAS); }
    else if (i < RB3) { src = wqb;  dst = dqb;  loc = i - RB2; }
    else if (i < RB4) { src = wkvb; dst = dkvb; loc = i - RB3; }
    else              { src = wo;   dst = dwo;  loc = i - RB4; }
    float4 v = make_float4(0.f, 0.f, 0.f, 0.f);
    if (ok) v = src[loc];
    uint2 out;
    out.x = pack_h2(v.x, v.y);
    out.y = pack_h2(v.z, v.w);
    *(uint2*)(dst + (size_t)loc * 4) = out;
}

// ---------------- fp16 GEMM: C[M,N] = A[M,K] * W[N,K]^T --------------------------
// BM=128, BN=128, BK=64 halves, 128 threads (4 warps 2x2), warp tile 64x64.
// smem row = 32 data words (+4 pad) -> SW=36; word = half2 (2 k-elems).
#define GS 36
#define STG_WORDS (2 * 128 * GS)
#define GEMM_STAGES 3
#define GEMM_SMEM_BYTES (GEMM_STAGES * STG_WORDS * 4)

__device__ __forceinline__ void gemm_issue(
    const __half* __restrict__ A, const __half* __restrict__ W, int K,
    int m0, int n0, int k0, unsigned sa, unsigned sb, int t)
{
#pragma unroll
    for (int i = 0; i < 8; i++) {
        int id = t + 128 * i;
        int r = id >> 3, cc = id & 7;
        cpa16(sa + (unsigned)(r * GS + cc * 4) * 4u, A + (size_t)(m0 + r) * K + k0 + cc * 8);
    }
#pragma unroll
    for (int i = 0; i < 8; i++) {
        int id = t + 128 * i;
        int r = id >> 3, cc = id & 7;
        cpa16(sb + (unsigned)(r * GS + cc * 4) * 4u, W + (size_t)(n0 + r) * K + k0 + cc * 8);
    }
    cp_commit();
}

__device__ __forceinline__ void gemm_mainloop(
    const __half* __restrict__ A, const __half* __restrict__ W, int K,
    int m0, int n0, unsigned* sm, float acc[4][8][4],
    int t, int warpM, int warpN, int ln4, int lnk)
{
    unsigned sbase = (unsigned)__cvta_generic_to_shared(sm);
    const int nIter = K >> 6;   // BK = 64 halves

    gemm_issue(A, W, K, m0, n0, 0, sbase, sbase + 128 * GS * 4, t);
    if (nIter > 1)
        gemm_issue(A, W, K, m0, n0, 64,
                   sbase + (unsigned)STG_WORDS * 4u,
                   sbase + (unsigned)(STG_WORDS + 128 * GS) * 4u, t);

    int buf = 0;
    for (int it = 0; it < nIter; it++) {
        if (it + 2 < nIter) {
            int nb = buf + 2; if (nb >= GEMM_STAGES) nb -= GEMM_STAGES;
            gemm_issue(A, W, K, m0, n0, (it + 2) << 6,
                       sbase + (unsigned)(nb * STG_WORDS) * 4u,
                       sbase + (unsigned)(nb * STG_WORDS + 128 * GS) * 4u, t);
            cp_wait<2>();
        } else if (it + 1 < nIter) {
            cp_wait<1>();
        } else {
            cp_wait<0>();
        }
        __syncthreads();

        const unsigned* As = sm + buf * STG_WORDS;
        const unsigned* Bs = As + 128 * GS;
#pragma unroll
        for (int ks = 0; ks < 4; ks++) {           // 4 x k16
            const int kk = ks * 8;
            unsigned a[4][4];
#pragma unroll
            for (int mt = 0; mt < 4; mt++) {
                const unsigned* p = As + (warpM * 64 + mt * 16 + ln4) * GS + kk + lnk;
                a[mt][0] = p[0];
                a[mt][1] = p[8 * GS];
                a[mt][2] = p[4];
                a[mt][3] = p[8 * GS + 4];
            }
#pragma unroll
            for (int nt = 0; nt < 8; nt++) {
                const unsigned* p = Bs + (warpN * 64 + nt * 8 + ln4) * GS + kk + lnk;
                unsigned b[2] = { p[0], p[4] };
#pragma unroll
                for (int mt = 0; mt < 4; mt++) mma16(acc[mt][nt], a[mt], b);
            }
        }
        __syncthreads();
        if (++buf == GEMM_STAGES) buf = 0;
    }
}

// HOUT: 1 = write __half C, 0 = write float C
template <int HOUT>
__global__ __launch_bounds__(128, 2) void gemm_f16(
    const __half* __restrict__ A, const __half* __restrict__ W,
    void* __restrict__ Cv, int M, int N, int K)
{
    extern __shared__ unsigned sm[];
    const int t = threadIdx.x;
    const int lane = t & 31, wid = t >> 5;
    const int ln4 = lane >> 2, lnk = lane & 3;
    const int warpM = wid & 1, warpN = wid >> 1;
    const int m0 = blockIdx.y * 128, n0 = blockIdx.x * 128;

    float acc[4][8][4];
#pragma unroll
    for (int mt = 0; mt < 4; mt++)
#pragma unroll
        for (int nt = 0; nt < 8; nt++)
#pragma unroll
            for (int j = 0; j < 4; j++) acc[mt][nt][j] = 0.f;

    gemm_mainloop(A, W, K, m0, n0, sm, acc, t, warpM, warpN, ln4, lnk);

#pragma unroll
    for (int mt = 0; mt < 4; mt++) {
        int r0 = m0 + warpM * 64 + mt * 16 + ln4;
#pragma unroll
        for (int nt = 0; nt < 8; nt++) {
            int c = n0 + warpN * 64 + nt * 8 + 2 * lnk;
            if (c < N) {
                if (HOUT) {
                    __half* C = (__half*)Cv;
                    *(unsigned*)(C + (size_t)r0 * N + c)       = pack_h2(acc[mt][nt][0], acc[mt][nt][1]);
                    *(unsigned*)(C + (size_t)(r0 + 8) * N + c) = pack_h2(acc[mt][nt][2], acc[mt][nt][3]);
                } else {
                    float* C = (float*)Cv;
                    *(float2*)(C + (size_t)r0 * N + c)       = make_float2(acc[mt][nt][0], acc[mt][nt][1]);
                    *(float2*)(C + (size_t)(r0 + 8) * N + c) = make_float2(acc[mt][nt][2], acc[mt][nt][3]);
                }
            }
        }
    }
}

// Fused down-proj: Wcat[2176,2048] -> qa[2048,1536] + ckv[2048,576]
__global__ __launch_bounds__(128, 2) void gemm_a_fused(
    const __half* __restrict__ A, const __half* __restrict__ W,
    __half* __restrict__ qa, __half* __restrict__ ckv)
{
    extern __shared__ unsigned sm[];
    const int t = threadIdx.x;
    const int lane = t & 31, wid = t >> 5;
    const int ln4 = lane >> 2, lnk = lane & 3;
    const int warpM = wid & 1, warpN = wid >> 1;
    const int m0 = blockIdx.y * 128, n0 = blockIdx.x * 128;

    float acc[4][8][4];
#pragma unroll
    for (int mt = 0; mt < 4; mt++)
#pragma unroll
        for (int nt = 0; nt < 8; nt++)
#pragma unroll
            for (int j = 0; j < 4; j++) acc[mt][nt][j] = 0.f;

    gemm_mainloop(A, W, HID, m0, n0, sm, acc, t, warpM, warpN, ln4, lnk);

#pragma unroll
    for (int mt = 0; mt < 4; mt++) {
        int r0 = m0 + warpM * 64 + mt * 16 + ln4;
#pragma unroll
        for (int nt = 0; nt < 8; nt++) {
            int c = n0 + warpN * 64 + nt * 8 + 2 * lnk;
            unsigned u0 = pack_h2(acc[mt][nt][0], acc[mt][nt][1]);
            unsigned u1 = pack_h2(acc[mt][nt][2], acc[mt][nt][3]);
            if (c < QLR) {
                *(unsigned*)(qa + (size_t)r0 * QLR + c)       = u0;
                *(unsigned*)(qa + (size_t)(r0 + 8) * QLR + c) = u1;
            } else {
                int cc = c - QLR;
                if (cc < 576) {
                    *(unsigned*)(ckv + (size_t)r0 * 576 + cc)       = u0;
                    *(unsigned*)(ckv + (size_t)(r0 + 8) * 576 + cc) = u1;
                }
            }
        }
    }
}

// kv up-proj: ckvn[2048,512] x w_kvb[4096,512]^T -> knope[s][h*128+j] and
// vt[(h*128+dv)][s] (V transposed per head).
__global__ __launch_bounds__(128, 2) void gemm_kv(
    const __half* __restrict__ A, const __half* __restrict__ W,
    __half* __restrict__ knope, __half* __restrict__ vt)
{
    extern __shared__ unsigned sm[];
    const int t = threadIdx.x;
    const int lane = t & 31, wid = t >> 5;
    const int ln4 = lane >> 2, lnk = lane & 3;
    const int warpM = wid & 1, warpN = wid >> 1;
    const int m0 = blockIdx.y * 128, n0 = blockIdx.x * 128;

    float acc[4][8][4];
#pragma unroll
    for (int mt = 0; mt < 4; mt++)
#pragma unroll
        for (int nt = 0; nt < 8; nt++)
#pragma unroll
            for (int j = 0; j < 4; j++) acc[mt][nt][j] = 0.f;

    gemm_mainloop(A, W, KVLR, m0, n0, sm, acc, t, warpM, warpN, ln4, lnk);

#pragma unroll
    for (int mt = 0; mt < 4; mt++) {
        int r0 = m0 + warpM * 64 + mt * 16 + ln4;
#pragma unroll
        for (int nt = 0; nt < 8; nt++) {
            int c = n0 + warpN * 64 + nt * 8 + 2 * lnk;
            int h = c >> 8, j = c & 255;
            if (j < 128) {
                *(unsigned*)(knope + (size_t)r0 * 2048 + h * 128 + j) =
                    pack_h2(acc[mt][nt][0], acc[mt][nt][1]);
                *(unsigned*)(knope + (size_t)(r0 + 8) * 2048 + h * 128 + j) =
                    pack_h2(acc[mt][nt][2], acc[mt][nt][3]);
            } else {
                int jd = j - 128;
                __half* v0 = vt + ((size_t)h * 128 + jd) * S_LEN;
                __half* v1 = vt + ((size_t)h * 128 + jd + 1) * S_LEN;
                v0[r0]     = __float2half_rn(acc[mt][nt][0]);
                v1[r0]     = __float2half_rn(acc[mt][nt][1]);
                v0[r0 + 8] = __float2half_rn(acc[mt][nt][2]);
                v1[r0 + 8] = __float2half_rn(acc[mt][nt][3]);
            }
        }
    }
}

// ---------------- RMSNorm (half in/out, fp32 math) -------------------------------
__global__ __launch_bounds__(256) void rmsnorm_kernel(
    const __half* __restrict__ X, int ldx, const float* __restrict__ w,
    __half* __restrict__ Y, int ldy, int n)
{
    const int row = blockIdx.x;
    const __half* x = X + (size_t)row * ldx;
    __half* y = Y + (size_t)row * ldy;

    float s = 0.f;
    for (int i = threadIdx.x; i < n; i += blockDim.x) {
        float v = __half2float(x[i]); s += v * v;
    }
    __shared__ float red[8];
    int lane = threadIdx.x & 31, wid = threadIdx.x >> 5;
#pragma unroll
    for (int o = 16; o; o >>= 1) s += __shfl_down_sync(0xFFFFFFFFu, s, o);
    if (!lane) red[wid] = s;
    __syncthreads();
    if (wid == 0) {
        s = (lane < 8) ? red[lane] : 0.f;
#pragma unroll
        for (int o = 4; o; o >>= 1) s += __shfl_down_sync(0xFFFFFFFFu, s, o);
        if (!lane) red[0] = s;
    }
    __syncthreads();
    const float inv = rsqrtf(red[0] / (float)n + EPSV);
    for (int i = threadIdx.x; i < n; i += blockDim.x)
        y[i] = __float2half_rn(__half2float(x[i]) * inv * w[i]);
}

// ---------------- k_pe RoPE --------------------------------------------------------
__global__ __launch_bounds__(256) void kpe_rope_kernel(
    const __half* __restrict__ ckv, const int* __restrict__ pos,
    const float* __restrict__ cosb, const float* __restrict__ sinb,
    __half* __restrict__ kpe)
{
    int warp = (blockIdx.x * blockDim.x + threadIdx.x) >> 5;
    int lane = threadIdx.x & 31;
    if (warp >= S_LEN) return;
    int s = warp;
    int p = pos[s];
    const __half* x = ckv + (size_t)s * 576 + 512;
    float x0 = __half2float(x[2 * lane]), x1 = __half2float(x[2 * lane + 1]);
    float c0 = cosb[(size_t)p * DR + lane],      s0 = sinb[(size_t)p * DR + lane];
    float c1 = cosb[(size_t)p * DR + 32 + lane], s1 = sinb[(size_t)p * DR + 32 + lane];
    kpe[(size_t)s * DR + lane]      = __float2half_rn(x0 * c0 - x1 * s0);
    kpe[(size_t)s * DR + 32 + lane] = __float2half_rn(x1 * c1 + x0 * s1);
}

// ---------------- q_pe RoPE (in place) ---------------------------------------------
__global__ __launch_bounds__(256) void q_rope_kernel(
    __half* __restrict__ Q, const int* __restrict__ pos,
    const float* __restrict__ cosb, const float* __restrict__ sinb)
{
    int warp = (blockIdx.x * blockDim.x + threadIdx.x) >> 5;
    int lane = threadIdx.x & 31;
    if (warp >= S_LEN * NH) return;
    int s = warp >> 4, h = warp & 15;
    int p = pos[s];
    __half* x = Q + (size_t)s * QDIM + h * DQ + DN;
    float x0 = __half2float(x[2 * lane]), x1 = __half2float(x[2 * lane + 1]);
    float c0 = cosb[(size_t)p * DR + lane],      s0 = sinb[(size_t)p * DR + lane];
    float c1 = cosb[(size_t)p * DR + 32 + lane], s1 = sinb[(size_t)p * DR + 32 + lane];
    __half o0 = __float2half_rn(x0 * c0 - x1 * s0);
    __half o1 = __float2half_rn(x1 * c1 + x0 * s1);
    __syncwarp();
    x[lane]      = o0;
    x[32 + lane] = o1;
}

// ---------------- Flash attention (causal, fp16 mma) -------------------------------
// K tile rows = 192 halves (96 words) -> KS_W=100; Vt tile 128 rows x 64 halves
// (32 words) -> VT_W=36; Ps f32 (PSF=68); Ph fp16 (PH_W=36).
#define KS_W 100
#define VT_W 36
#define PSF  68
#define PH_W 36
#define ATT_SMEM_WORDS (2 * 64 * KS_W + 2 * 128 * VT_W + 64 * PSF + 64 * PH_W + 3 * 64)

__global__ __launch_bounds__(256) void attn_kernel(
    const __half* __restrict__ Q, const __half* __restrict__ KNOPE,
    const __half* __restrict__ KPE, const __half* __restrict__ VT,
    __half* __restrict__ O)
{
    extern __shared__ unsigned smu[];
    unsigned* Ks0 = smu;                        // [2][64][KS_W]
    unsigned* Vt0 = Ks0 + 2 * 64 * KS_W;        // [2][128][VT_W]
    unsigned* Ps  = Vt0 + 2 * 128 * VT_W;       // [64][PSF] f32
    unsigned* Ph  = Ps + 64 * PSF;              // [64][PH_W] fp16
    float* mrow = (float*)(Ph + 64 * PH_W);
    float* lrow = mrow + 64;
    float* arow = lrow + 64;

    const unsigned sb = (unsigned)__cvta_generic_to_shared(smu);
    const unsigned ks_b = sb;
    const unsigned vt_b = sb + 2u * 64 * KS_W * 4;

    const int h  = blockIdx.y;
    const int qb = 31 - blockIdx.x;
    const int q0 = qb * 64;
    const int t    = threadIdx.x;
    const int lane = t & 31;
    const int wid  = t >> 5;
    const int ln4  = lane >> 2;
    const int lnk  = lane & 3;
    const int warpM = wid & 3;
    const int warpN = wid >> 2;

    // ---- stage Q tile [64 x 192 halves] via K buffer 0, preload fragments ----
    for (int idx = t; idx < 64 * 24; idx += 256) {
        int r = idx / 24, cc = idx % 24;
        *(uint4*)(Ks0 + r * KS_W + cc * 4) =
            *(const uint4*)(Q + (size_t)(q0 + r) * QDIM + h * DQ + cc * 8);
    }
    if (t < 64) { mrow[t] = -1e30f; lrow[t] = 0.f; }
    __syncthreads();

    unsigned qf[48];
    {
        const unsigned* qbase = Ks0 + (warpM * 16 + ln4) * KS_W + lnk;
#pragma unroll
        for (int ks = 0; ks < 12; ks++) {
            const int kk = ks * 8;
            qf[ks * 4 + 0] = qbase[kk];
            qf[ks * 4 + 1] = qbase[8 * KS_W + kk];
            qf[ks * 4 + 2] = qbase[kk + 4];
            qf[ks * 4 + 3] = qbase[8 * KS_W + kk + 4];
        }
    }

    float o[8][4];
#pragma unroll
    for (int nt = 0; nt < 8; nt++)
#pragma unroll
        for (int j = 0; j < 4; j++) o[nt][j] = 0.f;
    __syncthreads();

    // ---- cp.async issue of K(nope+pe) + Vt tile into buffer bf ----
    auto issue_kv = [&](int kt, int bf) {
        const unsigned ksb = ks_b + (unsigned)bf * 64 * KS_W * 4;
        const unsigned vsb = vt_b + (unsigned)bf * 128 * VT_W * 4;
        const int k0 = kt * 64;
#pragma unroll
        for (int i = 0; i < 4; i++) {           // knope: 1024 chunks
            int idx = t + 256 * i;
            int r = idx >> 4, cc = idx & 15;
            cpa16(ksb + (unsigned)(r * KS_W + cc * 4) * 4u,
                  KNOPE + (size_t)(k0 + r) * 2048 + h * 128 + cc * 8);
        }
#pragma unroll
        for (int i = 0; i < 2; i++) {           // kpe: 512 chunks
            int idx = t + 256 * i;
            int r = idx >> 3, cc = idx & 7;
            cpa16(ksb + (unsigned)(r * KS_W + 64 + cc * 4) * 4u,
                  KPE + (size_t)(k0 + r) * DR + cc * 8);
        }
#pragma unroll
        for (int i = 0; i < 4; i++) {           // vt: 1024 chunks
            int idx = t + 256 * i;
            int r = idx >> 3, cc = idx & 7;
            cpa16(vsb + (unsigned)(r * VT_W + cc * 4) * 4u,
                  VT + ((size_t)h * 128 + r) * S_LEN + k0 + cc * 8);
        }
        cp_commit();
    };

    issue_kv(0, 0);

    for (int kt = 0; kt <= qb; kt++) {
        const int buf = kt & 1;
        if (kt < qb) { issue_kv(kt + 1, buf ^ 1); cp_wait<1>(); }
        else         { cp_wait<0>(); }
        __syncthreads();

        const unsigned* Ks = Ks0 + buf * 64 * KS_W;
        const unsigned* Vs = Vt0 + buf * 128 * VT_W;

        // ---- S = Q K^T (k=192 -> 12 k16 steps) ----
        float sacc[4][4];
#pragma unroll
        for (int nt = 0; nt < 4; nt++)
#pragma unroll
            for (int j = 0; j < 4; j++) sacc[nt][j] = 0.f;

#pragma unroll
        for (int ks = 0; ks < 12; ks++) {
            const int kk = ks * 8;
#pragma unroll
            for (int nt = 0; nt < 4; nt++) {
                const unsigned* p = Ks + (warpN * 32 + nt * 8 + ln4) * KS_W + kk + lnk;
                unsigned b[2] = { p[0], p[4] };
                mma16(sacc[nt], &qf[ks * 4], b);
            }
        }

        const bool diag = (kt == qb);
        const int rl0 = warpM * 16 + ln4;
#pragma unroll
        for (int nt = 0; nt < 4; nt++) {
            int cl = warpN * 32 + nt * 8 + 2 * lnk;
            float v0 = sacc[nt][0] * SCALE;
            float v1 = sacc[nt][1] * SCALE;
            float v2 = sacc[nt][2] * SCALE;
            float v3 = sacc[nt][3] * SCALE;
            if (diag) {
                if (cl     > rl0)     v0 = -1e30f;
                if (cl + 1 > rl0)     v1 = -1e30f;
                if (cl     > rl0 + 8) v2 = -1e30f;
                if (cl + 1 > rl0 + 8) v3 = -1e30f;
            }
            Ps[rl0 * PSF + cl]           = __float_as_uint(v0);
            Ps[rl0 * PSF + cl + 1]       = __float_as_uint(v1);
            Ps[(rl0 + 8) * PSF + cl]     = __float_as_uint(v2);
            Ps[(rl0 + 8) * PSF + cl + 1] = __float_as_uint(v3);
        }
        __syncthreads();

        // ---- online softmax: 4 threads/row; write fp16 pairs to Ph ----
        {
            const int r = t >> 2, seg = t & 3;
            const float* pf = (const float*)Ps + r * PSF + seg * 16;
            unsigned* ph = Ph + r * PH_W + seg * 8;
            float mprev = mrow[r];
            float mx = mprev;
#pragma unroll
            for (int j = 0; j < 16; j++) mx = fmaxf(mx, pf[j]);
            mx = fmaxf(mx, __shfl_xor_sync(0xFFFFFFFFu, mx, 1));
            mx = fmaxf(mx, __shfl_xor_sync(0xFFFFFFFFu, mx, 2));
            float alpha = __expf(mprev - mx);
            float s = 0.f;
#pragma unroll
            for (int j = 0; j < 8; j++) {
                float e0 = __expf(pf[2 * j]     - mx);
                float e1 = __expf(pf[2 * j + 1] - mx);
                s += e0 + e1;
                ph[j] = pack_h2(e0, e1);
            }
            s += __shfl_xor_sync(0xFFFFFFFFu, s, 1);
            s += __shfl_xor_sync(0xFFFFFFFFu, s, 2);
            if (seg == 0) {
                mrow[r] = mx;
                lrow[r] = lrow[r] * alpha + s;
                arow[r] = alpha;
            }
        }
        __syncthreads();

        // ---- O = O*alpha + P @ V (k=64 -> 4 k16 steps, Vt B-fragment) ----
        {
            float ar0 = arow[warpM * 16 + ln4];
            float ar1 = arow[warpM * 16 + ln4 + 8];
#pragma unroll
            for (int nt = 0; nt < 8; nt++) {
                o[nt][0] *= ar0; o[nt][1] *= ar0;
                o[nt][2] *= ar1; o[nt][3] *= ar1;
            }
            const unsigned* pbase = Ph + (warpM * 16 + ln4) * PH_W + lnk;
#pragma unroll
            for (int ks = 0; ks < 4; ks++) {
                const int kk = ks * 8;
                unsigned a[4];
                a[0] = pbase[kk];
                a[1] = pbase[8 * PH_W + kk];
                a[2] = pbase[kk + 4];
                a[3] = pbase[8 * PH_W + kk + 4];
#pragma unroll
                for (int nt = 0; nt < 8; nt++) {
                    const unsigned* p = Vs + (warpN * 64 + nt * 8 + ln4) * VT_W + kk + lnk;
                    unsigned b[2] = { p[0], p[4] };
                    mma16(o[nt], a, b);
                }
            }
        }
        __syncthreads();
    }

    {
        float inv0 = 1.f / lrow[warpM * 16 + ln4];
        float inv1 = 1.f / lrow[warpM * 16 + ln4 + 8];
        int r0 = q0 + warpM * 16 + ln4;
#pragma unroll
        for (int nt = 0; nt < 8; nt++) {
            int c = warpN * 64 + nt * 8 + 2 * lnk;
            __half* dst0 = O + (size_t)r0 * AODIM + h * DV + c;
            __half* dst1 = O + (size_t)(r0 + 8) * AODIM + h * DV + c;
            *(unsigned*)dst0 = pack_h2(o[nt][0] * inv0, o[nt][1] * inv0);
            *(unsigned*)dst1 = pack_h2(o[nt][2] * inv1, o[nt][3] * inv1);
        }
    }
}

// ---------------- host launcher ----------------------------------------------------
template <int HOUT>
static inline void launch_gemm(const __half* A, const __half* W, void* C,
                               int M, int N, int K) {
    dim3 grid((N + 127) / 128, M / 128);
    gemm_f16<HOUT><<<grid, 128, GEMM_SMEM_BYTES>>>(A, W, C, M, N, K);
}

extern "C" void kernel_launch(void* const* d_in, const int* in_sizes, int n_in,
                              void* d_out, int out_size)
{
    const float* hidden  = (const float*)d_in[0];
    const float* q_a_w   = (const float*)d_in[1];
    const float* q_a_ln  = (const float*)d_in[2];
    const float* q_b_w   = (const float*)d_in[3];
    const float* kv_a_w  = (const float*)d_in[4];
    const float* kv_a_ln = (const float*)d_in[5];
    const float* kv_b_w  = (const float*)d_in[6];
    const float* o_w     = (const float*)d_in[7];
    const float* cosb    = (const float*)d_in[8];
    const float* sinb    = (const float*)d_in[9];
    // d_in[10] = attention_mask (causal triu; semantics reproduced directly)
    const int*   pos     = (const int*)d_in[11];
    float* out = (float*)d_out;

    __half* base;
    cudaGetSymbolAddress((void**)&base, g_scratch);
    __half* qa    = base + OFF_QA;
    __half* q     = base + OFF_Q;
    __half* ckv   = base + OFF_CKV;
    __half* ckvn  = base + OFF_CKVN;
    __half* kpe   = base + OFF_KPE;
    __half* knope = base + OFF_KNOPE;
    __half* vt    = base + OFF_VT;
    __half* attn  = base + OFF_ATTN;
    __half* hr    = base + OFF_HR;
    __half* w_qa  = base + OFF_W_QA;
    __half* w_kva = base + OFF_W_KVA;
    __half* w_qb  = base + OFF_W_QB;
    __half* w_kvb = base + OFF_W_KVB;
    __half* w_o   = base + OFF_W_O;
    (void)w_kva;

    cudaFuncSetAttribute(attn_kernel, cudaFuncAttributeMaxDynamicSharedMemorySize,
                         ATT_SMEM_WORDS * 4);
    cudaFuncSetAttribute(gemm_f16<0>, cudaFuncAttributeMaxDynamicSharedMemorySize,
                         GEMM_SMEM_BYTES);
    cudaFuncSetAttribute(gemm_f16<1>, cudaFuncAttributeMaxDynamicSharedMemorySize,
                         GEMM_SMEM_BYTES);
    cudaFuncSetAttribute(gemm_a_fused, cudaFuncAttributeMaxDynamicSharedMemorySize,
                         GEMM_SMEM_BYTES);
    cudaFuncSetAttribute(gemm_kv, cudaFuncAttributeMaxDynamicSharedMemorySize,
                         GEMM_SMEM_BYTES);

    // 0) round everything fp32 -> fp16 (one launch)
    round_all<<<(RB5 + 255) / 256, 256>>>(
        (const float4*)hidden, (const float4*)q_a_w, (const float4*)kv_a_w,
        (const float4*)q_b_w, (const float4*)kv_b_w, (const float4*)o_w,
        hr, w_qa, base + OFF_W_KVA, w_qb, w_kvb, w_o);

    // 1+2) fused down-projection
    {
        dim3 grid(17, 16);
        gemm_a_fused<<<grid, 128, GEMM_SMEM_BYTES>>>(hr, w_qa, qa, ckv);
    }
    // 3) rmsnorm(q_a) in place
    rmsnorm_kernel<<<S_LEN, 256>>>(qa, QLR, q_a_ln, qa, QLR, QLR);
    // 4) rmsnorm(ckv[:, :512]) -> ckvn
    rmsnorm_kernel<<<S_LEN, 256>>>(ckv, 576, kv_a_ln, ckvn, KVLR, KVLR);
    // 5) rope(k_pe) -> kpe
    kpe_rope_kernel<<<(S_LEN * 32 + 255) / 256, 256>>>(ckv, pos, cosb, sinb, kpe);
    // 6) q = qa_n @ q_b_w^T      [2048,3072]
    launch_gemm<1>(qa, w_qb, q, S_LEN, QDIM, QLR);
    // 7) kv up-proj -> knope + vt (transposed V)
    {
        dim3 grid(32, 16);
        gemm_kv<<<grid, 128, GEMM_SMEM_BYTES>>>(ckvn, w_kvb, knope, vt);
    }
    // 8) rope(q_pe) in place
    q_rope_kernel<<<(S_LEN * NH * 32 + 255) / 256, 256>>>(q, pos, cosb, sinb);
    // 9) attention -> attn       [2048,2048] fp16
    attn_kernel<<<dim3(32, NH), 256, ATT_SMEM_WORDS * 4>>>(q, knope, kpe, vt, attn);
    // 10) out = attn @ o_w^T     [2048,2048] fp32 out
    launch_gemm<0>(attn, w_o, out, S_LEN, HID, AODIM);
}

// round 16
// speedup vs baseline: 2.5796x; 1.0136x over previous
#include <cuda_runtime.h>
#include <cuda_fp16.h>
#include <math.h>

// Problem constants
#define S_LEN 2048
#define HID   2048
#define NH    16
#define DN    128
#define DR    64
#define DV    128
#define DQ    192
#define QLR   1536
#define KVLR  512
#define QDIM  (NH * DQ)        // 3072
#define AODIM (NH * DV)        // 2048
#define SCALE 0.07216878364870323f
#define EPSV  1e-6f

// ---------------- scratch (half elements) ---------------------------------------
#define OFF_QA    0UL
#define OFF_Q     (OFF_QA    + (size_t)S_LEN * QLR)
#define OFF_CKV   (OFF_Q     + (size_t)S_LEN * QDIM)
#define OFF_CKVN  (OFF_CKV   + (size_t)S_LEN * 576)
#define OFF_KPE   (OFF_CKVN  + (size_t)S_LEN * KVLR)
#define OFF_KNOPE (OFF_KPE   + (size_t)S_LEN * DR)
#define OFF_VT    (OFF_KNOPE + (size_t)S_LEN * 2048)        // [16][128][2048]
#define OFF_ATTN  (OFF_VT    + (size_t)NH * DV * S_LEN)
#define OFF_HR    (OFF_ATTN  + (size_t)S_LEN * AODIM)
#define OFF_W_QA  (OFF_HR    + (size_t)S_LEN * HID)
#define OFF_W_KVA (OFF_W_QA  + (size_t)QLR * HID)           // padded to 640 rows
#define OFF_W_QB  (OFF_W_KVA + (size_t)640 * HID)
#define OFF_W_KVB (OFF_W_QB  + (size_t)QDIM * QLR)
#define OFF_W_O   (OFF_W_KVB + (size_t)4096 * KVLR)
#define SCRATCH_TOTAL (OFF_W_O + (size_t)HID * AODIM)

__device__ __half g_scratch[SCRATCH_TOTAL];

// ---------------- helpers --------------------------------------------------------
__device__ __forceinline__ void mma16(float* d, const unsigned* a, const unsigned* b) {
    asm volatile(
        "mma.sync.aligned.m16n8k16.row.col.f32.f16.f16.f32 "
        "{%0,%1,%2,%3},{%4,%5,%6,%7},{%8,%9},{%0,%1,%2,%3};\n"
        : "+f"(d[0]), "+f"(d[1]), "+f"(d[2]), "+f"(d[3])
        : "r"(a[0]), "r"(a[1]), "r"(a[2]), "r"(a[3]), "r"(b[0]), "r"(b[1]));
}
__device__ __forceinline__ void cpa16(unsigned saddr, const void* g) {
    asm volatile("cp.async.cg.shared.global [%0], [%1], 16;\n" :: "r"(saddr), "l"(g));
}
__device__ __forceinline__ void cp_commit() { asm volatile("cp.async.commit_group;\n"); }
template <int N> __device__ __forceinline__ void cp_wait() {
    asm volatile("cp.async.wait_group %0;\n" :: "n"(N));
}
__device__ __forceinline__ unsigned pack_h2(float lo, float hi) {
    __half2 h = __floats2half2_rn(lo, hi);
    return *(unsigned*)&h;
}

// ---------------- fused rounding: fp32 -> fp16, grid-stride x4 (MLP=4) ----------
#define RN_H    ((S_LEN * HID) / 4)
#define RN_QA   ((QLR * HID) / 4)
#define RN_KVAD ((640 * HID) / 4)
#define RN_KVAS ((576 * HID) / 4)
#define RN_QB   ((QDIM * QLR) / 4)
#define RN_KVB  ((4096 * KVLR) / 4)
#define RN_O    ((HID * AODIM) / 4)
#define RB0 RN_H
#define RB1 (RB0 + RN_QA)
#define RB2 (RB1 + RN_KVAD)
#define RB3 (RB2 + RN_QB)
#define RB4 (RB3 + RN_KVB)
#define RB5 (RB4 + RN_O)
#define RND_GRID ((RB5 / 4 + 255) / 256)

__global__ __launch_bounds__(256) void round_all(
    const float4* __restrict__ h,    const float4* __restrict__ wqa,
    const float4* __restrict__ wkva, const float4* __restrict__ wqb,
    const float4* __restrict__ wkvb, const float4* __restrict__ wo,
    __half* __restrict__ dh,   __half* __restrict__ dqa,  __half* __restrict__ dkva,
    __half* __restrict__ dqb,  __half* __restrict__ dkvb, __half* __restrict__ dwo)
{
    const int tid = blockIdx.x * blockDim.x + threadIdx.x;
    const int G = gridDim.x * blockDim.x;
#pragma unroll
    for (int rep = 0; rep < 4; rep++) {
        int i = tid + rep * G;
        if (i >= RB5) continue;
        const float4* src; __half* dst; int loc; bool ok = true;
        if (i < RB0)      { src = h;    dst = dh;   loc = i; }
        else if (i < RB1) { src = wqa;  dst = dqa;  loc = i - RB0; }
        else if (i < RB2) { src = wkva; dst = dkva; loc = i - RB1; ok = (loc < RN_KVAS); }
        else if (i < RB3) { src = wqb;  dst = dqb;  loc = i - RB2; }
        else if (i < RB4) { src = wkvb; dst = dkvb; loc = i - RB3; }
        else              { src = wo;   dst = dwo;  loc = i - RB4; }
        float4 v = make_float4(0.f, 0.f, 0.f, 0.f);
        if (ok) v = src[loc];
        uint2 out;
        out.x = pack_h2(v.x, v.y);
        out.y = pack_h2(v.z, v.w);
        *(uint2*)(dst + (size_t)loc * 4) = out;
    }
}

// ---------------- fp16 GEMM: C[M,N] = A[M,K] * W[N,K]^T --------------------------
// BM=128, BN=128, BK=64 halves, 128 threads (4 warps 2x2), warp tile 64x64.
#define GS 36
#define STG_WORDS (2 * 128 * GS)
#define GEMM_STAGES 3
#define GEMM_SMEM_BYTES (GEMM_STAGES * STG_WORDS * 4)

__device__ __forceinline__ void gemm_issue(
    const __half* __restrict__ A, const __half* __restrict__ W, int K,
    int m0, int n0, int k0, unsigned sa, unsigned sb, int t)
{
#pragma unroll
    for (int i = 0; i < 8; i++) {
        int id = t + 128 * i;
        int r = id >> 3, cc = id & 7;
        cpa16(sa + (unsigned)(r * GS + cc * 4) * 4u, A + (size_t)(m0 + r) * K + k0 + cc * 8);
    }
#pragma unroll
    for (int i = 0; i < 8; i++) {
        int id = t + 128 * i;
        int r = id >> 3, cc = id & 7;
        cpa16(sb + (unsigned)(r * GS + cc * 4) * 4u, W + (size_t)(n0 + r) * K + k0 + cc * 8);
    }
    cp_commit();
}

__device__ __forceinline__ void gemm_mainloop(
    const __half* __restrict__ A, const __half* __restrict__ W, int K,
    int m0, int n0, unsigned* sm, float acc[4][8][4],
    int t, int warpM, int warpN, int ln4, int lnk)
{
    unsigned sbase = (unsigned)__cvta_generic_to_shared(sm);
    const int nIter = K >> 6;

    gemm_issue(A, W, K, m0, n0, 0, sbase, sbase + 128 * GS * 4, t);
    if (nIter > 1)
        gemm_issue(A, W, K, m0, n0, 64,
                   sbase + (unsigned)STG_WORDS * 4u,
                   sbase + (unsigned)(STG_WORDS + 128 * GS) * 4u, t);

    int buf = 0;
    for (int it = 0; it < nIter; it++) {
        if (it + 2 < nIter) {
            int nb = buf + 2; if (nb >= GEMM_STAGES) nb -= GEMM_STAGES;
            gemm_issue(A, W, K, m0, n0, (it + 2) << 6,
                       sbase + (unsigned)(nb * STG_WORDS) * 4u,
                       sbase + (unsigned)(nb * STG_WORDS + 128 * GS) * 4u, t);
            cp_wait<2>();
        } else if (it + 1 < nIter) {
            cp_wait<1>();
        } else {
            cp_wait<0>();
        }
        __syncthreads();

        const unsigned* As = sm + buf * STG_WORDS;
        const unsigned* Bs = As + 128 * GS;
#pragma unroll
        for (int ks = 0; ks < 4; ks++) {
            const int kk = ks * 8;
            unsigned a[4][4];
#pragma unroll
            for (int mt = 0; mt < 4; mt++) {
                const unsigned* p = As + (warpM * 64 + mt * 16 + ln4) * GS + kk + lnk;
                a[mt][0] = p[0];
                a[mt][1] = p[8 * GS];
                a[mt][2] = p[4];
                a[mt][3] = p[8 * GS + 4];
            }
#pragma unroll
            for (int nt = 0; nt < 8; nt++) {
                const unsigned* p = Bs + (warpN * 64 + nt * 8 + ln4) * GS + kk + lnk;
                unsigned b[2] = { p[0], p[4] };
#pragma unroll
                for (int mt = 0; mt < 4; mt++) mma16(acc[mt][nt], a[mt], b);
            }
        }
        __syncthreads();
        if (++buf == GEMM_STAGES) buf = 0;
    }
}

template <int HOUT>
__global__ __launch_bounds__(128, 2) void gemm_f16(
    const __half* __restrict__ A, const __half* __restrict__ W,
    void* __restrict__ Cv, int M, int N, int K)
{
    extern __shared__ unsigned sm[];
    const int t = threadIdx.x;
    const int lane = t & 31, wid = t >> 5;
    const int ln4 = lane >> 2, lnk = lane & 3;
    const int warpM = wid & 1, warpN = wid >> 1;
    const int m0 = blockIdx.y * 128, n0 = blockIdx.x * 128;

    float acc[4][8][4];
#pragma unroll
    for (int mt = 0; mt < 4; mt++)
#pragma unroll
        for (int nt = 0; nt < 8; nt++)
#pragma unroll
            for (int j = 0; j < 4; j++) acc[mt][nt][j] = 0.f;

    gemm_mainloop(A, W, K, m0, n0, sm, acc, t, warpM, warpN, ln4, lnk);

#pragma unroll
    for (int mt = 0; mt < 4; mt++) {
        int r0 = m0 + warpM * 64 + mt * 16 + ln4;
#pragma unroll
        for (int nt = 0; nt < 8; nt++) {
            int c = n0 + warpN * 64 + nt * 8 + 2 * lnk;
            if (c < N) {
                if (HOUT) {
                    __half* C = (__half*)Cv;
                    *(unsigned*)(C + (size_t)r0 * N + c)       = pack_h2(acc[mt][nt][0], acc[mt][nt][1]);
                    *(unsigned*)(C + (size_t)(r0 + 8) * N + c) = pack_h2(acc[mt][nt][2], acc[mt][nt][3]);
                } else {
                    float* C = (float*)Cv;
                    *(float2*)(C + (size_t)r0 * N + c)       = make_float2(acc[mt][nt][0], acc[mt][nt][1]);
                    *(float2*)(C + (size_t)(r0 + 8) * N + c) = make_float2(acc[mt][nt][2], acc[mt][nt][3]);
                }
            }
        }
    }
}

// Fused down-proj: Wcat[2176,2048] -> qa[2048,1536] + ckv[2048,576]
__global__ __launch_bounds__(128, 2) void gemm_a_fused(
    const __half* __restrict__ A, const __half* __restrict__ W,
    __half* __restrict__ qa, __half* __restrict__ ckv)
{
    extern __shared__ unsigned sm[];
    const int t = threadIdx.x;
    const int lane = t & 31, wid = t >> 5;
    const int ln4 = lane >> 2, lnk = lane & 3;
    const int warpM = wid & 1, warpN = wid >> 1;
    const int m0 = blockIdx.y * 128, n0 = blockIdx.x * 128;

    float acc[4][8][4];
#pragma unroll
    for (int mt = 0; mt < 4; mt++)
#pragma unroll
        for (int nt = 0; nt < 8; nt++)
#pragma unroll
            for (int j = 0; j < 4; j++) acc[mt][nt][j] = 0.f;

    gemm_mainloop(A, W, HID, m0, n0, sm, acc, t, warpM, warpN, ln4, lnk);

#pragma unroll
    for (int mt = 0; mt < 4; mt++) {
        int r0 = m0 + warpM * 64 + mt * 16 + ln4;
#pragma unroll
        for (int nt = 0; nt < 8; nt++) {
            int c = n0 + warpN * 64 + nt * 8 + 2 * lnk;
            unsigned u0 = pack_h2(acc[mt][nt][0], acc[mt][nt][1]);
            unsigned u1 = pack_h2(acc[mt][nt][2], acc[mt][nt][3]);
            if (c < QLR) {
                *(unsigned*)(qa + (size_t)r0 * QLR + c)       = u0;
                *(unsigned*)(qa + (size_t)(r0 + 8) * QLR + c) = u1;
            } else {
                int cc = c - QLR;
                if (cc < 576) {
                    *(unsigned*)(ckv + (size_t)r0 * 576 + cc)       = u0;
                    *(unsigned*)(ckv + (size_t)(r0 + 8) * 576 + cc) = u1;
                }
            }
        }
    }
}

// kv up-proj -> knope + transposed V
__global__ __launch_bounds__(128, 2) void gemm_kv(
    const __half* __restrict__ A, const __half* __restrict__ W,
    __half* __restrict__ knope, __half* __restrict__ vt)
{
    extern __shared__ unsigned sm[];
    const int t = threadIdx.x;
    const int lane = t & 31, wid = t >> 5;
    const int ln4 = lane >> 2, lnk = lane & 3;
    const int warpM = wid & 1, warpN = wid >> 1;
    const int m0 = blockIdx.y * 128, n0 = blockIdx.x * 128;

    float acc[4][8][4];
#pragma unroll
    for (int mt = 0; mt < 4; mt++)
#pragma unroll
        for (int nt = 0; nt < 8; nt++)
#pragma unroll
            for (int j = 0; j < 4; j++) acc[mt][nt][j] = 0.f;

    gemm_mainloop(A, W, KVLR, m0, n0, sm, acc, t, warpM, warpN, ln4, lnk);

#pragma unroll
    for (int mt = 0; mt < 4; mt++) {
        int r0 = m0 + warpM * 64 + mt * 16 + ln4;
#pragma unroll
        for (int nt = 0; nt < 8; nt++) {
            int c = n0 + warpN * 64 + nt * 8 + 2 * lnk;
            int h = c >> 8, j = c & 255;
            if (j < 128) {
                *(unsigned*)(knope + (size_t)r0 * 2048 + h * 128 + j) =
                    pack_h2(acc[mt][nt][0], acc[mt][nt][1]);
                *(unsigned*)(knope + (size_t)(r0 + 8) * 2048 + h * 128 + j) =
                    pack_h2(acc[mt][nt][2], acc[mt][nt][3]);
            } else {
                int jd = j - 128;
                __half* v0 = vt + ((size_t)h * 128 + jd) * S_LEN;
                __half* v1 = vt + ((size_t)h * 128 + jd + 1) * S_LEN;
                v0[r0]     = __float2half_rn(acc[mt][nt][0]);
                v1[r0]     = __float2half_rn(acc[mt][nt][1]);
                v0[r0 + 8] = __float2half_rn(acc[mt][nt][2]);
                v1[r0 + 8] = __float2half_rn(acc[mt][nt][3]);
            }
        }
    }
}

// ---------------- fused RMSNorm: rows 0..2047 = qa, 2048..4095 = ckv -------------
__global__ __launch_bounds__(256) void rmsnorm2_kernel(
    __half* __restrict__ QA, const float* __restrict__ wq,
    const __half* __restrict__ CKV, const float* __restrict__ wkv,
    __half* __restrict__ CKVN)
{
    int row = blockIdx.x;
    const __half* x; __half* y; const float* w; int n;
    if (row < S_LEN) { x = QA + (size_t)row * QLR; y = (__half*)x; w = wq; n = QLR; }
    else {
        row -= S_LEN;
        x = CKV + (size_t)row * 576; y = CKVN + (size_t)row * KVLR; w = wkv; n = KVLR;
    }
    float s = 0.f;
    for (int i = threadIdx.x; i < n; i += blockDim.x) {
        float v = __half2float(x[i]); s += v * v;
    }
    __shared__ float red[8];
    int lane = threadIdx.x & 31, wid = threadIdx.x >> 5;
#pragma unroll
    for (int o = 16; o; o >>= 1) s += __shfl_down_sync(0xFFFFFFFFu, s, o);
    if (!lane) red[wid] = s;
    __syncthreads();
    if (wid == 0) {
        s = (lane < 8) ? red[lane] : 0.f;
#pragma unroll
        for (int o = 4; o; o >>= 1) s += __shfl_down_sync(0xFFFFFFFFu, s, o);
        if (!lane) red[0] = s;
    }
    __syncthreads();
    const float inv = rsqrtf(red[0] / (float)n + EPSV);
    for (int i = threadIdx.x; i < n; i += blockDim.x)
        y[i] = __float2half_rn(__half2float(x[i]) * inv * w[i]);
}

// ---------------- fused RoPE: warps 0..2047 = kpe, rest = q_pe -------------------
#define ROPE_WARPS (S_LEN + S_LEN * NH)     // 34816
__global__ __launch_bounds__(256) void rope_all_kernel(
    __half* __restrict__ Q, const __half* __restrict__ ckv,
    __half* __restrict__ kpe, const int* __restrict__ pos,
    const float* __restrict__ cosb, const float* __restrict__ sinb)
{
    int warp = (blockIdx.x * blockDim.x + threadIdx.x) >> 5;
    int lane = threadIdx.x & 31;
    if (warp >= ROPE_WARPS) return;
    if (warp < S_LEN) {
        int s = warp;
        int p = pos[s];
        const __half* x = ckv + (size_t)s * 576 + 512;
        float x0 = __half2float(x[2 * lane]), x1 = __half2float(x[2 * lane + 1]);
        float c0 = cosb[(size_t)p * DR + lane],      s0 = sinb[(size_t)p * DR + lane];
        float c1 = cosb[(size_t)p * DR + 32 + lane], s1 = sinb[(size_t)p * DR + 32 + lane];
        kpe[(size_t)s * DR + lane]      = __float2half_rn(x0 * c0 - x1 * s0);
        kpe[(size_t)s * DR + 32 + lane] = __float2half_rn(x1 * c1 + x0 * s1);
    } else {
        int w = warp - S_LEN;
        int s = w >> 4, h = w & 15;
        int p = pos[s];
        __half* x = Q + (size_t)s * QDIM + h * DQ + DN;
        float x0 = __half2float(x[2 * lane]), x1 = __half2float(x[2 * lane + 1]);
        float c0 = cosb[(size_t)p * DR + lane],      s0 = sinb[(size_t)p * DR + lane];
        float c1 = cosb[(size_t)p * DR + 32 + lane], s1 = sinb[(size_t)p * DR + 32 + lane];
        __half o0 = __float2half_rn(x0 * c0 - x1 * s0);
        __half o1 = __float2half_rn(x1 * c1 + x0 * s1);
        __syncwarp();
        x[lane]      = o0;
        x[32 + lane] = o1;
    }
}

// ---------------- Flash attention (causal, fp16 mma) -------------------------------
#define KS_W 100
#define VT_W 36
#define PSF  68
#define PH_W 36
#define ATT_SMEM_WORDS (2 * 64 * KS_W + 2 * 128 * VT_W + 64 * PSF + 64 * PH_W + 3 * 64)

__global__ __launch_bounds__(256) void attn_kernel(
    const __half* __restrict__ Q, const __half* __restrict__ KNOPE,
    const __half* __restrict__ KPE, const __half* __restrict__ VT,
    __half* __restrict__ O)
{
    extern __shared__ unsigned smu[];
    unsigned* Ks0 = smu;
    unsigned* Vt0 = Ks0 + 2 * 64 * KS_W;
    unsigned* Ps  = Vt0 + 2 * 128 * VT_W;
    unsigned* Ph  = Ps + 64 * PSF;
    float* mrow = (float*)(Ph + 64 * PH_W);
    float* lrow = mrow + 64;
    float* arow = lrow + 64;

    const unsigned sb = (unsigned)__cvta_generic_to_shared(smu);
    const unsigned ks_b = sb;
    const unsigned vt_b = sb + 2u * 64 * KS_W * 4;

    const int h  = blockIdx.y;
    const int qb = 31 - blockIdx.x;
    const int q0 = qb * 64;
    const int t    = threadIdx.x;
    const int lane = t & 31;
    const int wid  = t >> 5;
    const int ln4  = lane >> 2;
    const int lnk  = lane & 3;
    const int warpM = wid & 3;
    const int warpN = wid >> 2;

    for (int idx = t; idx < 64 * 24; idx += 256) {
        int r = idx / 24, cc = idx % 24;
        *(uint4*)(Ks0 + r * KS_W + cc * 4) =
            *(const uint4*)(Q + (size_t)(q0 + r) * QDIM + h * DQ + cc * 8);
    }
    if (t < 64) { mrow[t] = -1e30f; lrow[t] = 0.f; }
    __syncthreads();

    unsigned qf[48];
    {
        const unsigned* qbase = Ks0 + (warpM * 16 + ln4) * KS_W + lnk;
#pragma unroll
        for (int ks = 0; ks < 12; ks++) {
            const int kk = ks * 8;
            qf[ks * 4 + 0] = qbase[kk];
            qf[ks * 4 + 1] = qbase[8 * KS_W + kk];
            qf[ks * 4 + 2] = qbase[kk + 4];
            qf[ks * 4 + 3] = qbase[8 * KS_W + kk + 4];
        }
    }

    float o[8][4];
#pragma unroll
    for (int nt = 0; nt < 8; nt++)
#pragma unroll
        for (int j = 0; j < 4; j++) o[nt][j] = 0.f;
    __syncthreads();

    auto issue_kv = [&](int kt, int bf) {
        const unsigned ksb = ks_b + (unsigned)bf * 64 * KS_W * 4;
        const unsigned vsb = vt_b + (unsigned)bf * 128 * VT_W * 4;
        const int k0 = kt * 64;
#pragma unroll
        for (int i = 0; i < 4; i++) {
            int idx = t + 256 * i;
            int r = idx >> 4, cc = idx & 15;
            cpa16(ksb + (unsigned)(r * KS_W + cc * 4) * 4u,
                  KNOPE + (size_t)(k0 + r) * 2048 + h * 128 + cc * 8);
        }
#pragma unroll
        for (int i = 0; i < 2; i++) {
            int idx = t + 256 * i;
            int r = idx >> 3, cc = idx & 7;
            cpa16(ksb + (unsigned)(r * KS_W + 64 + cc * 4) * 4u,
                  KPE + (size_t)(k0 + r) * DR + cc * 8);
        }
#pragma unroll
        for (int i = 0; i < 4; i++) {
            int idx = t + 256 * i;
            int r = idx >> 3, cc = idx & 7;
            cpa16(vsb + (unsigned)(r * VT_W + cc * 4) * 4u,
                  VT + ((size_t)h * 128 + r) * S_LEN + k0 + cc * 8);
        }
        cp_commit();
    };

    issue_kv(0, 0);

    for (int kt = 0; kt <= qb; kt++) {
        const int buf = kt & 1;
        if (kt < qb) { issue_kv(kt + 1, buf ^ 1); cp_wait<1>(); }
        else         { cp_wait<0>(); }
        __syncthreads();

        const unsigned* Ks = Ks0 + buf * 64 * KS_W;
        const unsigned* Vs = Vt0 + buf * 128 * VT_W;

        float sacc[4][4];
#pragma unroll
        for (int nt = 0; nt < 4; nt++)
#pragma unroll
            for (int j = 0; j < 4; j++) sacc[nt][j] = 0.f;

#pragma unroll
        for (int ks = 0; ks < 12; ks++) {
            const int kk = ks * 8;
#pragma unroll
            for (int nt = 0; nt < 4; nt++) {
                const unsigned* p = Ks + (warpN * 32 + nt * 8 + ln4) * KS_W + kk + lnk;
                unsigned b[2] = { p[0], p[4] };
                mma16(sacc[nt], &qf[ks * 4], b);
            }
        }

        const bool diag = (kt == qb);
        const int rl0 = warpM * 16 + ln4;
#pragma unroll
        for (int nt = 0; nt < 4; nt++) {
            int cl = warpN * 32 + nt * 8 + 2 * lnk;
            float v0 = sacc[nt][0] * SCALE;
            float v1 = sacc[nt][1] * SCALE;
            float v2 = sacc[nt][2] * SCALE;
            float v3 = sacc[nt][3] * SCALE;
            if (diag) {
                if (cl     > rl0)     v0 = -1e30f;
                if (cl + 1 > rl0)     v1 = -1e30f;
                if (cl     > rl0 + 8) v2 = -1e30f;
                if (cl + 1 > rl0 + 8) v3 = -1e30f;
            }
            Ps[rl0 * PSF + cl]           = __float_as_uint(v0);
            Ps[rl0 * PSF + cl + 1]       = __float_as_uint(v1);
            Ps[(rl0 + 8) * PSF + cl]     = __float_as_uint(v2);
            Ps[(rl0 + 8) * PSF + cl + 1] = __float_as_uint(v3);
        }
        __syncthreads();

        {
            const int r = t >> 2, seg = t & 3;
            const float* pf = (const float*)Ps + r * PSF + seg * 16;
            unsigned* ph = Ph + r * PH_W + seg * 8;
            float mprev = mrow[r];
            float mx = mprev;
#pragma unroll
            for (int j = 0; j < 16; j++) mx = fmaxf(mx, pf[j]);
            mx = fmaxf(mx, __shfl_xor_sync(0xFFFFFFFFu, mx, 1));
            mx = fmaxf(mx, __shfl_xor_sync(0xFFFFFFFFu, mx, 2));
            float alpha = __expf(mprev - mx);
            float s = 0.f;
#pragma unroll
            for (int j = 0; j < 8; j++) {
                float e0 = __expf(pf[2 * j]     - mx);
                float e1 = __expf(pf[2 * j + 1] - mx);
                s += e0 + e1;
                ph[j] = pack_h2(e0, e1);
            }
            s += __shfl_xor_sync(0xFFFFFFFFu, s, 1);
            s += __shfl_xor_sync(0xFFFFFFFFu, s, 2);
            if (seg == 0) {
                mrow[r] = mx;
                lrow[r] = lrow[r] * alpha + s;
                arow[r] = alpha;
            }
        }
        __syncthreads();

        {
            float ar0 = arow[warpM * 16 + ln4];
            float ar1 = arow[warpM * 16 + ln4 + 8];
#pragma unroll
            for (int nt = 0; nt < 8; nt++) {
                o[nt][0] *= ar0; o[nt][1] *= ar0;
                o[nt][2] *= ar1; o[nt][3] *= ar1;
            }
            const unsigned* pbase = Ph + (warpM * 16 + ln4) * PH_W + lnk;
#pragma unroll
            for (int ks = 0; ks < 4; ks++) {
                const int kk = ks * 8;
                unsigned a[4];
                a[0] = pbase[kk];
                a[1] = pbase[8 * PH_W + kk];
                a[2] = pbase[kk + 4];
                a[3] = pbase[8 * PH_W + kk + 4];
#pragma unroll
                for (int nt = 0; nt < 8; nt++) {
                    const unsigned* p = Vs + (warpN * 64 + nt * 8 + ln4) * VT_W + kk + lnk;
                    unsigned b[2] = { p[0], p[4] };
                    mma16(o[nt], a, b);
                }
            }
        }
        __syncthreads();
    }

    {
        float inv0 = 1.f / lrow[warpM * 16 + ln4];
        float inv1 = 1.f / lrow[warpM * 16 + ln4 + 8];
        int r0 = q0 + warpM * 16 + ln4;
#pragma unroll
        for (int nt = 0; nt < 8; nt++) {
            int c = warpN * 64 + nt * 8 + 2 * lnk;
            __half* dst0 = O + (size_t)r0 * AODIM + h * DV + c;
            __half* dst1 = O + (size_t)(r0 + 8) * AODIM + h * DV + c;
            *(unsigned*)dst0 = pack_h2(o[nt][0] * inv0, o[nt][1] * inv0);
            *(unsigned*)dst1 = pack_h2(o[nt][2] * inv1, o[nt][3] * inv1);
        }
    }
}

// ---------------- host launcher ----------------------------------------------------
template <int HOUT>
static inline void launch_gemm(const __half* A, const __half* W, void* C,
                               int M, int N, int K) {
    dim3 grid((N + 127) / 128, M / 128);
    gemm_f16<HOUT><<<grid, 128, GEMM_SMEM_BYTES>>>(A, W, C, M, N, K);
}

extern "C" void kernel_launch(void* const* d_in, const int* in_sizes, int n_in,
                              void* d_out, int out_size)
{
    const float* hidden  = (const float*)d_in[0];
    const float* q_a_w   = (const float*)d_in[1];
    const float* q_a_ln  = (const float*)d_in[2];
    const float* q_b_w   = (const float*)d_in[3];
    const float* kv_a_w  = (const float*)d_in[4];
    const float* kv_a_ln = (const float*)d_in[5];
    const float* kv_b_w  = (const float*)d_in[6];
    const float* o_w     = (const float*)d_in[7];
    const float* cosb    = (const float*)d_in[8];
    const float* sinb    = (const float*)d_in[9];
    // d_in[10] = attention_mask (causal triu; semantics reproduced directly)
    const int*   pos     = (const int*)d_in[11];
    float* out = (float*)d_out;

    __half* base;
    cudaGetSymbolAddress((void**)&base, g_scratch);
    __half* qa    = base + OFF_QA;
    __half* q     = base + OFF_Q;
    __half* ckv   = base + OFF_CKV;
    __half* ckvn  = base + OFF_CKVN;
    __half* kpe   = base + OFF_KPE;
    __half* knope = base + OFF_KNOPE;
    __half* vt    = base + OFF_VT;
    __half* attn  = base + OFF_ATTN;
    __half* hr    = base + OFF_HR;
    __half* w_qa  = base + OFF_W_QA;
    __half* w_qb  = base + OFF_W_QB;
    __half* w_kvb = base + OFF_W_KVB;
    __half* w_o   = base + OFF_W_O;

    cudaFuncSetAttribute(attn_kernel, cudaFuncAttributeMaxDynamicSharedMemorySize,
                         ATT_SMEM_WORDS * 4);
    cudaFuncSetAttribute(gemm_f16<0>, cudaFuncAttributeMaxDynamicSharedMemorySize,
                         GEMM_SMEM_BYTES);
    cudaFuncSetAttribute(gemm_f16<1>, cudaFuncAttributeMaxDynamicSharedMemorySize,
                         GEMM_SMEM_BYTES);
    cudaFuncSetAttribute(gemm_a_fused, cudaFuncAttributeMaxDynamicSharedMemorySize,
                         GEMM_SMEM_BYTES);
    cudaFuncSetAttribute(gemm_kv, cudaFuncAttributeMaxDynamicSharedMemorySize,
                         GEMM_SMEM_BYTES);

    // 0) round everything fp32 -> fp16 (grid-stride x4)
    round_all<<<RND_GRID, 256>>>(
        (const float4*)hidden, (const float4*)q_a_w, (const float4*)kv_a_w,
        (const float4*)q_b_w, (const float4*)kv_b_w, (const float4*)o_w,
        hr, w_qa, base + OFF_W_KVA, w_qb, w_kvb, w_o);

    // 1+2) fused down-projection
    {
        dim3 grid(17, 16);
        gemm_a_fused<<<grid, 128, GEMM_SMEM_BYTES>>>(hr, w_qa, qa, ckv);
    }
    // 3+4) both rmsnorms in one launch
    rmsnorm2_kernel<<<2 * S_LEN, 256>>>(qa, q_a_ln, ckv, kv_a_ln, ckvn);
    // 5) q = qa_n @ q_b_w^T      [2048,3072]
    launch_gemm<1>(qa, w_qb, q, S_LEN, QDIM, QLR);
    // 6) kv up-proj -> knope + vt
    {
        dim3 grid(32, 16);
        gemm_kv<<<grid, 128, GEMM_SMEM_BYTES>>>(ckvn, w_kvb, knope, vt);
    }
    // 7) both ropes in one launch (kpe from ckv, q_pe in place)
    rope_all_kernel<<<(ROPE_WARPS * 32 + 255) / 256, 256>>>(q, ckv, kpe, pos, cosb, sinb);
    // 8) attention -> attn       [2048,2048] fp16
    attn_kernel<<<dim3(32, NH), 256, ATT_SMEM_WORDS * 4>>>(q, knope, kpe, vt, attn);
    // 9) out = attn @ o_w^T      [2048,2048] fp32 out
    launch_gemm<0>(attn, w_o, out, S_LEN, HID, AODIM);
}